// round 2
// baseline (speedup 1.0000x reference)
#include <cuda_runtime.h>
#include <math.h>

#define BB 16
#define TT 4096
#define DINNER 384
#define NH 8
#define HD 48
#define DS 64
#define DPROJ 904
#define NC 64
#define CS 64
#define MIXD 32

// ---------------- scratch (static device arrays; no runtime alloc) ----------
__device__ float g_W1[4 * DPROJ];            // w_in @ w_inproj
__device__ float g_mvec[BB * DPROJ];         // (b_in + relu(mic)) @ w_inproj
__device__ float g_W2[DINNER * MIXD];        // w_outproj @ w_mix1
__device__ float g_hb[BB * 192];
__device__ float g_A[NH];
__device__ float g_x[(size_t)BB * TT * DINNER];   // silu(conv) xs
__device__ float g_bc[(size_t)BB * TT * 128];     // B(64) | C(64)
__device__ float g_dt[(size_t)BB * TT * NH];
__device__ float g_decay[(size_t)BB * TT * NH];
__device__ float g_S[(size_t)128 * NC * HD * DS]; // chunk states -> h_in (in place)
__device__ float g_Dc[128 * NC];
__device__ float g_y[(size_t)BB * TT * DINNER];
__device__ float g_part[512 * MIXD];

__device__ __forceinline__ float siluf(float v) { return v / (1.f + expf(-v)); }
__device__ __forceinline__ float softplusf(float v) { return v > 20.f ? v : log1pf(expf(v)); }

// ---------------- k0a: mic MLP + A ----------------
__global__ void k0a(const float* __restrict__ mic_pos, const float* __restrict__ w_mic,
                    const float* __restrict__ b_mic, const float* __restrict__ b_in,
                    const float* __restrict__ A_log) {
    int tid = threadIdx.x;
    for (int i = tid; i < BB * 192; i += 256) {
        int b = i / 192, d = i % 192;
        float s = b_mic[d];
        #pragma unroll
        for (int j = 0; j < 12; j++) s = fmaf(mic_pos[b * 12 + j], w_mic[j * 192 + d], s);
        g_hb[i] = b_in[d] + fmaxf(s, 0.f);
    }
    if (tid < NH) g_A[tid] = -expf(A_log[tid]);
}

// ---------------- k0b: folded weights ----------------
__global__ void k0b(const float* __restrict__ w_in, const float* __restrict__ w_inproj,
                    const float* __restrict__ w_outproj, const float* __restrict__ w_mix1) {
    int i = blockIdx.x * 256 + threadIdx.x;
    if (i < 4 * DPROJ) {
        int j = i / DPROJ, d = i % DPROJ;
        float s = 0.f;
        for (int m = 0; m < 192; m++) s = fmaf(w_in[j * 192 + m], w_inproj[m * DPROJ + d], s);
        g_W1[i] = s;
    } else if (i < 4 * DPROJ + BB * DPROJ) {
        int ii = i - 4 * DPROJ;
        int b = ii / DPROJ, d = ii % DPROJ;
        float s = 0.f;
        for (int m = 0; m < 192; m++) s = fmaf(g_hb[b * 192 + m], w_inproj[m * DPROJ + d], s);
        g_mvec[ii] = s;
    } else if (i < 4 * DPROJ + BB * DPROJ + DINNER * MIXD) {
        int ii = i - (4 * DPROJ + BB * DPROJ);
        int d = ii / MIXD, o = ii % MIXD;
        float s = 0.f;
        for (int m = 0; m < 192; m++) s = fmaf(w_outproj[d * 192 + m], w_mix1[m * MIXD + o], s);
        g_W2[ii] = s;
    }
}

// ---------------- k1: fused inproj + conv4 + silu + dt/decay ----------------
// grid (32, 16) block 128 : thread = one t
__global__ void k1(const float* __restrict__ x, const float* __restrict__ conv_w,
                   const float* __restrict__ conv_b, const float* __restrict__ dt_bias) {
    __shared__ float sW1[4 * 520];   // proj dims 384..903
    __shared__ float smv[520];
    __shared__ float scw[512 * 4];
    __shared__ float scb[512];
    __shared__ float sx4[131 * 4];
    __shared__ float sraw[131 * 33];

    int tid = threadIdx.x;
    int b = blockIdx.y;
    int t0 = blockIdx.x * 128;

    for (int i = tid; i < 4 * 520; i += 128) sW1[i] = g_W1[(i / 520) * DPROJ + 384 + (i % 520)];
    for (int i = tid; i < 520; i += 128) smv[i] = g_mvec[b * DPROJ + 384 + i];
    for (int i = tid; i < 512 * 4; i += 128) scw[i] = conv_w[i];
    for (int i = tid; i < 512; i += 128) scb[i] = conv_b[i];
    for (int i = tid; i < 131 * 4; i += 128) {
        int r = i >> 2, j = i & 3;
        int t = t0 + r - 3;
        sx4[i] = (t >= 0) ? x[((size_t)b * TT + t) * 4 + j] : 0.f;
    }

    int t = t0 + tid;
    for (int c16 = 0; c16 < 16; c16++) {
        __syncthreads();
        for (int i = tid; i < 131 * 32; i += 128) {
            int r = i >> 5, dc = i & 31;
            int dd = c16 * 32 + dc;
            float v = 0.f;
            if (t0 + r - 3 >= 0) {
                v = smv[dd];
                #pragma unroll
                for (int j = 0; j < 4; j++) v = fmaf(sx4[r * 4 + j], sW1[j * 520 + dd], v);
            }
            sraw[r * 33 + dc] = v;
        }
        __syncthreads();
        float v[32];
        #pragma unroll
        for (int dc = 0; dc < 32; dc++) {
            int dd = c16 * 32 + dc;
            float a = scb[dd];
            #pragma unroll
            for (int k = 0; k < 4; k++) a = fmaf(sraw[(tid + k) * 33 + dc], scw[dd * 4 + k], a);
            v[dc] = siluf(a);
        }
        float* dst;
        if (c16 < 12) dst = g_x + ((size_t)b * TT + t) * DINNER + c16 * 32;
        else          dst = g_bc + ((size_t)b * TT + t) * 128 + (c16 - 12) * 32;
        #pragma unroll
        for (int q = 0; q < 8; q++)
            ((float4*)dst)[q] = make_float4(v[4 * q], v[4 * q + 1], v[4 * q + 2], v[4 * q + 3]);
    }

    // dt path (proj dims 896..903 via sW1 dims 512..519)
    #pragma unroll
    for (int hh = 0; hh < NH; hh++) {
        int dd = 512 + hh;
        float v = smv[dd];
        #pragma unroll
        for (int j = 0; j < 4; j++) v = fmaf(sx4[(tid + 3) * 4 + j], sW1[j * 520 + dd], v);
        float dt = softplusf(v + dt_bias[hh]);
        size_t o = ((size_t)b * TT + t) * NH + hh;
        g_dt[o] = dt;
        g_decay[o] = expf(dt * g_A[hh]);
    }
}

// ---------------- kA: chunk-local end states ----------------
// grid (NC, 128) block 192 : thread = (p, nq)
__global__ void kA() {
    __shared__ float sx[CS * HD];
    __shared__ float sB[CS * DS];
    __shared__ float sdec[CS];
    __shared__ float sdt[CS];

    int c = blockIdx.x, bh = blockIdx.y;
    int b = bh >> 3, h = bh & 7;
    int tid = threadIdx.x;
    int p = tid >> 2, nq = tid & 3;
    int t0 = c * CS;

    const float* xp = g_x + ((size_t)b * TT + t0) * DINNER + h * HD;
    for (int i = tid; i < CS * 12; i += 192) {
        int r = i / 12, col = i % 12;
        ((float4*)sx)[r * 12 + col] = ((const float4*)(xp + (size_t)r * DINNER))[col];
    }
    const float* bp = g_bc + ((size_t)b * TT + t0) * 128;
    for (int i = tid; i < CS * 16; i += 192) {
        int r = i / 16, col = i % 16;
        ((float4*)sB)[r * 16 + col] = ((const float4*)(bp + (size_t)r * 128))[col];
    }
    for (int i = tid; i < CS; i += 192) {
        size_t o = ((size_t)b * TT + t0 + i) * NH + h;
        sdec[i] = g_decay[o];
        sdt[i] = g_dt[o];
    }
    __syncthreads();

    float S[16];
    #pragma unroll
    for (int k = 0; k < 16; k++) S[k] = 0.f;
    float rc = 1.f;
    for (int t = CS - 1; t >= 0; t--) {
        float w = rc * sdt[t] * sx[t * HD + p];
        const float* Bp = sB + t * DS + nq * 16;
        #pragma unroll
        for (int k = 0; k < 16; k++) S[k] = fmaf(w, Bp[k], S[k]);
        rc *= sdec[t];
    }
    float* sp = g_S + ((size_t)bh * NC + c) * (HD * DS) + tid * 16;
    #pragma unroll
    for (int q = 0; q < 4; q++)
        ((float4*)sp)[q] = make_float4(S[4 * q], S[4 * q + 1], S[4 * q + 2], S[4 * q + 3]);
    if (tid == 0) g_Dc[bh * NC + c] = rc;
}

// ---------------- kB: inter-chunk scan (in place: g_S becomes h_in) -------
// grid 128 block 384 : thread owns 8 contiguous states
__global__ void kB() {
    int bh = blockIdx.x, tid = threadIdx.x;
    float h8[8];
    #pragma unroll
    for (int k = 0; k < 8; k++) h8[k] = 0.f;
    size_t base = (size_t)bh * NC * (HD * DS) + tid * 8;
    for (int c = 0; c < NC; c++) {
        float* sp = g_S + base + (size_t)c * (HD * DS);
        float4 a = ((float4*)sp)[0];
        float4 d = ((float4*)sp)[1];
        ((float4*)sp)[0] = make_float4(h8[0], h8[1], h8[2], h8[3]);
        ((float4*)sp)[1] = make_float4(h8[4], h8[5], h8[6], h8[7]);
        float Dc = g_Dc[bh * NC + c];
        h8[0] = fmaf(h8[0], Dc, a.x); h8[1] = fmaf(h8[1], Dc, a.y);
        h8[2] = fmaf(h8[2], Dc, a.z); h8[3] = fmaf(h8[3], Dc, a.w);
        h8[4] = fmaf(h8[4], Dc, d.x); h8[5] = fmaf(h8[5], Dc, d.y);
        h8[6] = fmaf(h8[6], Dc, d.z); h8[7] = fmaf(h8[7], Dc, d.w);
    }
}

// ---------------- kC: intra-chunk scan + y ----------------
// grid (NC, 128) block 192 : thread = (p, nq)
__global__ void kC(const float* __restrict__ D_skip) {
    __shared__ float sx[CS * HD];
    __shared__ float sBC[CS * 128];
    __shared__ float sdec[CS];
    __shared__ float sdt[CS];

    int c = blockIdx.x, bh = blockIdx.y;
    int b = bh >> 3, h = bh & 7;
    int tid = threadIdx.x;
    int p = tid >> 2, nq = tid & 3;
    int t0 = c * CS;

    const float* xp = g_x + ((size_t)b * TT + t0) * DINNER + h * HD;
    for (int i = tid; i < CS * 12; i += 192) {
        int r = i / 12, col = i % 12;
        ((float4*)sx)[r * 12 + col] = ((const float4*)(xp + (size_t)r * DINNER))[col];
    }
    const float* bp = g_bc + ((size_t)b * TT + t0) * 128;
    for (int i = tid; i < CS * 32; i += 192) {
        int r = i / 32, col = i % 32;
        ((float4*)sBC)[r * 32 + col] = ((const float4*)(bp + (size_t)r * 128))[col];
    }
    for (int i = tid; i < CS; i += 192) {
        size_t o = ((size_t)b * TT + t0 + i) * NH + h;
        sdec[i] = g_decay[o];
        sdt[i] = g_dt[o];
    }

    const float4* hp = (const float4*)(g_S + ((size_t)bh * NC + c) * (HD * DS) + tid * 16);
    float4 h0 = hp[0], h1 = hp[1], h2 = hp[2], h3 = hp[3];
    float hreg[16] = {h0.x, h0.y, h0.z, h0.w, h1.x, h1.y, h1.z, h1.w,
                      h2.x, h2.y, h2.z, h2.w, h3.x, h3.y, h3.z, h3.w};
    float dskip = D_skip[h];
    __syncthreads();

    float* yp = g_y + ((size_t)b * TT + t0) * DINNER + h * HD + p;
    for (int t = 0; t < CS; t++) {
        float dec = sdec[t];
        float xv = sx[t * HD + p];
        float dtx = sdt[t] * xv;
        const float* Bp = sBC + t * 128 + nq * 16;
        const float* Cp = Bp + DS;
        float y = 0.f;
        #pragma unroll
        for (int k = 0; k < 16; k++) {
            float hk = fmaf(hreg[k], dec, dtx * Bp[k]);
            hreg[k] = hk;
            y = fmaf(hk, Cp[k], y);
        }
        y += __shfl_xor_sync(0xffffffffu, y, 1);
        y += __shfl_xor_sync(0xffffffffu, y, 2);
        if (nq == 0) yp[(size_t)t * DINNER] = y + dskip * xv;
    }
}

// ---------------- kD: gating + RMSNorm + (yn @ W2) + mix2 + partial mean --
// grid (32, 16) block 128 : thread = one t
__global__ void kD(const float* __restrict__ x, const float* __restrict__ norm_w,
                   const float* __restrict__ w_mix2, const float* __restrict__ b_mix1,
                   const float* __restrict__ b_mix2) {
    __shared__ float sy[128 * 51];     // 48-d chunk, stride 51 (also reused as reduce buf)
    __shared__ float sW2[48 * MIXD];
    __shared__ float sxx[128 * 4];
    __shared__ float smvz[DINNER];
    __shared__ float sW1z[4 * DINNER];
    __shared__ float snw[DINNER];
    __shared__ float swm2[MIXD * MIXD];

    int tid = threadIdx.x;
    int b = blockIdx.y;
    int t0 = blockIdx.x * 128;
    int t = t0 + tid;

    for (int i = tid; i < DINNER; i += 128) { smvz[i] = g_mvec[b * DPROJ + i]; snw[i] = norm_w[i]; }
    for (int i = tid; i < 4 * DINNER; i += 128) sW1z[i] = g_W1[(i / DINNER) * DPROJ + (i % DINNER)];
    for (int i = tid; i < MIXD * MIXD; i += 128) swm2[i] = w_mix2[i];
    for (int i = tid; i < 128 * 4; i += 128) {
        int r = i >> 2, j = i & 3;
        sxx[i] = x[((size_t)b * TT + t0 + r) * 4 + j];
    }
    __syncthreads();
    float x0 = sxx[tid * 4 + 0], x1 = sxx[tid * 4 + 1], x2 = sxx[tid * 4 + 2], x3 = sxx[tid * 4 + 3];

    const float* yrow = g_y + ((size_t)b * TT + t0) * DINNER;

    // phase 1: sum of squares of gated y
    float ss = 0.f;
    for (int ch = 0; ch < 8; ch++) {
        __syncthreads();
        for (int i = tid; i < 128 * 48; i += 128) {
            int r = i / 48, cc = i % 48;
            sy[r * 51 + cc] = yrow[(size_t)r * DINNER + ch * 48 + cc];
        }
        __syncthreads();
        #pragma unroll 4
        for (int dc = 0; dc < 48; dc++) {
            int dd = ch * 48 + dc;
            float z = smvz[dd];
            z = fmaf(x0, sW1z[dd], z);
            z = fmaf(x1, sW1z[DINNER + dd], z);
            z = fmaf(x2, sW1z[2 * DINNER + dd], z);
            z = fmaf(x3, sW1z[3 * DINNER + dd], z);
            float gg = sy[tid * 51 + dc] * siluf(z);
            ss = fmaf(gg, gg, ss);
        }
    }
    float rstd = rsqrtf(ss * (1.f / DINNER) + 1e-5f);

    // phase 2: yn @ W2
    float acc[MIXD];
    #pragma unroll
    for (int o = 0; o < MIXD; o++) acc[o] = 0.f;
    for (int ch = 0; ch < 8; ch++) {
        __syncthreads();
        for (int i = tid; i < 128 * 48; i += 128) {
            int r = i / 48, cc = i % 48;
            sy[r * 51 + cc] = yrow[(size_t)r * DINNER + ch * 48 + cc];
        }
        for (int i = tid; i < 48 * MIXD; i += 128) sW2[i] = g_W2[ch * 48 * MIXD + i];
        __syncthreads();
        for (int dc = 0; dc < 48; dc++) {
            int dd = ch * 48 + dc;
            float z = smvz[dd];
            z = fmaf(x0, sW1z[dd], z);
            z = fmaf(x1, sW1z[DINNER + dd], z);
            z = fmaf(x2, sW1z[2 * DINNER + dd], z);
            z = fmaf(x3, sW1z[3 * DINNER + dd], z);
            float yn = sy[tid * 51 + dc] * siluf(z) * rstd * snw[dd];
            const float* w = sW2 + dc * MIXD;
            #pragma unroll
            for (int o = 0; o < MIXD; o++) acc[o] = fmaf(yn, w[o], acc[o]);
        }
    }

    // m1 -> m2
    float m1[MIXD];
    #pragma unroll
    for (int o = 0; o < MIXD; o++) m1[o] = fmaxf(acc[o] + b_mix1[o], 0.f);
    float m2[MIXD];
    #pragma unroll
    for (int o = 0; o < MIXD; o++) {
        float s = b_mix2[o];
        #pragma unroll
        for (int i = 0; i < MIXD; i++) s = fmaf(m1[i], swm2[i * MIXD + o], s);
        m2[o] = fmaxf(s, 0.f);
    }

    // deterministic block tree-reduce of m2 (reuse sy; row stride 33)
    __syncthreads();
    float* red = sy;
    #pragma unroll
    for (int o = 0; o < MIXD; o++) red[tid * 33 + o] = m2[o];
    __syncthreads();
    for (int s = 64; s >= 1; s >>= 1) {
        if (tid < s) {
            #pragma unroll
            for (int o = 0; o < MIXD; o++) red[tid * 33 + o] += red[(tid + s) * 33 + o];
        }
        __syncthreads();
    }
    if (tid < MIXD) g_part[(b * 32 + blockIdx.x) * MIXD + tid] = red[tid];
}

// ---------------- kF: final mean + w_out ----------------
__global__ void kF(const float* __restrict__ w_out, const float* __restrict__ b_out,
                   float* __restrict__ out) {
    int b = threadIdx.x;
    if (b < BB) {
        float s = 0.f;
        for (int o = 0; o < MIXD; o++) {
            float a = 0.f;
            for (int blk = 0; blk < 32; blk++) a += g_part[(b * 32 + blk) * MIXD + o];
            s = fmaf(a * (1.f / (float)TT), w_out[o], s);
        }
        out[b] = s + b_out[0];
    }
}

extern "C" void kernel_launch(void* const* d_in, const int* in_sizes, int n_in,
                              void* d_out, int out_size) {
    const float* x        = (const float*)d_in[0];
    const float* mic_pos  = (const float*)d_in[1];
    const float* w_in     = (const float*)d_in[2];
    const float* b_in     = (const float*)d_in[3];
    const float* w_mic    = (const float*)d_in[4];
    const float* b_mic    = (const float*)d_in[5];
    const float* w_inproj = (const float*)d_in[6];
    const float* conv_w   = (const float*)d_in[7];
    const float* conv_b   = (const float*)d_in[8];
    const float* dt_bias  = (const float*)d_in[9];
    const float* A_log    = (const float*)d_in[10];
    const float* D_skip   = (const float*)d_in[11];
    const float* norm_w   = (const float*)d_in[12];
    const float* w_outproj= (const float*)d_in[13];
    const float* w_mix1   = (const float*)d_in[14];
    const float* b_mix1   = (const float*)d_in[15];
    const float* w_mix2   = (const float*)d_in[16];
    const float* b_mix2   = (const float*)d_in[17];
    const float* w_out    = (const float*)d_in[18];
    const float* b_out    = (const float*)d_in[19];
    float* out = (float*)d_out;

    k0a<<<1, 256>>>(mic_pos, w_mic, b_mic, b_in, A_log);
    k0b<<<(4 * DPROJ + BB * DPROJ + DINNER * MIXD + 255) / 256, 256>>>(w_in, w_inproj, w_outproj, w_mix1);
    k1<<<dim3(32, 16), 128>>>(x, conv_w, conv_b, dt_bias);
    kA<<<dim3(NC, 128), 192>>>();
    kB<<<128, 384>>>();
    kC<<<dim3(NC, 128), 192>>>(D_skip);
    kD<<<dim3(32, 16), 128>>>(x, norm_w, w_mix2, b_mix1, b_mix2);
    kF<<<1, 32>>>(w_out, b_out, out);
}

// round 3
// speedup vs baseline: 1.4087x; 1.4087x over previous
#include <cuda_runtime.h>
#include <math.h>

#define BB 16
#define TT 4096
#define DINNER 384
#define NH 8
#define HD 48
#define DS 64
#define DPROJ 904
#define NC 64
#define CS 64
#define MIXD 32

// ---------------- scratch (static device arrays; no runtime alloc) ----------
__device__ float g_W1[4 * DPROJ];            // w_in @ w_inproj
__device__ float g_mvec[BB * DPROJ];         // (b_in + relu(mic)) @ w_inproj
__device__ float g_W2[DINNER * MIXD];        // w_outproj @ w_mix1
__device__ float g_hb[BB * 192];
__device__ float g_A[NH];
__device__ float g_x[(size_t)BB * TT * DINNER];   // silu(conv) xs
__device__ float g_bc[(size_t)BB * TT * 128];     // B(64) | C(64)
__device__ float g_dt[(size_t)BB * TT * NH];
__device__ float g_la[(size_t)BB * TT * NH];      // log-decay = dt*A
__device__ float g_S[(size_t)128 * NC * HD * DS]; // chunk states -> h_in (in place)
__device__ float g_Dc[128 * NC];
__device__ float g_y[(size_t)BB * TT * DINNER];
__device__ float g_part[2048 * MIXD];

__device__ __forceinline__ float siluf(float v) { return v / (1.f + expf(-v)); }
__device__ __forceinline__ float softplusf(float v) { return v > 20.f ? v : log1pf(expf(v)); }

// ---------------- k0a: mic MLP + A ----------------
__global__ void k0a(const float* __restrict__ mic_pos, const float* __restrict__ w_mic,
                    const float* __restrict__ b_mic, const float* __restrict__ b_in,
                    const float* __restrict__ A_log) {
    int tid = threadIdx.x;
    for (int i = tid; i < BB * 192; i += 256) {
        int b = i / 192, d = i % 192;
        float s = b_mic[d];
        #pragma unroll
        for (int j = 0; j < 12; j++) s = fmaf(mic_pos[b * 12 + j], w_mic[j * 192 + d], s);
        g_hb[i] = b_in[d] + fmaxf(s, 0.f);
    }
    if (tid < NH) g_A[tid] = -expf(A_log[tid]);
}

// ---------------- k0b: folded weights ----------------
__global__ void k0b(const float* __restrict__ w_in, const float* __restrict__ w_inproj,
                    const float* __restrict__ w_outproj, const float* __restrict__ w_mix1) {
    int i = blockIdx.x * 256 + threadIdx.x;
    if (i < 4 * DPROJ) {
        int j = i / DPROJ, d = i % DPROJ;
        float s = 0.f;
        for (int m = 0; m < 192; m++) s = fmaf(w_in[j * 192 + m], w_inproj[m * DPROJ + d], s);
        g_W1[i] = s;
    } else if (i < 4 * DPROJ + BB * DPROJ) {
        int ii = i - 4 * DPROJ;
        int b = ii / DPROJ, d = ii % DPROJ;
        float s = 0.f;
        for (int m = 0; m < 192; m++) s = fmaf(g_hb[b * 192 + m], w_inproj[m * DPROJ + d], s);
        g_mvec[ii] = s;
    } else if (i < 4 * DPROJ + BB * DPROJ + DINNER * MIXD) {
        int ii = i - (4 * DPROJ + BB * DPROJ);
        int d = ii / MIXD, o = ii % MIXD;
        float s = 0.f;
        for (int m = 0; m < 192; m++) s = fmaf(w_outproj[d * 192 + m], w_mix1[m * MIXD + o], s);
        g_W2[ii] = s;
    }
}

// ---------------- k1: fused inproj + conv4 + silu + dt/la ----------------
// grid (32, 16) block 128 : thread = one t
__global__ void k1(const float* __restrict__ x, const float* __restrict__ conv_w,
                   const float* __restrict__ conv_b, const float* __restrict__ dt_bias) {
    __shared__ float sW1[4 * 520];   // proj dims 384..903
    __shared__ float smv[520];
    __shared__ float scw[512 * 4];
    __shared__ float scb[512];
    __shared__ float sx4[131 * 4];
    __shared__ float sraw[131 * 33];

    int tid = threadIdx.x;
    int b = blockIdx.y;
    int t0 = blockIdx.x * 128;

    for (int i = tid; i < 4 * 520; i += 128) sW1[i] = g_W1[(i / 520) * DPROJ + 384 + (i % 520)];
    for (int i = tid; i < 520; i += 128) smv[i] = g_mvec[b * DPROJ + 384 + i];
    for (int i = tid; i < 512 * 4; i += 128) scw[i] = conv_w[i];
    for (int i = tid; i < 512; i += 128) scb[i] = conv_b[i];
    for (int i = tid; i < 131 * 4; i += 128) {
        int r = i >> 2, j = i & 3;
        int t = t0 + r - 3;
        sx4[i] = (t >= 0) ? x[((size_t)b * TT + t) * 4 + j] : 0.f;
    }

    int t = t0 + tid;
    for (int c16 = 0; c16 < 16; c16++) {
        __syncthreads();
        for (int i = tid; i < 131 * 32; i += 128) {
            int r = i >> 5, dc = i & 31;
            int dd = c16 * 32 + dc;
            float v = 0.f;
            if (t0 + r - 3 >= 0) {
                v = smv[dd];
                #pragma unroll
                for (int j = 0; j < 4; j++) v = fmaf(sx4[r * 4 + j], sW1[j * 520 + dd], v);
            }
            sraw[r * 33 + dc] = v;
        }
        __syncthreads();
        float v[32];
        #pragma unroll
        for (int dc = 0; dc < 32; dc++) {
            int dd = c16 * 32 + dc;
            float a = scb[dd];
            #pragma unroll
            for (int k = 0; k < 4; k++) a = fmaf(sraw[(tid + k) * 33 + dc], scw[dd * 4 + k], a);
            v[dc] = siluf(a);
        }
        float* dst;
        if (c16 < 12) dst = g_x + ((size_t)b * TT + t) * DINNER + c16 * 32;
        else          dst = g_bc + ((size_t)b * TT + t) * 128 + (c16 - 12) * 32;
        #pragma unroll
        for (int q = 0; q < 8; q++)
            ((float4*)dst)[q] = make_float4(v[4 * q], v[4 * q + 1], v[4 * q + 2], v[4 * q + 3]);
    }

    // dt path (proj dims 896..903 via sW1 dims 512..519)
    #pragma unroll
    for (int hh = 0; hh < NH; hh++) {
        int dd = 512 + hh;
        float v = smv[dd];
        #pragma unroll
        for (int j = 0; j < 4; j++) v = fmaf(sx4[(tid + 3) * 4 + j], sW1[j * 520 + dd], v);
        float dt = softplusf(v + dt_bias[hh]);
        size_t o = ((size_t)b * TT + t) * NH + hh;
        g_dt[o] = dt;
        g_la[o] = dt * g_A[hh];
    }
}

// ---------------- kA: chunk-local end states as GEMM ----------------
// grid (NC, 128) block 192 : thread = (ip, in) 12x16, 4x4 tile of S[48][64]
__global__ void kA() {
    __shared__ float sxw[CS * HD];   // [t][p] = w(t)*x(t,p)
    __shared__ float sB[CS * DS];    // [t][n]
    __shared__ float scs[CS];
    __shared__ float sdt[CS];

    int c = blockIdx.x, bh = blockIdx.y;
    int b = bh >> 3, h = bh & 7;
    int tid = threadIdx.x;
    int t0 = c * CS;

    // log-decay prefix sum (inclusive) over the chunk
    if (tid < CS) {
        size_t o = ((size_t)b * TT + t0 + tid) * NH + h;
        scs[tid] = g_la[o];
        sdt[tid] = g_dt[o];
    }
    __syncthreads();
    for (int off = 1; off < CS; off <<= 1) {
        float v = 0.f;
        if (tid < CS && tid >= off) v = scs[tid - off];
        __syncthreads();
        if (tid < CS) scs[tid] += v;
        __syncthreads();
    }

    const float* bp = g_bc + ((size_t)b * TT + t0) * 128;
    for (int i = tid; i < CS * 16; i += 192) {
        int r = i / 16, col = i % 16;
        ((float4*)sB)[r * 16 + col] = ((const float4*)(bp + (size_t)r * 128))[col];
    }
    float cstot = scs[CS - 1];
    const float* xp = g_x + ((size_t)b * TT + t0) * DINNER + h * HD;
    for (int i = tid; i < CS * 12; i += 192) {
        int r = i / 12, col = i % 12;
        float w = __expf(cstot - scs[r]) * sdt[r];
        float4 v = ((const float4*)(xp + (size_t)r * DINNER))[col];
        v.x *= w; v.y *= w; v.z *= w; v.w *= w;
        ((float4*)sxw)[r * 12 + col] = v;
    }
    __syncthreads();

    int in = tid & 15, ip = tid >> 4;   // n-tile, p-tile
    int n0 = in * 4, p0 = ip * 4;
    float acc[4][4];
    #pragma unroll
    for (int i = 0; i < 4; i++)
        #pragma unroll
        for (int j = 0; j < 4; j++) acc[i][j] = 0.f;

    #pragma unroll 4
    for (int t = 0; t < CS; t++) {
        float4 xw = *(const float4*)&sxw[t * HD + p0];
        float4 bb = *(const float4*)&sB[t * DS + n0];
        float xr[4] = {xw.x, xw.y, xw.z, xw.w};
        float br[4] = {bb.x, bb.y, bb.z, bb.w};
        #pragma unroll
        for (int i = 0; i < 4; i++)
            #pragma unroll
            for (int j = 0; j < 4; j++) acc[i][j] = fmaf(xr[i], br[j], acc[i][j]);
    }

    float* sp = g_S + ((size_t)bh * NC + c) * (HD * DS);
    #pragma unroll
    for (int i = 0; i < 4; i++)
        *(float4*)&sp[(p0 + i) * DS + n0] = make_float4(acc[i][0], acc[i][1], acc[i][2], acc[i][3]);
    if (tid == 0) g_Dc[bh * NC + c] = __expf(cstot);
}

// ---------------- kB: inter-chunk scan (in place: g_S becomes h_in) -------
__global__ void kB() {
    int bh = blockIdx.x, tid = threadIdx.x;
    float h8[8];
    #pragma unroll
    for (int k = 0; k < 8; k++) h8[k] = 0.f;
    size_t base = (size_t)bh * NC * (HD * DS) + tid * 8;
    for (int c = 0; c < NC; c++) {
        float* sp = g_S + base + (size_t)c * (HD * DS);
        float4 a = ((float4*)sp)[0];
        float4 d = ((float4*)sp)[1];
        ((float4*)sp)[0] = make_float4(h8[0], h8[1], h8[2], h8[3]);
        ((float4*)sp)[1] = make_float4(h8[4], h8[5], h8[6], h8[7]);
        float Dc = g_Dc[bh * NC + c];
        h8[0] = fmaf(h8[0], Dc, a.x); h8[1] = fmaf(h8[1], Dc, a.y);
        h8[2] = fmaf(h8[2], Dc, a.z); h8[3] = fmaf(h8[3], Dc, a.w);
        h8[4] = fmaf(h8[4], Dc, d.x); h8[5] = fmaf(h8[5], Dc, d.y);
        h8[6] = fmaf(h8[6], Dc, d.z); h8[7] = fmaf(h8[7], Dc, d.w);
    }
}

// ---------------- kC: chunked SSD via three GEMMs ----------------
// grid (NC, 128) block 256, dynamic smem
// smem layout (floats): sCt[64*68] | sBt/sG[64*68] | sx[64*48] | shin[64*52] | scs[64] | sdt[64]
#define KC_CT 0
#define KC_BT 4352
#define KC_SX 8704
#define KC_SHIN 11776
#define KC_SCS 15104
#define KC_SDT 15168
#define KC_SMEM_FLOATS 15232

__global__ __launch_bounds__(256) void kC(const float* __restrict__ D_skip) {
    extern __shared__ float sm[];
    float* sCt  = sm + KC_CT;    // [n][t] stride 68
    float* sBt  = sm + KC_BT;    // [n][s] stride 68 -> reused as sG [s][t] stride 68
    float* sx   = sm + KC_SX;    // [s][p] stride 48
    float* shin = sm + KC_SHIN;  // [n][p] stride 52
    float* scs  = sm + KC_SCS;
    float* sdt  = sm + KC_SDT;

    int c = blockIdx.x, bh = blockIdx.y;
    int b = bh >> 3, h = bh & 7;
    int tid = threadIdx.x;
    int t0c = c * CS;

    if (tid < CS) {
        size_t o = ((size_t)b * TT + t0c + tid) * NH + h;
        scs[tid] = g_la[o];
        sdt[tid] = g_dt[o];
    }
    __syncthreads();
    for (int off = 1; off < CS; off <<= 1) {
        float v = 0.f;
        if (tid < CS && tid >= off) v = scs[tid - off];
        __syncthreads();
        if (tid < CS) scs[tid] += v;
        __syncthreads();
    }

    // loads (transposed B,C; direct x; transposed h_in)
    const float* bp = g_bc + ((size_t)b * TT + t0c) * 128;
    for (int i = tid; i < CS * 16; i += 256) {
        int s = i >> 4, nq = i & 15;
        float4 v = ((const float4*)(bp + (size_t)s * 128))[nq];          // B[s][n]
        sBt[(nq * 4 + 0) * 68 + s] = v.x;
        sBt[(nq * 4 + 1) * 68 + s] = v.y;
        sBt[(nq * 4 + 2) * 68 + s] = v.z;
        sBt[(nq * 4 + 3) * 68 + s] = v.w;
        float4 w = ((const float4*)(bp + (size_t)s * 128))[nq + 16];     // C[s][n]
        sCt[(nq * 4 + 0) * 68 + s] = w.x;
        sCt[(nq * 4 + 1) * 68 + s] = w.y;
        sCt[(nq * 4 + 2) * 68 + s] = w.z;
        sCt[(nq * 4 + 3) * 68 + s] = w.w;
    }
    const float* xp = g_x + ((size_t)b * TT + t0c) * DINNER + h * HD;
    for (int i = tid; i < CS * 12; i += 256) {
        int s = i / 12, col = i % 12;
        ((float4*)(sx + s * HD))[col] = ((const float4*)(xp + (size_t)s * DINNER))[col];
    }
    const float* hp = g_S + ((size_t)bh * NC + c) * (HD * DS);
    for (int i = tid; i < HD * 16; i += 256) {
        int p = i >> 4, nq = i & 15;
        float4 v = ((const float4*)(hp + p * DS))[nq];
        shin[(nq * 4 + 0) * 52 + p] = v.x;
        shin[(nq * 4 + 1) * 52 + p] = v.y;
        shin[(nq * 4 + 2) * 52 + p] = v.z;
        shin[(nq * 4 + 3) * 52 + p] = v.w;
    }
    __syncthreads();

    // GEMM1: G[t][s] = sum_n C[t][n]*B[s][n]
    int it = tid & 15, is = tid >> 4;
    int tt0 = it * 4, ss0 = is * 4;
    float g4[4][4];
    #pragma unroll
    for (int i = 0; i < 4; i++)
        #pragma unroll
        for (int j = 0; j < 4; j++) g4[i][j] = 0.f;
    #pragma unroll 4
    for (int n = 0; n < DS; n++) {
        float4 cc = *(const float4*)&sCt[n * 68 + tt0];
        float4 bb = *(const float4*)&sBt[n * 68 + ss0];
        float cr[4] = {cc.x, cc.y, cc.z, cc.w};
        float br[4] = {bb.x, bb.y, bb.z, bb.w};
        #pragma unroll
        for (int i = 0; i < 4; i++)
            #pragma unroll
            for (int j = 0; j < 4; j++) g4[i][j] = fmaf(cr[i], br[j], g4[i][j]);
    }
    __syncthreads();   // all reads of sBt done before overwrite

    // mask+scale, store transposed into sG = sBt buffer: sG[s][t]
    #pragma unroll
    for (int j = 0; j < 4; j++) {
        int s = ss0 + j;
        float csj = scs[s], dtj = sdt[s];
        #pragma unroll
        for (int i = 0; i < 4; i++) {
            int t = tt0 + i;
            float m = (s <= t) ? __expf(scs[t] - csj) * dtj : 0.f;
            sBt[s * 68 + t] = g4[i][j] * m;
        }
    }
    __syncthreads();

    // GEMM2: Yintra[t][p] = sum_s G'[t][s]*x[s][p]
    // GEMM3: Yinter[t][p] = sum_n Ct[n][t]*hin[n][p]
    int it2 = tid & 15, ip = tid >> 4;
    int tb = it2 * 4, p0 = ip * 3;
    float accA[4][3], accB[4][3];
    #pragma unroll
    for (int i = 0; i < 4; i++)
        #pragma unroll
        for (int j = 0; j < 3; j++) { accA[i][j] = 0.f; accB[i][j] = 0.f; }

    #pragma unroll 4
    for (int s = 0; s < CS; s++) {
        float4 g = *(const float4*)&sBt[s * 68 + tb];
        float gr[4] = {g.x, g.y, g.z, g.w};
        float xr[3] = {sx[s * HD + p0], sx[s * HD + p0 + 1], sx[s * HD + p0 + 2]};
        #pragma unroll
        for (int i = 0; i < 4; i++)
            #pragma unroll
            for (int j = 0; j < 3; j++) accA[i][j] = fmaf(gr[i], xr[j], accA[i][j]);
    }
    #pragma unroll 4
    for (int n = 0; n < DS; n++) {
        float4 cc = *(const float4*)&sCt[n * 68 + tb];
        float cr[4] = {cc.x, cc.y, cc.z, cc.w};
        float hr[3] = {shin[n * 52 + p0], shin[n * 52 + p0 + 1], shin[n * 52 + p0 + 2]};
        #pragma unroll
        for (int i = 0; i < 4; i++)
            #pragma unroll
            for (int j = 0; j < 3; j++) accB[i][j] = fmaf(cr[i], hr[j], accB[i][j]);
    }

    float dskip = D_skip[h];
    float* yp = g_y + ((size_t)b * TT + t0c) * DINNER + h * HD;
    #pragma unroll
    for (int i = 0; i < 4; i++) {
        int t = tb + i;
        float et = __expf(scs[t]);
        #pragma unroll
        for (int j = 0; j < 3; j++) {
            float y = accA[i][j] + et * accB[i][j] + dskip * sx[t * HD + p0 + j];
            yp[(size_t)t * DINNER + p0 + j] = y;
        }
    }
}

// ---------------- kD: gating + RMSNorm + GEMM(W2) + mix2 + partial ------
// grid (128, 16) block 256, 32 rows/block, dynamic smem
#define KD_SG 0            // 32*388
#define KD_SWM2 12416      // 1024
#define KD_SW1Z 13440      // 1536
#define KD_SMV 14976       // 384
#define KD_SNW 15360       // 384
#define KD_SM1 15744       // 32*33
#define KD_SRSTD 16800     // 32
#define KD_SMEM_FLOATS 16832

__global__ __launch_bounds__(256) void kD(const float* __restrict__ x, const float* __restrict__ norm_w,
                   const float* __restrict__ w_mix2, const float* __restrict__ b_mix1,
                   const float* __restrict__ b_mix2) {
    extern __shared__ float sm[];
    float* sg   = sm + KD_SG;     // [r][dd] stride 388
    float* swm2 = sm + KD_SWM2;
    float* sW1z = sm + KD_SW1Z;
    float* smv  = sm + KD_SMV;
    float* snw  = sm + KD_SNW;
    float* sm1  = sm + KD_SM1;    // [r][o] stride 33
    float* srstd= sm + KD_SRSTD;

    int tid = threadIdx.x;
    int b = blockIdx.y;
    int t0 = blockIdx.x * 32;

    for (int i = tid; i < DINNER; i += 256) { smv[i] = g_mvec[b * DPROJ + i]; snw[i] = norm_w[i]; }
    for (int i = tid; i < 4 * DINNER; i += 256) sW1z[i] = g_W1[(i / DINNER) * DPROJ + (i % DINNER)];
    for (int i = tid; i < MIXD * MIXD; i += 256) swm2[i] = w_mix2[i];
    __syncthreads();

    // phase 1: gating, store g to smem, row sum-of-squares
    int r = tid >> 3, seg = tid & 7;
    int dd0 = seg * 48;
    const float* xr = x + ((size_t)b * TT + t0 + r) * 4;
    float x0 = xr[0], x1 = xr[1], x2 = xr[2], x3 = xr[3];
    const float* yr = g_y + ((size_t)b * TT + t0 + r) * DINNER + dd0;
    float ss = 0.f;
    #pragma unroll
    for (int q = 0; q < 12; q++) {
        float4 y4 = ((const float4*)yr)[q];
        float gv[4] = {y4.x, y4.y, y4.z, y4.w};
        #pragma unroll
        for (int u = 0; u < 4; u++) {
            int dd = dd0 + q * 4 + u;
            float z = smv[dd];
            z = fmaf(x0, sW1z[dd], z);
            z = fmaf(x1, sW1z[DINNER + dd], z);
            z = fmaf(x2, sW1z[2 * DINNER + dd], z);
            z = fmaf(x3, sW1z[3 * DINNER + dd], z);
            float g = gv[u] * siluf(z);
            gv[u] = g;
            ss = fmaf(g, g, ss);
        }
        *(float4*)&sg[r * 388 + dd0 + q * 4] = make_float4(gv[0], gv[1], gv[2], gv[3]);
    }
    ss += __shfl_xor_sync(0xffffffffu, ss, 1);
    ss += __shfl_xor_sync(0xffffffffu, ss, 2);
    ss += __shfl_xor_sync(0xffffffffu, ss, 4);
    if (seg == 0) srstd[r] = rsqrtf(ss * (1.f / DINNER) + 1e-5f);
    __syncthreads();

    // rescale by rstd * norm_w
    {
        float rs = srstd[r];
        #pragma unroll
        for (int q = 0; q < 48; q++) {
            int dd = dd0 + q;
            sg[r * 388 + dd] *= rs * snw[dd];
        }
    }
    __syncthreads();

    // GEMM: m[r][o] = sum_dd sg[r][dd] * W2[dd][o]   (W2 via L1)
    int io4 = tid & 7, r2 = tid >> 3;
    int o0 = io4 * 4;
    float acc[4] = {0.f, 0.f, 0.f, 0.f};
    const float* gr = sg + r2 * 388;
    #pragma unroll 8
    for (int dd = 0; dd < DINNER; dd++) {
        float g = gr[dd];
        float4 w = __ldg((const float4*)&g_W2[dd * MIXD + o0]);
        acc[0] = fmaf(g, w.x, acc[0]);
        acc[1] = fmaf(g, w.y, acc[1]);
        acc[2] = fmaf(g, w.z, acc[2]);
        acc[3] = fmaf(g, w.w, acc[3]);
    }
    #pragma unroll
    for (int u = 0; u < 4; u++) sm1[r2 * 33 + o0 + u] = fmaxf(acc[u] + b_mix1[o0 + u], 0.f);
    __syncthreads();

    // mix2 + relu
    float m2[4] = {b_mix2[o0], b_mix2[o0 + 1], b_mix2[o0 + 2], b_mix2[o0 + 3]};
    #pragma unroll
    for (int i = 0; i < MIXD; i++) {
        float m = sm1[r2 * 33 + i];
        float4 w = *(const float4*)&swm2[i * MIXD + o0];
        m2[0] = fmaf(m, w.x, m2[0]);
        m2[1] = fmaf(m, w.y, m2[1]);
        m2[2] = fmaf(m, w.z, m2[2]);
        m2[3] = fmaf(m, w.w, m2[3]);
    }
    // block reduce over 32 rows: reuse sg area as [r][o] stride 33
    float* sred = sg;
    #pragma unroll
    for (int u = 0; u < 4; u++) sred[r2 * 33 + o0 + u] = fmaxf(m2[u], 0.f);
    __syncthreads();
    if (tid < MIXD) {
        float a = 0.f;
        for (int rr = 0; rr < 32; rr++) a += sred[rr * 33 + tid];
        g_part[((size_t)b * 128 + blockIdx.x) * MIXD + tid] = a;
    }
}

// ---------------- kF: final mean + w_out ----------------
__global__ void kF(const float* __restrict__ w_out, const float* __restrict__ b_out,
                   float* __restrict__ out) {
    int b = threadIdx.x;
    if (b < BB) {
        float s = 0.f;
        for (int o = 0; o < MIXD; o++) {
            float a = 0.f;
            for (int blk = 0; blk < 128; blk++) a += g_part[((size_t)b * 128 + blk) * MIXD + o];
            s = fmaf(a * (1.f / (float)TT), w_out[o], s);
        }
        out[b] = s + b_out[0];
    }
}

extern "C" void kernel_launch(void* const* d_in, const int* in_sizes, int n_in,
                              void* d_out, int out_size) {
    const float* x        = (const float*)d_in[0];
    const float* mic_pos  = (const float*)d_in[1];
    const float* w_in     = (const float*)d_in[2];
    const float* b_in     = (const float*)d_in[3];
    const float* w_mic    = (const float*)d_in[4];
    const float* b_mic    = (const float*)d_in[5];
    const float* w_inproj = (const float*)d_in[6];
    const float* conv_w   = (const float*)d_in[7];
    const float* conv_b   = (const float*)d_in[8];
    const float* dt_bias  = (const float*)d_in[9];
    const float* A_log    = (const float*)d_in[10];
    const float* D_skip   = (const float*)d_in[11];
    const float* norm_w   = (const float*)d_in[12];
    const float* w_outproj= (const float*)d_in[13];
    const float* w_mix1   = (const float*)d_in[14];
    const float* b_mix1   = (const float*)d_in[15];
    const float* w_mix2   = (const float*)d_in[16];
    const float* b_mix2   = (const float*)d_in[17];
    const float* w_out    = (const float*)d_in[18];
    const float* b_out    = (const float*)d_in[19];
    float* out = (float*)d_out;

    cudaFuncSetAttribute(kC, cudaFuncAttributeMaxDynamicSharedMemorySize, KC_SMEM_FLOATS * 4);
    cudaFuncSetAttribute(kD, cudaFuncAttributeMaxDynamicSharedMemorySize, KD_SMEM_FLOATS * 4);

    k0a<<<1, 256>>>(mic_pos, w_mic, b_mic, b_in, A_log);
    k0b<<<(4 * DPROJ + BB * DPROJ + DINNER * MIXD + 255) / 256, 256>>>(w_in, w_inproj, w_outproj, w_mix1);
    k1<<<dim3(32, 16), 128>>>(x, conv_w, conv_b, dt_bias);
    kA<<<dim3(NC, 128), 192>>>();
    kB<<<128, 384>>>();
    kC<<<dim3(NC, 128), 256, KC_SMEM_FLOATS * 4>>>(D_skip);
    kD<<<dim3(128, 16), 256, KD_SMEM_FLOATS * 4>>>(x, norm_w, w_mix2, b_mix1, b_mix2);
    kF<<<1, 32>>>(w_out, b_out, out);
}

// round 4
// speedup vs baseline: 1.5723x; 1.1161x over previous
#include <cuda_runtime.h>
#include <math.h>

#define BB 16
#define TT 4096
#define DINNER 384
#define NH 8
#define HD 48
#define DS 64
#define DPROJ 904
#define NC 64
#define CS 64
#define MIXD 32

// ---------------- scratch (static device arrays; no runtime alloc) ----------
__device__ float g_W1[4 * DPROJ];            // w_in @ w_inproj
__device__ float g_mvec[BB * DPROJ];         // (b_in + relu(mic)) @ w_inproj
__device__ float g_W2[DINNER * MIXD];        // w_outproj @ w_mix1
__device__ float g_hb[BB * 192];
__device__ float g_A[NH];
__device__ float g_x[(size_t)BB * TT * DINNER];   // silu(conv) xs
__device__ float g_bc[(size_t)BB * TT * 128];     // B(64) | C(64)
__device__ float g_dt[(size_t)BB * TT * NH];
__device__ float g_la[(size_t)BB * TT * NH];      // log-decay = dt*A
__device__ float g_S[(size_t)128 * NC * HD * DS]; // chunk states -> h_in (in place)
__device__ float g_Dc[128 * NC];
__device__ float g_y[(size_t)BB * TT * DINNER];
__device__ float g_part[2048 * MIXD];

__device__ __forceinline__ float siluf(float v) { return __fdividef(v, 1.f + __expf(-v)); }
__device__ __forceinline__ float softplusf(float v) { return v > 20.f ? v : __logf(1.f + __expf(v)); }

// ---------------- k0a: mic MLP + A ----------------
__global__ void k0a(const float* __restrict__ mic_pos, const float* __restrict__ w_mic,
                    const float* __restrict__ b_mic, const float* __restrict__ b_in,
                    const float* __restrict__ A_log) {
    int tid = threadIdx.x;
    for (int i = tid; i < BB * 192; i += 256) {
        int b = i / 192, d = i % 192;
        float s = b_mic[d];
        #pragma unroll
        for (int j = 0; j < 12; j++) s = fmaf(mic_pos[b * 12 + j], w_mic[j * 192 + d], s);
        g_hb[i] = b_in[d] + fmaxf(s, 0.f);
    }
    if (tid < NH) g_A[tid] = -expf(A_log[tid]);
}

// ---------------- k0b: folded weights ----------------
__global__ void k0b(const float* __restrict__ w_in, const float* __restrict__ w_inproj,
                    const float* __restrict__ w_outproj, const float* __restrict__ w_mix1) {
    int i = blockIdx.x * 256 + threadIdx.x;
    if (i < 4 * DPROJ) {
        int j = i / DPROJ, d = i % DPROJ;
        float s = 0.f;
        for (int m = 0; m < 192; m++) s = fmaf(w_in[j * 192 + m], w_inproj[m * DPROJ + d], s);
        g_W1[i] = s;
    } else if (i < 4 * DPROJ + BB * DPROJ) {
        int ii = i - 4 * DPROJ;
        int b = ii / DPROJ, d = ii % DPROJ;
        float s = 0.f;
        for (int m = 0; m < 192; m++) s = fmaf(g_hb[b * 192 + m], w_inproj[m * DPROJ + d], s);
        g_mvec[ii] = s;
    } else if (i < 4 * DPROJ + BB * DPROJ + DINNER * MIXD) {
        int ii = i - (4 * DPROJ + BB * DPROJ);
        int d = ii / MIXD, o = ii % MIXD;
        float s = 0.f;
        for (int m = 0; m < 192; m++) s = fmaf(w_outproj[d * 192 + m], w_mix1[m * MIXD + o], s);
        g_W2[ii] = s;
    }
}

// ---------------- k1: fused inproj + conv4 + silu + dt/la ----------------
// grid (32, 16) block 128 : thread = one t
__global__ void k1(const float* __restrict__ x, const float* __restrict__ conv_w,
                   const float* __restrict__ conv_b, const float* __restrict__ dt_bias) {
    __shared__ float sW1[4 * 520];   // proj dims 384..903
    __shared__ float smv[520];
    __shared__ float scw[512 * 4];
    __shared__ float scb[512];
    __shared__ float sx4[131 * 4];
    __shared__ float sraw[131 * 33];

    int tid = threadIdx.x;
    int b = blockIdx.y;
    int t0 = blockIdx.x * 128;

    for (int i = tid; i < 4 * 520; i += 128) sW1[i] = g_W1[(i / 520) * DPROJ + 384 + (i % 520)];
    for (int i = tid; i < 520; i += 128) smv[i] = g_mvec[b * DPROJ + 384 + i];
    for (int i = tid; i < 512 * 4; i += 128) scw[i] = conv_w[i];
    for (int i = tid; i < 512; i += 128) scb[i] = conv_b[i];
    for (int i = tid; i < 131 * 4; i += 128) {
        int r = i >> 2, j = i & 3;
        int t = t0 + r - 3;
        sx4[i] = (t >= 0) ? x[((size_t)b * TT + t) * 4 + j] : 0.f;
    }

    int t = t0 + tid;
    for (int c16 = 0; c16 < 16; c16++) {
        __syncthreads();
        for (int i = tid; i < 131 * 32; i += 128) {
            int r = i >> 5, dc = i & 31;
            int dd = c16 * 32 + dc;
            float v = 0.f;
            if (t0 + r - 3 >= 0) {
                v = smv[dd];
                #pragma unroll
                for (int j = 0; j < 4; j++) v = fmaf(sx4[r * 4 + j], sW1[j * 520 + dd], v);
            }
            sraw[r * 33 + dc] = v;
        }
        __syncthreads();
        float v[32];
        #pragma unroll
        for (int dc = 0; dc < 32; dc++) {
            int dd = c16 * 32 + dc;
            float a = scb[dd];
            #pragma unroll
            for (int k = 0; k < 4; k++) a = fmaf(sraw[(tid + k) * 33 + dc], scw[dd * 4 + k], a);
            v[dc] = siluf(a);
        }
        float* dst;
        if (c16 < 12) dst = g_x + ((size_t)b * TT + t) * DINNER + c16 * 32;
        else          dst = g_bc + ((size_t)b * TT + t) * 128 + (c16 - 12) * 32;
        #pragma unroll
        for (int q = 0; q < 8; q++)
            ((float4*)dst)[q] = make_float4(v[4 * q], v[4 * q + 1], v[4 * q + 2], v[4 * q + 3]);
    }

    // dt path (proj dims 896..903 via sW1 dims 512..519)
    #pragma unroll
    for (int hh = 0; hh < NH; hh++) {
        int dd = 512 + hh;
        float v = smv[dd];
        #pragma unroll
        for (int j = 0; j < 4; j++) v = fmaf(sx4[(tid + 3) * 4 + j], sW1[j * 520 + dd], v);
        float dt = softplusf(v + dt_bias[hh]);
        size_t o = ((size_t)b * TT + t) * NH + hh;
        g_dt[o] = dt;
        g_la[o] = dt * g_A[hh];
    }
}

// ---------------- kA: chunk-local end states as GEMM ----------------
// grid (NC, 128) block 192 : thread = (ip, in) 12x16, 4x4 tile of S[48][64]
__global__ void kA() {
    __shared__ float sxw[CS * HD];   // [t][p] = w(t)*x(t,p)
    __shared__ float sB[CS * DS];    // [t][n]
    __shared__ float scs[CS];
    __shared__ float sdt[CS];

    int c = blockIdx.x, bh = blockIdx.y;
    int b = bh >> 3, h = bh & 7;
    int tid = threadIdx.x;
    int t0 = c * CS;

    // log-decay prefix sum (inclusive) over the chunk
    if (tid < CS) {
        size_t o = ((size_t)b * TT + t0 + tid) * NH + h;
        scs[tid] = g_la[o];
        sdt[tid] = g_dt[o];
    }
    __syncthreads();
    for (int off = 1; off < CS; off <<= 1) {
        float v = 0.f;
        if (tid < CS && tid >= off) v = scs[tid - off];
        __syncthreads();
        if (tid < CS) scs[tid] += v;
        __syncthreads();
    }

    const float* bp = g_bc + ((size_t)b * TT + t0) * 128;
    for (int i = tid; i < CS * 16; i += 192) {
        int r = i / 16, col = i % 16;
        ((float4*)sB)[r * 16 + col] = ((const float4*)(bp + (size_t)r * 128))[col];
    }
    float cstot = scs[CS - 1];
    const float* xp = g_x + ((size_t)b * TT + t0) * DINNER + h * HD;
    for (int i = tid; i < CS * 12; i += 192) {
        int r = i / 12, col = i % 12;
        float w = __expf(cstot - scs[r]) * sdt[r];
        float4 v = ((const float4*)(xp + (size_t)r * DINNER))[col];
        v.x *= w; v.y *= w; v.z *= w; v.w *= w;
        ((float4*)sxw)[r * 12 + col] = v;
    }
    __syncthreads();

    int in = tid & 15, ip = tid >> 4;   // n-tile, p-tile
    int n0 = in * 4, p0 = ip * 4;
    float acc[4][4];
    #pragma unroll
    for (int i = 0; i < 4; i++)
        #pragma unroll
        for (int j = 0; j < 4; j++) acc[i][j] = 0.f;

    #pragma unroll 4
    for (int t = 0; t < CS; t++) {
        float4 xw = *(const float4*)&sxw[t * HD + p0];
        float4 bb = *(const float4*)&sB[t * DS + n0];
        float xr[4] = {xw.x, xw.y, xw.z, xw.w};
        float br[4] = {bb.x, bb.y, bb.z, bb.w};
        #pragma unroll
        for (int i = 0; i < 4; i++)
            #pragma unroll
            for (int j = 0; j < 4; j++) acc[i][j] = fmaf(xr[i], br[j], acc[i][j]);
    }

    float* sp = g_S + ((size_t)bh * NC + c) * (HD * DS);
    #pragma unroll
    for (int i = 0; i < 4; i++)
        *(float4*)&sp[(p0 + i) * DS + n0] = make_float4(acc[i][0], acc[i][1], acc[i][2], acc[i][3]);
    if (tid == 0) g_Dc[bh * NC + c] = __expf(cstot);
}

// ---------------- kB: inter-chunk scan (in place: g_S becomes h_in) -------
// grid (128, 2) block 384 : thread owns 4 contiguous states
__global__ void kB() {
    int bh = blockIdx.x, half = blockIdx.y;
    int tid = threadIdx.x;
    float h4[4] = {0.f, 0.f, 0.f, 0.f};
    size_t base = (size_t)bh * NC * (HD * DS) + (size_t)half * 1536 + tid * 4;
    for (int c = 0; c < NC; c++) {
        float* sp = g_S + base + (size_t)c * (HD * DS);
        float4 a = *(float4*)sp;
        *(float4*)sp = make_float4(h4[0], h4[1], h4[2], h4[3]);
        float Dc = g_Dc[bh * NC + c];
        h4[0] = fmaf(h4[0], Dc, a.x); h4[1] = fmaf(h4[1], Dc, a.y);
        h4[2] = fmaf(h4[2], Dc, a.z); h4[3] = fmaf(h4[3], Dc, a.w);
    }
}

// ---------------- kC: chunked SSD, all 8 heads per block ----------------
// grid (NC, BB) block 256, dynamic smem
// smem floats: sCt[64*68] | sBt/sG[64*68] | sx[64*48] | shin[64*52] | sCS[8*64] | sDT[8*64]
#define KC_CT 0
#define KC_BT 4352
#define KC_SX 8704
#define KC_SHIN 11776
#define KC_SCS 15104
#define KC_SDT 15616
#define KC_SMEM_FLOATS 16128

__global__ __launch_bounds__(256) void kC(const float* __restrict__ D_skip) {
    extern __shared__ float sm[];
    float* sCt  = sm + KC_CT;    // [n][t] stride 68
    float* sBt  = sm + KC_BT;    // [n][s] stride 68 -> reused as sG [s][t] stride 68
    float* sx   = sm + KC_SX;    // [s][p] stride 48 (per head)
    float* shin = sm + KC_SHIN;  // [n][p] stride 52 (per head)
    float* sCS  = sm + KC_SCS;   // [h][t] inclusive log-decay prefix
    float* sDT  = sm + KC_SDT;   // [h][t]

    int c = blockIdx.x, b = blockIdx.y;
    int tid = threadIdx.x;
    int wid = tid >> 5, lane = tid & 31;
    int t0c = c * CS;

    // load la/dt for all heads (contiguous 512 floats each), transpose to [h][t]
    if (tid < 128) {
        const float* lap = g_la + ((size_t)b * TT + t0c) * NH;
        const float* dtp = g_dt + ((size_t)b * TT + t0c) * NH;
        float4 v = ((const float4*)lap)[tid];
        float4 w = ((const float4*)dtp)[tid];
        int j0 = tid * 4;
        #pragma unroll
        for (int u = 0; u < 4; u++) {
            int j = j0 + u;
            int t = j >> 3, h = j & 7;
            sCS[h * 64 + t] = (&v.x)[u];
            sDT[h * 64 + t] = (&w.x)[u];
        }
    }

    // load B,C transposed
    const float* bp = g_bc + ((size_t)b * TT + t0c) * 128;
    for (int i = tid; i < CS * 16; i += 256) {
        int s = i >> 4, nq = i & 15;
        float4 v = ((const float4*)(bp + (size_t)s * 128))[nq];          // B[s][n]
        sBt[(nq * 4 + 0) * 68 + s] = v.x;
        sBt[(nq * 4 + 1) * 68 + s] = v.y;
        sBt[(nq * 4 + 2) * 68 + s] = v.z;
        sBt[(nq * 4 + 3) * 68 + s] = v.w;
        float4 w = ((const float4*)(bp + (size_t)s * 128))[nq + 16];     // C[s][n]
        sCt[(nq * 4 + 0) * 68 + s] = w.x;
        sCt[(nq * 4 + 1) * 68 + s] = w.y;
        sCt[(nq * 4 + 2) * 68 + s] = w.z;
        sCt[(nq * 4 + 3) * 68 + s] = w.w;
    }
    __syncthreads();

    // per-head inclusive prefix scan via warp shuffles: warp w = head w
    {
        float a0 = sCS[wid * 64 + 2 * lane];
        float a1 = sCS[wid * 64 + 2 * lane + 1];
        float ps = a0 + a1;
        #pragma unroll
        for (int off = 1; off < 32; off <<= 1) {
            float v = __shfl_up_sync(0xffffffffu, ps, off);
            if (lane >= off) ps += v;
        }
        sCS[wid * 64 + 2 * lane + 1] = ps;
        sCS[wid * 64 + 2 * lane]     = ps - a1;
    }

    // GEMM1 (shared across heads): raw[t][s] = sum_n C[t][n]*B[s][n], kept in regs
    int it = tid & 15, is = tid >> 4;
    int tt0 = it * 4, ss0 = is * 4;
    float g4[4][4];
    #pragma unroll
    for (int i = 0; i < 4; i++)
        #pragma unroll
        for (int j = 0; j < 4; j++) g4[i][j] = 0.f;
    #pragma unroll 4
    for (int n = 0; n < DS; n++) {
        float4 cc = *(const float4*)&sCt[n * 68 + tt0];
        float4 bb = *(const float4*)&sBt[n * 68 + ss0];
        float cr[4] = {cc.x, cc.y, cc.z, cc.w};
        float br[4] = {bb.x, bb.y, bb.z, bb.w};
        #pragma unroll
        for (int i = 0; i < 4; i++)
            #pragma unroll
            for (int j = 0; j < 4; j++) g4[i][j] = fmaf(cr[i], br[j], g4[i][j]);
    }

    int it2 = tid & 15, ip = tid >> 4;
    int tb = it2 * 4, p0 = ip * 3;

    for (int h = 0; h < NH; h++) {
        __syncthreads();   // prior readers of sBt/sG/sx/shin done (also orders scan & GEMM1)

        // load x and h_in for this head
        const float* xp = g_x + ((size_t)b * TT + t0c) * DINNER + h * HD;
        for (int i = tid; i < CS * 12; i += 256) {
            int s = i / 12, col = i % 12;
            ((float4*)(sx + s * HD))[col] = ((const float4*)(xp + (size_t)s * DINNER))[col];
        }
        const float* hp = g_S + ((size_t)(b * NH + h) * NC + c) * (HD * DS);
        for (int i = tid; i < HD * 16; i += 256) {
            int p = i >> 4, nq = i & 15;
            float4 v = ((const float4*)(hp + p * DS))[nq];
            shin[(nq * 4 + 0) * 52 + p] = v.x;
            shin[(nq * 4 + 1) * 52 + p] = v.y;
            shin[(nq * 4 + 2) * 52 + p] = v.z;
            shin[(nq * 4 + 3) * 52 + p] = v.w;
        }

        // mask+scale raw CB^T with this head's decay, store transposed: sG[s][t]
        const float* csh = sCS + h * 64;
        const float* dth = sDT + h * 64;
        #pragma unroll
        for (int j = 0; j < 4; j++) {
            int s = ss0 + j;
            float csj = csh[s], dtj = dth[s];
            #pragma unroll
            for (int i = 0; i < 4; i++) {
                int t = tt0 + i;
                float m = (s <= t) ? __expf(csh[t] - csj) * dtj : 0.f;
                sBt[s * 68 + t] = g4[i][j] * m;
            }
        }
        __syncthreads();

        // GEMM2: Yintra[t][p] = sum_s G[t][s]*x[s][p]
        // GEMM3: Yinter[t][p] = sum_n Ct[n][t]*hin[n][p]
        float accA[4][3], accB[4][3];
        #pragma unroll
        for (int i = 0; i < 4; i++)
            #pragma unroll
            for (int j = 0; j < 3; j++) { accA[i][j] = 0.f; accB[i][j] = 0.f; }

        #pragma unroll 4
        for (int s = 0; s < CS; s++) {
            float4 g = *(const float4*)&sBt[s * 68 + tb];
            float gr[4] = {g.x, g.y, g.z, g.w};
            float xr[3] = {sx[s * HD + p0], sx[s * HD + p0 + 1], sx[s * HD + p0 + 2]};
            #pragma unroll
            for (int i = 0; i < 4; i++)
                #pragma unroll
                for (int j = 0; j < 3; j++) accA[i][j] = fmaf(gr[i], xr[j], accA[i][j]);
        }
        #pragma unroll 4
        for (int n = 0; n < DS; n++) {
            float4 cc = *(const float4*)&sCt[n * 68 + tb];
            float cr[4] = {cc.x, cc.y, cc.z, cc.w};
            float hr[3] = {shin[n * 52 + p0], shin[n * 52 + p0 + 1], shin[n * 52 + p0 + 2]};
            #pragma unroll
            for (int i = 0; i < 4; i++)
                #pragma unroll
                for (int j = 0; j < 3; j++) accB[i][j] = fmaf(cr[i], hr[j], accB[i][j]);
        }

        float dskip = D_skip[h];
        float* yp = g_y + ((size_t)b * TT + t0c) * DINNER + h * HD;
        #pragma unroll
        for (int i = 0; i < 4; i++) {
            int t = tb + i;
            float et = __expf(csh[t]);
            #pragma unroll
            for (int j = 0; j < 3; j++) {
                float y = accA[i][j] + et * accB[i][j] + dskip * sx[t * HD + p0 + j];
                yp[(size_t)t * DINNER + p0 + j] = y;
            }
        }
    }
}

// ---------------- kD: gating + RMSNorm + GEMM(W2) + mix2 + partial ------
// grid (128, 16) block 256, 32 rows/block, dynamic smem
#define KD_SG 0            // 32*388
#define KD_SWM2 12416      // 1024
#define KD_SW1Z 13440      // 1536
#define KD_SMV 14976       // 384
#define KD_SNW 15360       // 384
#define KD_SM1 15744       // 32*33
#define KD_SRSTD 16800     // 32
#define KD_SMEM_FLOATS 16832

__global__ __launch_bounds__(256) void kD(const float* __restrict__ x, const float* __restrict__ norm_w,
                   const float* __restrict__ w_mix2, const float* __restrict__ b_mix1,
                   const float* __restrict__ b_mix2) {
    extern __shared__ float sm[];
    float* sg   = sm + KD_SG;     // [r][dd] stride 388
    float* swm2 = sm + KD_SWM2;
    float* sW1z = sm + KD_SW1Z;
    float* smv  = sm + KD_SMV;
    float* snw  = sm + KD_SNW;
    float* sm1  = sm + KD_SM1;    // [r][o] stride 33
    float* srstd= sm + KD_SRSTD;

    int tid = threadIdx.x;
    int b = blockIdx.y;
    int t0 = blockIdx.x * 32;

    for (int i = tid; i < DINNER; i += 256) { smv[i] = g_mvec[b * DPROJ + i]; snw[i] = norm_w[i]; }
    for (int i = tid; i < 4 * DINNER; i += 256) sW1z[i] = g_W1[(i / DINNER) * DPROJ + (i % DINNER)];
    for (int i = tid; i < MIXD * MIXD; i += 256) swm2[i] = w_mix2[i];
    __syncthreads();

    // phase 1: gating, store g to smem, row sum-of-squares
    int r = tid >> 3, seg = tid & 7;
    int dd0 = seg * 48;
    const float* xr = x + ((size_t)b * TT + t0 + r) * 4;
    float x0 = xr[0], x1 = xr[1], x2 = xr[2], x3 = xr[3];
    const float* yr = g_y + ((size_t)b * TT + t0 + r) * DINNER + dd0;
    float ss = 0.f;
    #pragma unroll
    for (int q = 0; q < 12; q++) {
        float4 y4 = ((const float4*)yr)[q];
        float gv[4] = {y4.x, y4.y, y4.z, y4.w};
        #pragma unroll
        for (int u = 0; u < 4; u++) {
            int dd = dd0 + q * 4 + u;
            float z = smv[dd];
            z = fmaf(x0, sW1z[dd], z);
            z = fmaf(x1, sW1z[DINNER + dd], z);
            z = fmaf(x2, sW1z[2 * DINNER + dd], z);
            z = fmaf(x3, sW1z[3 * DINNER + dd], z);
            float g = gv[u] * siluf(z);
            gv[u] = g;
            ss = fmaf(g, g, ss);
        }
        *(float4*)&sg[r * 388 + dd0 + q * 4] = make_float4(gv[0], gv[1], gv[2], gv[3]);
    }
    ss += __shfl_xor_sync(0xffffffffu, ss, 1);
    ss += __shfl_xor_sync(0xffffffffu, ss, 2);
    ss += __shfl_xor_sync(0xffffffffu, ss, 4);
    if (seg == 0) srstd[r] = rsqrtf(ss * (1.f / DINNER) + 1e-5f);
    __syncthreads();

    // rescale by rstd * norm_w
    {
        float rs = srstd[r];
        #pragma unroll
        for (int q = 0; q < 48; q++) {
            int dd = dd0 + q;
            sg[r * 388 + dd] *= rs * snw[dd];
        }
    }
    __syncthreads();

    // GEMM: m[r][o] = sum_dd sg[r][dd] * W2[dd][o]   (W2 via L1)
    int io4 = tid & 7, r2 = tid >> 3;
    int o0 = io4 * 4;
    float acc[4] = {0.f, 0.f, 0.f, 0.f};
    const float* gr = sg + r2 * 388;
    #pragma unroll 8
    for (int dd = 0; dd < DINNER; dd++) {
        float g = gr[dd];
        float4 w = __ldg((const float4*)&g_W2[dd * MIXD + o0]);
        acc[0] = fmaf(g, w.x, acc[0]);
        acc[1] = fmaf(g, w.y, acc[1]);
        acc[2] = fmaf(g, w.z, acc[2]);
        acc[3] = fmaf(g, w.w, acc[3]);
    }
    #pragma unroll
    for (int u = 0; u < 4; u++) sm1[r2 * 33 + o0 + u] = fmaxf(acc[u] + b_mix1[o0 + u], 0.f);
    __syncthreads();

    // mix2 + relu
    float m2[4] = {b_mix2[o0], b_mix2[o0 + 1], b_mix2[o0 + 2], b_mix2[o0 + 3]};
    #pragma unroll
    for (int i = 0; i < MIXD; i++) {
        float m = sm1[r2 * 33 + i];
        float4 w = *(const float4*)&swm2[i * MIXD + o0];
        m2[0] = fmaf(m, w.x, m2[0]);
        m2[1] = fmaf(m, w.y, m2[1]);
        m2[2] = fmaf(m, w.z, m2[2]);
        m2[3] = fmaf(m, w.w, m2[3]);
    }
    // block reduce over 32 rows: reuse sg area as [r][o] stride 33
    float* sred = sg;
    #pragma unroll
    for (int u = 0; u < 4; u++) sred[r2 * 33 + o0 + u] = fmaxf(m2[u], 0.f);
    __syncthreads();
    if (tid < MIXD) {
        float a = 0.f;
        for (int rr = 0; rr < 32; rr++) a += sred[rr * 33 + tid];
        g_part[((size_t)b * 128 + blockIdx.x) * MIXD + tid] = a;
    }
}

// ---------------- kF: final mean + w_out ----------------
__global__ void kF(const float* __restrict__ w_out, const float* __restrict__ b_out,
                   float* __restrict__ out) {
    int b = threadIdx.x;
    if (b < BB) {
        float s = 0.f;
        for (int o = 0; o < MIXD; o++) {
            float a = 0.f;
            for (int blk = 0; blk < 128; blk++) a += g_part[((size_t)b * 128 + blk) * MIXD + o];
            s = fmaf(a * (1.f / (float)TT), w_out[o], s);
        }
        out[b] = s + b_out[0];
    }
}

extern "C" void kernel_launch(void* const* d_in, const int* in_sizes, int n_in,
                              void* d_out, int out_size) {
    const float* x        = (const float*)d_in[0];
    const float* mic_pos  = (const float*)d_in[1];
    const float* w_in     = (const float*)d_in[2];
    const float* b_in     = (const float*)d_in[3];
    const float* w_mic    = (const float*)d_in[4];
    const float* b_mic    = (const float*)d_in[5];
    const float* w_inproj = (const float*)d_in[6];
    const float* conv_w   = (const float*)d_in[7];
    const float* conv_b   = (const float*)d_in[8];
    const float* dt_bias  = (const float*)d_in[9];
    const float* A_log    = (const float*)d_in[10];
    const float* D_skip   = (const float*)d_in[11];
    const float* norm_w   = (const float*)d_in[12];
    const float* w_outproj= (const float*)d_in[13];
    const float* w_mix1   = (const float*)d_in[14];
    const float* b_mix1   = (const float*)d_in[15];
    const float* w_mix2   = (const float*)d_in[16];
    const float* b_mix2   = (const float*)d_in[17];
    const float* w_out    = (const float*)d_in[18];
    const float* b_out    = (const float*)d_in[19];
    float* out = (float*)d_out;

    cudaFuncSetAttribute(kC, cudaFuncAttributeMaxDynamicSharedMemorySize, KC_SMEM_FLOATS * 4);
    cudaFuncSetAttribute(kD, cudaFuncAttributeMaxDynamicSharedMemorySize, KD_SMEM_FLOATS * 4);

    k0a<<<1, 256>>>(mic_pos, w_mic, b_mic, b_in, A_log);
    k0b<<<(4 * DPROJ + BB * DPROJ + DINNER * MIXD + 255) / 256, 256>>>(w_in, w_inproj, w_outproj, w_mix1);
    k1<<<dim3(32, 16), 128>>>(x, conv_w, conv_b, dt_bias);
    kA<<<dim3(NC, 128), 192>>>();
    kB<<<dim3(128, 2), 384>>>();
    kC<<<dim3(NC, BB), 256, KC_SMEM_FLOATS * 4>>>(D_skip);
    kD<<<dim3(128, 16), 256, KD_SMEM_FLOATS * 4>>>(x, norm_w, w_mix2, b_mix1, b_mix2);
    kF<<<1, 32>>>(w_out, b_out, out);
}

// round 5
// speedup vs baseline: 1.8420x; 1.1715x over previous
#include <cuda_runtime.h>
#include <math.h>
#include <stdint.h>

#define BB 16
#define TT 4096
#define DINNER 384
#define NH 8
#define HD 48
#define DS 64
#define DPROJ 904
#define NC 64
#define CS 64
#define MIXD 32

// ---------------- scratch (static device arrays; no runtime alloc) ----------
__device__ float g_W1[4 * DPROJ];            // w_in @ w_inproj
__device__ float g_mvec[BB * DPROJ];         // (b_in + relu(mic)) @ w_inproj
__device__ float g_W2[DINNER * MIXD];        // w_outproj @ w_mix1
__device__ float g_hb[BB * 192];
__device__ float g_A[NH];
__device__ float g_x[(size_t)BB * TT * DINNER];   // silu(conv) xs
__device__ float g_bc[(size_t)BB * TT * 128];     // B(64) | C(64)
__device__ float g_dt[(size_t)BB * TT * NH];
__device__ float g_la[(size_t)BB * TT * NH];      // log-decay = dt*A
__device__ float g_S[(size_t)128 * NC * HD * DS]; // chunk states -> h_in (in place)
__device__ float g_Dc[128 * NC];
__device__ float g_y[(size_t)BB * TT * DINNER];
__device__ float g_part[2048 * MIXD];

__device__ __forceinline__ float siluf(float v) { return __fdividef(v, 1.f + __expf(-v)); }
__device__ __forceinline__ float softplusf(float v) { return v > 20.f ? v : __logf(1.f + __expf(v)); }

__device__ __forceinline__ uint32_t tf32u(float x) {
    uint32_t r;
    asm("cvt.rna.tf32.f32 %0, %1;" : "=r"(r) : "f"(x));
    return r;
}
__device__ __forceinline__ float tf32f(float x) { return __uint_as_float(tf32u(x)); }

__device__ __forceinline__ void mma8(float d[4], const uint32_t a[4], const uint32_t b[2]) {
    asm volatile(
        "mma.sync.aligned.m16n8k8.row.col.f32.tf32.tf32.f32 "
        "{%0,%1,%2,%3},{%4,%5,%6,%7},{%8,%9},{%0,%1,%2,%3};\n"
        : "+f"(d[0]), "+f"(d[1]), "+f"(d[2]), "+f"(d[3])
        : "r"(a[0]), "r"(a[1]), "r"(a[2]), "r"(a[3]),
          "r"(b[0]), "r"(b[1]));
}

// ---------------- k0a: mic MLP + A ----------------
__global__ void k0a(const float* __restrict__ mic_pos, const float* __restrict__ w_mic,
                    const float* __restrict__ b_mic, const float* __restrict__ b_in,
                    const float* __restrict__ A_log) {
    int tid = threadIdx.x;
    for (int i = tid; i < BB * 192; i += 256) {
        int b = i / 192, d = i % 192;
        float s = b_mic[d];
        #pragma unroll
        for (int j = 0; j < 12; j++) s = fmaf(mic_pos[b * 12 + j], w_mic[j * 192 + d], s);
        g_hb[i] = b_in[d] + fmaxf(s, 0.f);
    }
    if (tid < NH) g_A[tid] = -expf(A_log[tid]);
}

// ---------------- k0b: folded weights ----------------
__global__ void k0b(const float* __restrict__ w_in, const float* __restrict__ w_inproj,
                    const float* __restrict__ w_outproj, const float* __restrict__ w_mix1) {
    int i = blockIdx.x * 256 + threadIdx.x;
    if (i < 4 * DPROJ) {
        int j = i / DPROJ, d = i % DPROJ;
        float s = 0.f;
        for (int m = 0; m < 192; m++) s = fmaf(w_in[j * 192 + m], w_inproj[m * DPROJ + d], s);
        g_W1[i] = s;
    } else if (i < 4 * DPROJ + BB * DPROJ) {
        int ii = i - 4 * DPROJ;
        int b = ii / DPROJ, d = ii % DPROJ;
        float s = 0.f;
        for (int m = 0; m < 192; m++) s = fmaf(g_hb[b * 192 + m], w_inproj[m * DPROJ + d], s);
        g_mvec[ii] = s;
    } else if (i < 4 * DPROJ + BB * DPROJ + DINNER * MIXD) {
        int ii = i - (4 * DPROJ + BB * DPROJ);
        int d = ii / MIXD, o = ii % MIXD;
        float s = 0.f;
        for (int m = 0; m < 192; m++) s = fmaf(w_outproj[d * 192 + m], w_mix1[m * MIXD + o], s);
        g_W2[ii] = s;
    }
}

// ---------------- k1: fused inproj + conv4 + silu + dt/la ----------------
// grid (32, 16) block 128 : thread = one t
__global__ void k1(const float* __restrict__ x, const float* __restrict__ conv_w,
                   const float* __restrict__ conv_b, const float* __restrict__ dt_bias) {
    __shared__ float sW1[4 * 520];   // proj dims 384..903
    __shared__ float smv[520];
    __shared__ float scw[512 * 4];
    __shared__ float scb[512];
    __shared__ float sx4[131 * 4];
    __shared__ float sraw[131 * 33];

    int tid = threadIdx.x;
    int b = blockIdx.y;
    int t0 = blockIdx.x * 128;

    for (int i = tid; i < 4 * 520; i += 128) sW1[i] = g_W1[(i / 520) * DPROJ + 384 + (i % 520)];
    for (int i = tid; i < 520; i += 128) smv[i] = g_mvec[b * DPROJ + 384 + i];
    for (int i = tid; i < 512 * 4; i += 128) scw[i] = conv_w[i];
    for (int i = tid; i < 512; i += 128) scb[i] = conv_b[i];
    for (int i = tid; i < 131 * 4; i += 128) {
        int r = i >> 2, j = i & 3;
        int t = t0 + r - 3;
        sx4[i] = (t >= 0) ? x[((size_t)b * TT + t) * 4 + j] : 0.f;
    }

    int t = t0 + tid;
    for (int c16 = 0; c16 < 16; c16++) {
        __syncthreads();
        for (int i = tid; i < 131 * 32; i += 128) {
            int r = i >> 5, dc = i & 31;
            int dd = c16 * 32 + dc;
            float v = 0.f;
            if (t0 + r - 3 >= 0) {
                v = smv[dd];
                #pragma unroll
                for (int j = 0; j < 4; j++) v = fmaf(sx4[r * 4 + j], sW1[j * 520 + dd], v);
            }
            sraw[r * 33 + dc] = v;
        }
        __syncthreads();
        float v[32];
        #pragma unroll
        for (int dc = 0; dc < 32; dc++) {
            int dd = c16 * 32 + dc;
            float a = scb[dd];
            #pragma unroll
            for (int k = 0; k < 4; k++) a = fmaf(sraw[(tid + k) * 33 + dc], scw[dd * 4 + k], a);
            v[dc] = siluf(a);
        }
        float* dst;
        if (c16 < 12) dst = g_x + ((size_t)b * TT + t) * DINNER + c16 * 32;
        else          dst = g_bc + ((size_t)b * TT + t) * 128 + (c16 - 12) * 32;
        #pragma unroll
        for (int q = 0; q < 8; q++)
            ((float4*)dst)[q] = make_float4(v[4 * q], v[4 * q + 1], v[4 * q + 2], v[4 * q + 3]);
    }

    // dt path (proj dims 896..903 via sW1 dims 512..519)
    #pragma unroll
    for (int hh = 0; hh < NH; hh++) {
        int dd = 512 + hh;
        float v = smv[dd];
        #pragma unroll
        for (int j = 0; j < 4; j++) v = fmaf(sx4[(tid + 3) * 4 + j], sW1[j * 520 + dd], v);
        float dt = softplusf(v + dt_bias[hh]);
        size_t o = ((size_t)b * TT + t) * NH + hh;
        g_dt[o] = dt;
        g_la[o] = dt * g_A[hh];
    }
}

// ---------------- kA: chunk-local end states as GEMM (fp32) ----------------
// grid (NC, 128) block 192 : thread = (ip, in) 12x16, 4x4 tile of S[48][64]
__global__ void kA() {
    __shared__ float sxw[CS * HD];   // [t][p] = w(t)*x(t,p)
    __shared__ float sB[CS * DS];    // [t][n]
    __shared__ float scs[CS];
    __shared__ float sdt[CS];

    int c = blockIdx.x, bh = blockIdx.y;
    int b = bh >> 3, h = bh & 7;
    int tid = threadIdx.x;
    int t0 = c * CS;

    if (tid < CS) {
        size_t o = ((size_t)b * TT + t0 + tid) * NH + h;
        scs[tid] = g_la[o];
        sdt[tid] = g_dt[o];
    }
    __syncthreads();
    for (int off = 1; off < CS; off <<= 1) {
        float v = 0.f;
        if (tid < CS && tid >= off) v = scs[tid - off];
        __syncthreads();
        if (tid < CS) scs[tid] += v;
        __syncthreads();
    }

    const float* bp = g_bc + ((size_t)b * TT + t0) * 128;
    for (int i = tid; i < CS * 16; i += 192) {
        int r = i / 16, col = i % 16;
        ((float4*)sB)[r * 16 + col] = ((const float4*)(bp + (size_t)r * 128))[col];
    }
    float cstot = scs[CS - 1];
    const float* xp = g_x + ((size_t)b * TT + t0) * DINNER + h * HD;
    for (int i = tid; i < CS * 12; i += 192) {
        int r = i / 12, col = i % 12;
        float w = __expf(cstot - scs[r]) * sdt[r];
        float4 v = ((const float4*)(xp + (size_t)r * DINNER))[col];
        v.x *= w; v.y *= w; v.z *= w; v.w *= w;
        ((float4*)sxw)[r * 12 + col] = v;
    }
    __syncthreads();

    int in = tid & 15, ip = tid >> 4;
    int n0 = in * 4, p0 = ip * 4;
    float acc[4][4];
    #pragma unroll
    for (int i = 0; i < 4; i++)
        #pragma unroll
        for (int j = 0; j < 4; j++) acc[i][j] = 0.f;

    #pragma unroll 4
    for (int t = 0; t < CS; t++) {
        float4 xw = *(const float4*)&sxw[t * HD + p0];
        float4 bb = *(const float4*)&sB[t * DS + n0];
        float xr[4] = {xw.x, xw.y, xw.z, xw.w};
        float br[4] = {bb.x, bb.y, bb.z, bb.w};
        #pragma unroll
        for (int i = 0; i < 4; i++)
            #pragma unroll
            for (int j = 0; j < 4; j++) acc[i][j] = fmaf(xr[i], br[j], acc[i][j]);
    }

    float* sp = g_S + ((size_t)bh * NC + c) * (HD * DS);
    #pragma unroll
    for (int i = 0; i < 4; i++)
        *(float4*)&sp[(p0 + i) * DS + n0] = make_float4(acc[i][0], acc[i][1], acc[i][2], acc[i][3]);
    if (tid == 0) g_Dc[bh * NC + c] = __expf(cstot);
}

// ---------------- kB: inter-chunk scan ----------------
// grid (128, 2) block 384 : thread owns 4 contiguous states
__global__ void kB() {
    int bh = blockIdx.x, half = blockIdx.y;
    int tid = threadIdx.x;
    float h4[4] = {0.f, 0.f, 0.f, 0.f};
    size_t base = (size_t)bh * NC * (HD * DS) + (size_t)half * 1536 + tid * 4;
    for (int c = 0; c < NC; c++) {
        float* sp = g_S + base + (size_t)c * (HD * DS);
        float4 a = *(float4*)sp;
        *(float4*)sp = make_float4(h4[0], h4[1], h4[2], h4[3]);
        float Dc = g_Dc[bh * NC + c];
        h4[0] = fmaf(h4[0], Dc, a.x); h4[1] = fmaf(h4[1], Dc, a.y);
        h4[2] = fmaf(h4[2], Dc, a.z); h4[3] = fmaf(h4[3], Dc, a.w);
    }
}

// ---------------- kC: chunked SSD via tf32 tensor-core mma ----------------
// grid (NC, BB) block 256 (8 warps)
// smem floats (stride 72 for 64-wide, 56 for 48-wide):
#define ST64 72
#define ST48 56
#define KC_BT   0                       // [n][s] tf32, 64*72
#define KC_CT   (KC_BT + 64 * ST64)     // [n][t] tf32
#define KC_G    (KC_CT + 64 * ST64)     // [t][s] tf32 (per head)
#define KC_SX   (KC_G + 64 * ST64)      // [s][p] fp32, 64*56
#define KC_SHIN (KC_SX + 64 * ST48)     // [n][p] tf32, 64*56
#define KC_SCS  (KC_SHIN + 64 * ST48)   // 8*64
#define KC_SDT  (KC_SCS + 512)          // 8*64
#define KC_SMEM_FLOATS (KC_SDT + 512)

__global__ __launch_bounds__(256) void kC(const float* __restrict__ D_skip) {
    extern __shared__ float sm[];
    float* sBt  = sm + KC_BT;
    float* sCt  = sm + KC_CT;
    float* sG   = sm + KC_G;
    float* sx   = sm + KC_SX;
    float* shin = sm + KC_SHIN;
    float* sCS  = sm + KC_SCS;
    float* sDT  = sm + KC_SDT;

    int c = blockIdx.x, b = blockIdx.y;
    int tid = threadIdx.x;
    int wid = tid >> 5, lane = tid & 31;
    int lq = lane & 3, lh = lane >> 2;
    int t0c = c * CS;

    // la/dt for all heads, transpose to [h][t]
    if (tid < 128) {
        const float* lap = g_la + ((size_t)b * TT + t0c) * NH;
        const float* dtp = g_dt + ((size_t)b * TT + t0c) * NH;
        float4 v = ((const float4*)lap)[tid];
        float4 w = ((const float4*)dtp)[tid];
        int j0 = tid * 4;
        #pragma unroll
        for (int u = 0; u < 4; u++) {
            int j = j0 + u;
            int t = j >> 3, h = j & 7;
            sCS[h * 64 + t] = (&v.x)[u];
            sDT[h * 64 + t] = (&w.x)[u];
        }
    }

    // B,C transposed + tf32 conversion
    const float* bp = g_bc + ((size_t)b * TT + t0c) * 128;
    for (int i = tid; i < CS * 16; i += 256) {
        int s = i >> 4, nq = i & 15;
        float4 v = ((const float4*)(bp + (size_t)s * 128))[nq];          // B[s][n]
        sBt[(nq * 4 + 0) * ST64 + s] = tf32f(v.x);
        sBt[(nq * 4 + 1) * ST64 + s] = tf32f(v.y);
        sBt[(nq * 4 + 2) * ST64 + s] = tf32f(v.z);
        sBt[(nq * 4 + 3) * ST64 + s] = tf32f(v.w);
        float4 w = ((const float4*)(bp + (size_t)s * 128))[nq + 16];     // C[s][n]
        sCt[(nq * 4 + 0) * ST64 + s] = tf32f(w.x);
        sCt[(nq * 4 + 1) * ST64 + s] = tf32f(w.y);
        sCt[(nq * 4 + 2) * ST64 + s] = tf32f(w.z);
        sCt[(nq * 4 + 3) * ST64 + s] = tf32f(w.w);
    }
    __syncthreads();

    // per-head inclusive log-decay prefix (warp w = head w)
    {
        float a0 = sCS[wid * 64 + 2 * lane];
        float a1 = sCS[wid * 64 + 2 * lane + 1];
        float ps = a0 + a1;
        #pragma unroll
        for (int off = 1; off < 32; off <<= 1) {
            float v = __shfl_up_sync(0xffffffffu, ps, off);
            if (lane >= off) ps += v;
        }
        sCS[wid * 64 + 2 * lane + 1] = ps;
        sCS[wid * 64 + 2 * lane]     = ps - a1;
    }

    // GEMM1 (shared across heads): Graw[t][s] = sum_n C[t][n]*B[s][n]
    // warp w: t-strip (w&3)*16, s-half (w>>2)*32 (4 n8-tiles)
    int t0 = (wid & 3) * 16;
    int sb = (wid >> 2) * 32;
    float g1[4][4];
    #pragma unroll
    for (int j = 0; j < 4; j++)
        #pragma unroll
        for (int e = 0; e < 4; e++) g1[j][e] = 0.f;

    #pragma unroll
    for (int k = 0; k < DS; k += 8) {
        uint32_t a[4];
        a[0] = __float_as_uint(sCt[(k + lq) * ST64 + t0 + lh]);
        a[1] = __float_as_uint(sCt[(k + lq) * ST64 + t0 + lh + 8]);
        a[2] = __float_as_uint(sCt[(k + 4 + lq) * ST64 + t0 + lh]);
        a[3] = __float_as_uint(sCt[(k + 4 + lq) * ST64 + t0 + lh + 8]);
        #pragma unroll
        for (int j = 0; j < 4; j++) {
            uint32_t bfr[2];
            bfr[0] = __float_as_uint(sBt[(k + lq) * ST64 + sb + 8 * j + lh]);
            bfr[1] = __float_as_uint(sBt[(k + 4 + lq) * ST64 + sb + 8 * j + lh]);
            mma8(g1[j], a, bfr);
        }
    }

    // GEMM2/3 warp tiling: t-strip (w&3)*16, p-half (w>>2)*24 (3 n8-tiles)
    int pb = (wid >> 2) * 24;

    for (int h = 0; h < NH; h++) {
        __syncthreads();   // prior head's reads of sG/sx/shin done; scan visible on h=0

        // load x (fp32) and h_in (tf32) for this head
        const float* xp = g_x + ((size_t)b * TT + t0c) * DINNER + h * HD;
        for (int i = tid; i < CS * 12; i += 256) {
            int s = i / 12, col = i % 12;
            float4 v = ((const float4*)(xp + (size_t)s * DINNER))[col];
            *(float4*)&sx[s * ST48 + col * 4] = v;
        }
        const float* hp = g_S + ((size_t)(b * NH + h) * NC + c) * (HD * DS);
        for (int i = tid; i < HD * 16; i += 256) {
            int p = i >> 4, nq = i & 15;
            float4 v = ((const float4*)(hp + p * DS))[nq];
            shin[(nq * 4 + 0) * ST48 + p] = tf32f(v.x);
            shin[(nq * 4 + 1) * ST48 + p] = tf32f(v.y);
            shin[(nq * 4 + 2) * ST48 + p] = tf32f(v.z);
            shin[(nq * 4 + 3) * ST48 + p] = tf32f(v.w);
        }

        // apply per-head mask to Graw fragments, store tf32 G[t][s]
        const float* csh = sCS + h * 64;
        const float* dth = sDT + h * 64;
        {
            float cs_r0 = csh[t0 + lh], cs_r1 = csh[t0 + lh + 8];
            #pragma unroll
            for (int j = 0; j < 4; j++) {
                int c0 = sb + 8 * j + 2 * lq;
                float cs_c0 = csh[c0], cs_c1 = csh[c0 + 1];
                float dt_c0 = dth[c0], dt_c1 = dth[c0 + 1];
                int r0 = t0 + lh, r1 = r0 + 8;
                float m00 = (c0 <= r0) ? __expf(cs_r0 - cs_c0) * dt_c0 : 0.f;
                float m01 = (c0 + 1 <= r0) ? __expf(cs_r0 - cs_c1) * dt_c1 : 0.f;
                float m10 = (c0 <= r1) ? __expf(cs_r1 - cs_c0) * dt_c0 : 0.f;
                float m11 = (c0 + 1 <= r1) ? __expf(cs_r1 - cs_c1) * dt_c1 : 0.f;
                sG[r0 * ST64 + c0]     = tf32f(g1[j][0] * m00);
                sG[r0 * ST64 + c0 + 1] = tf32f(g1[j][1] * m01);
                sG[r1 * ST64 + c0]     = tf32f(g1[j][2] * m10);
                sG[r1 * ST64 + c0 + 1] = tf32f(g1[j][3] * m11);
            }
        }
        __syncthreads();

        // GEMM2: Yintra[t][p] = sum_s G[t][s]*x[s][p]
        // GEMM3: Yinter[t][p] = sum_n C[t][n]*hin[n][p]
        float accA[3][4], accB[3][4];
        #pragma unroll
        for (int j = 0; j < 3; j++)
            #pragma unroll
            for (int e = 0; e < 4; e++) { accA[j][e] = 0.f; accB[j][e] = 0.f; }

        #pragma unroll
        for (int k = 0; k < CS; k += 8) {
            uint32_t a[4];
            a[0] = __float_as_uint(sG[(t0 + lh) * ST64 + k + lq]);
            a[1] = __float_as_uint(sG[(t0 + lh + 8) * ST64 + k + lq]);
            a[2] = __float_as_uint(sG[(t0 + lh) * ST64 + k + 4 + lq]);
            a[3] = __float_as_uint(sG[(t0 + lh + 8) * ST64 + k + 4 + lq]);
            #pragma unroll
            for (int j = 0; j < 3; j++) {
                uint32_t bfr[2];
                bfr[0] = tf32u(sx[(k + lq) * ST48 + pb + 8 * j + lh]);
                bfr[1] = tf32u(sx[(k + 4 + lq) * ST48 + pb + 8 * j + lh]);
                mma8(accA[j], a, bfr);
            }
        }
        #pragma unroll
        for (int k = 0; k < DS; k += 8) {
            uint32_t a[4];
            a[0] = __float_as_uint(sCt[(k + lq) * ST64 + t0 + lh]);
            a[1] = __float_as_uint(sCt[(k + lq) * ST64 + t0 + lh + 8]);
            a[2] = __float_as_uint(sCt[(k + 4 + lq) * ST64 + t0 + lh]);
            a[3] = __float_as_uint(sCt[(k + 4 + lq) * ST64 + t0 + lh + 8]);
            #pragma unroll
            for (int j = 0; j < 3; j++) {
                uint32_t bfr[2];
                bfr[0] = __float_as_uint(shin[(k + lq) * ST48 + pb + 8 * j + lh]);
                bfr[1] = __float_as_uint(shin[(k + 4 + lq) * ST48 + pb + 8 * j + lh]);
                mma8(accB[j], a, bfr);
            }
        }

        // epilogue: y = intra + exp(cs[t])*inter + D*x
        float dskip = D_skip[h];
        float et0 = __expf(csh[t0 + lh]);
        float et1 = __expf(csh[t0 + lh + 8]);
        float* yp = g_y + ((size_t)b * TT + t0c) * DINNER + h * HD;
        #pragma unroll
        for (int j = 0; j < 3; j++) {
            int p0 = pb + 8 * j + 2 * lq;
            int r0 = t0 + lh, r1 = r0 + 8;
            yp[(size_t)r0 * DINNER + p0]     = accA[j][0] + et0 * accB[j][0] + dskip * sx[r0 * ST48 + p0];
            yp[(size_t)r0 * DINNER + p0 + 1] = accA[j][1] + et0 * accB[j][1] + dskip * sx[r0 * ST48 + p0 + 1];
            yp[(size_t)r1 * DINNER + p0]     = accA[j][2] + et1 * accB[j][2] + dskip * sx[r1 * ST48 + p0];
            yp[(size_t)r1 * DINNER + p0 + 1] = accA[j][3] + et1 * accB[j][3] + dskip * sx[r1 * ST48 + p0 + 1];
        }
    }
}

// ---------------- kD: gating + RMSNorm + GEMM(W2) + mix2 + partial ------
// grid (128, 16) block 256, 32 rows/block, dynamic smem
#define KD_SG 0            // 32*388
#define KD_SWM2 12416      // 1024
#define KD_SW1Z 13440      // 1536
#define KD_SMV 14976       // 384
#define KD_SNW 15360       // 384
#define KD_SM1 15744       // 32*33
#define KD_SRSTD 16800     // 32
#define KD_SMEM_FLOATS 16832

__global__ __launch_bounds__(256) void kD(const float* __restrict__ x, const float* __restrict__ norm_w,
                   const float* __restrict__ w_mix2, const float* __restrict__ b_mix1,
                   const float* __restrict__ b_mix2) {
    extern __shared__ float sm[];
    float* sg   = sm + KD_SG;     // [r][dd] stride 388
    float* swm2 = sm + KD_SWM2;
    float* sW1z = sm + KD_SW1Z;
    float* smv  = sm + KD_SMV;
    float* snw  = sm + KD_SNW;
    float* sm1  = sm + KD_SM1;    // [r][o] stride 33
    float* srstd= sm + KD_SRSTD;

    int tid = threadIdx.x;
    int b = blockIdx.y;
    int t0 = blockIdx.x * 32;

    for (int i = tid; i < DINNER; i += 256) { smv[i] = g_mvec[b * DPROJ + i]; snw[i] = norm_w[i]; }
    for (int i = tid; i < 4 * DINNER; i += 256) sW1z[i] = g_W1[(i / DINNER) * DPROJ + (i % DINNER)];
    for (int i = tid; i < MIXD * MIXD; i += 256) swm2[i] = w_mix2[i];
    __syncthreads();

    int r = tid >> 3, seg = tid & 7;
    int dd0 = seg * 48;
    const float* xr = x + ((size_t)b * TT + t0 + r) * 4;
    float x0 = xr[0], x1 = xr[1], x2 = xr[2], x3 = xr[3];
    const float* yr = g_y + ((size_t)b * TT + t0 + r) * DINNER + dd0;
    float ss = 0.f;
    #pragma unroll
    for (int q = 0; q < 12; q++) {
        float4 y4 = ((const float4*)yr)[q];
        float gv[4] = {y4.x, y4.y, y4.z, y4.w};
        #pragma unroll
        for (int u = 0; u < 4; u++) {
            int dd = dd0 + q * 4 + u;
            float z = smv[dd];
            z = fmaf(x0, sW1z[dd], z);
            z = fmaf(x1, sW1z[DINNER + dd], z);
            z = fmaf(x2, sW1z[2 * DINNER + dd], z);
            z = fmaf(x3, sW1z[3 * DINNER + dd], z);
            float g = gv[u] * siluf(z);
            gv[u] = g;
            ss = fmaf(g, g, ss);
        }
        *(float4*)&sg[r * 388 + dd0 + q * 4] = make_float4(gv[0], gv[1], gv[2], gv[3]);
    }
    ss += __shfl_xor_sync(0xffffffffu, ss, 1);
    ss += __shfl_xor_sync(0xffffffffu, ss, 2);
    ss += __shfl_xor_sync(0xffffffffu, ss, 4);
    if (seg == 0) srstd[r] = rsqrtf(ss * (1.f / DINNER) + 1e-5f);
    __syncthreads();

    {
        float rs = srstd[r];
        #pragma unroll
        for (int q = 0; q < 48; q++) {
            int dd = dd0 + q;
            sg[r * 388 + dd] *= rs * snw[dd];
        }
    }
    __syncthreads();

    int io4 = tid & 7, r2 = tid >> 3;
    int o0 = io4 * 4;
    float acc[4] = {0.f, 0.f, 0.f, 0.f};
    const float* gr = sg + r2 * 388;
    #pragma unroll 8
    for (int dd = 0; dd < DINNER; dd++) {
        float g = gr[dd];
        float4 w = __ldg((const float4*)&g_W2[dd * MIXD + o0]);
        acc[0] = fmaf(g, w.x, acc[0]);
        acc[1] = fmaf(g, w.y, acc[1]);
        acc[2] = fmaf(g, w.z, acc[2]);
        acc[3] = fmaf(g, w.w, acc[3]);
    }
    #pragma unroll
    for (int u = 0; u < 4; u++) sm1[r2 * 33 + o0 + u] = fmaxf(acc[u] + b_mix1[o0 + u], 0.f);
    __syncthreads();

    float m2[4] = {b_mix2[o0], b_mix2[o0 + 1], b_mix2[o0 + 2], b_mix2[o0 + 3]};
    #pragma unroll
    for (int i = 0; i < MIXD; i++) {
        float m = sm1[r2 * 33 + i];
        float4 w = *(const float4*)&swm2[i * MIXD + o0];
        m2[0] = fmaf(m, w.x, m2[0]);
        m2[1] = fmaf(m, w.y, m2[1]);
        m2[2] = fmaf(m, w.z, m2[2]);
        m2[3] = fmaf(m, w.w, m2[3]);
    }
    float* sred = sg;
    #pragma unroll
    for (int u = 0; u < 4; u++) sred[r2 * 33 + o0 + u] = fmaxf(m2[u], 0.f);
    __syncthreads();
    if (tid < MIXD) {
        float a = 0.f;
        for (int rr = 0; rr < 32; rr++) a += sred[rr * 33 + tid];
        g_part[((size_t)b * 128 + blockIdx.x) * MIXD + tid] = a;
    }
}

// ---------------- kF: final mean + w_out ----------------
__global__ void kF(const float* __restrict__ w_out, const float* __restrict__ b_out,
                   float* __restrict__ out) {
    int b = threadIdx.x;
    if (b < BB) {
        float s = 0.f;
        for (int o = 0; o < MIXD; o++) {
            float a = 0.f;
            for (int blk = 0; blk < 128; blk++) a += g_part[((size_t)b * 128 + blk) * MIXD + o];
            s = fmaf(a * (1.f / (float)TT), w_out[o], s);
        }
        out[b] = s + b_out[0];
    }
}

extern "C" void kernel_launch(void* const* d_in, const int* in_sizes, int n_in,
                              void* d_out, int out_size) {
    const float* x        = (const float*)d_in[0];
    const float* mic_pos  = (const float*)d_in[1];
    const float* w_in     = (const float*)d_in[2];
    const float* b_in     = (const float*)d_in[3];
    const float* w_mic    = (const float*)d_in[4];
    const float* b_mic    = (const float*)d_in[5];
    const float* w_inproj = (const float*)d_in[6];
    const float* conv_w   = (const float*)d_in[7];
    const float* conv_b   = (const float*)d_in[8];
    const float* dt_bias  = (const float*)d_in[9];
    const float* A_log    = (const float*)d_in[10];
    const float* D_skip   = (const float*)d_in[11];
    const float* norm_w   = (const float*)d_in[12];
    const float* w_outproj= (const float*)d_in[13];
    const float* w_mix1   = (const float*)d_in[14];
    const float* b_mix1   = (const float*)d_in[15];
    const float* w_mix2   = (const float*)d_in[16];
    const float* b_mix2   = (const float*)d_in[17];
    const float* w_out    = (const float*)d_in[18];
    const float* b_out    = (const float*)d_in[19];
    float* out = (float*)d_out;

    cudaFuncSetAttribute(kC, cudaFuncAttributeMaxDynamicSharedMemorySize, KC_SMEM_FLOATS * 4);
    cudaFuncSetAttribute(kD, cudaFuncAttributeMaxDynamicSharedMemorySize, KD_SMEM_FLOATS * 4);

    k0a<<<1, 256>>>(mic_pos, w_mic, b_mic, b_in, A_log);
    k0b<<<(4 * DPROJ + BB * DPROJ + DINNER * MIXD + 255) / 256, 256>>>(w_in, w_inproj, w_outproj, w_mix1);
    k1<<<dim3(32, 16), 128>>>(x, conv_w, conv_b, dt_bias);
    kA<<<dim3(NC, 128), 192>>>();
    kB<<<dim3(128, 2), 384>>>();
    kC<<<dim3(NC, BB), 256, KC_SMEM_FLOATS * 4>>>(D_skip);
    kD<<<dim3(128, 16), 256, KD_SMEM_FLOATS * 4>>>(x, norm_w, w_mix2, b_mix1, b_mix2);
    kF<<<1, 32>>>(w_out, b_out, out);
}

// round 6
// speedup vs baseline: 2.3985x; 1.3022x over previous
#include <cuda_runtime.h>
#include <math.h>
#include <stdint.h>

#define BB 16
#define TT 4096
#define DINNER 384
#define NH 8
#define HD 48
#define DS 64
#define DPROJ 904
#define NC 64
#define CS 64
#define MIXD 32

// ---------------- scratch (static device arrays; no runtime alloc) ----------
__device__ float g_W1[4 * DPROJ];            // w_in @ w_inproj
__device__ float g_mvec[BB * DPROJ];         // (b_in + relu(mic)) @ w_inproj
__device__ float g_W2[DINNER * MIXD];        // norm_w * (w_outproj @ w_mix1)
__device__ float g_hb[BB * 192];
__device__ float g_A[NH];
__device__ float g_x[(size_t)BB * TT * DINNER];   // silu(conv) xs
__device__ float g_bc[(size_t)BB * TT * 128];     // B(64) | C(64)
__device__ float g_dt[(size_t)BB * TT * NH];
__device__ float g_la[(size_t)BB * TT * NH];      // log-decay = dt*A
__device__ float g_S[(size_t)128 * NC * HD * DS]; // chunk states -> h_in (in place)
__device__ float g_Dc[128 * NC];
__device__ float g_y[(size_t)BB * TT * DINNER];
__device__ float g_part[2048 * MIXD];

__device__ __forceinline__ float siluf(float v) { return __fdividef(v, 1.f + __expf(-v)); }
__device__ __forceinline__ float softplusf(float v) { return v > 20.f ? v : __logf(1.f + __expf(v)); }

__device__ __forceinline__ uint32_t tf32u(float x) {
    uint32_t r;
    asm("cvt.rna.tf32.f32 %0, %1;" : "=r"(r) : "f"(x));
    return r;
}
__device__ __forceinline__ float tf32f(float x) { return __uint_as_float(tf32u(x)); }

__device__ __forceinline__ void mma8(float d[4], const uint32_t a[4], const uint32_t b[2]) {
    asm volatile(
        "mma.sync.aligned.m16n8k8.row.col.f32.tf32.tf32.f32 "
        "{%0,%1,%2,%3},{%4,%5,%6,%7},{%8,%9},{%0,%1,%2,%3};\n"
        : "+f"(d[0]), "+f"(d[1]), "+f"(d[2]), "+f"(d[3])
        : "r"(a[0]), "r"(a[1]), "r"(a[2]), "r"(a[3]),
          "r"(b[0]), "r"(b[1]));
}

// ---------------- k0a: mic MLP + A ----------------
__global__ void k0a(const float* __restrict__ mic_pos, const float* __restrict__ w_mic,
                    const float* __restrict__ b_mic, const float* __restrict__ b_in,
                    const float* __restrict__ A_log) {
    int tid = threadIdx.x;
    for (int i = tid; i < BB * 192; i += 256) {
        int b = i / 192, d = i % 192;
        float s = b_mic[d];
        #pragma unroll
        for (int j = 0; j < 12; j++) s = fmaf(mic_pos[b * 12 + j], w_mic[j * 192 + d], s);
        g_hb[i] = b_in[d] + fmaxf(s, 0.f);
    }
    if (tid < NH) g_A[tid] = -expf(A_log[tid]);
}

// ---------------- k0b: folded weights (norm_w folded into W2) ----------------
__global__ void k0b(const float* __restrict__ w_in, const float* __restrict__ w_inproj,
                    const float* __restrict__ w_outproj, const float* __restrict__ w_mix1,
                    const float* __restrict__ norm_w) {
    int i = blockIdx.x * 256 + threadIdx.x;
    if (i < 4 * DPROJ) {
        int j = i / DPROJ, d = i % DPROJ;
        float s = 0.f;
        for (int m = 0; m < 192; m++) s = fmaf(w_in[j * 192 + m], w_inproj[m * DPROJ + d], s);
        g_W1[i] = s;
    } else if (i < 4 * DPROJ + BB * DPROJ) {
        int ii = i - 4 * DPROJ;
        int b = ii / DPROJ, d = ii % DPROJ;
        float s = 0.f;
        for (int m = 0; m < 192; m++) s = fmaf(g_hb[b * 192 + m], w_inproj[m * DPROJ + d], s);
        g_mvec[ii] = s;
    } else if (i < 4 * DPROJ + BB * DPROJ + DINNER * MIXD) {
        int ii = i - (4 * DPROJ + BB * DPROJ);
        int d = ii / MIXD, o = ii % MIXD;
        float s = 0.f;
        for (int m = 0; m < 192; m++) s = fmaf(w_outproj[d * 192 + m], w_mix1[m * MIXD + o], s);
        g_W2[ii] = s * norm_w[d];
    }
}

// ---------------- k1: fused inproj + conv4 + silu + dt/la ----------------
// grid (32, 16) block 128 : thread = one t
__global__ void k1(const float* __restrict__ x, const float* __restrict__ conv_w,
                   const float* __restrict__ conv_b, const float* __restrict__ dt_bias) {
    __shared__ float sW1[4 * 520];   // proj dims 384..903
    __shared__ float smv[520];
    __shared__ float scw[512 * 4];
    __shared__ float scb[512];
    __shared__ float sx4[131 * 4];
    __shared__ float sraw[131 * 33];

    int tid = threadIdx.x;
    int b = blockIdx.y;
    int t0 = blockIdx.x * 128;

    for (int i = tid; i < 4 * 520; i += 128) sW1[i] = g_W1[(i / 520) * DPROJ + 384 + (i % 520)];
    for (int i = tid; i < 520; i += 128) smv[i] = g_mvec[b * DPROJ + 384 + i];
    for (int i = tid; i < 512 * 4; i += 128) scw[i] = conv_w[i];
    for (int i = tid; i < 512; i += 128) scb[i] = conv_b[i];
    for (int i = tid; i < 131 * 4; i += 128) {
        int r = i >> 2, j = i & 3;
        int t = t0 + r - 3;
        sx4[i] = (t >= 0) ? x[((size_t)b * TT + t) * 4 + j] : 0.f;
    }

    int t = t0 + tid;
    for (int c16 = 0; c16 < 16; c16++) {
        __syncthreads();
        for (int i = tid; i < 131 * 32; i += 128) {
            int r = i >> 5, dc = i & 31;
            int dd = c16 * 32 + dc;
            float v = 0.f;
            if (t0 + r - 3 >= 0) {
                v = smv[dd];
                #pragma unroll
                for (int j = 0; j < 4; j++) v = fmaf(sx4[r * 4 + j], sW1[j * 520 + dd], v);
            }
            sraw[r * 33 + dc] = v;
        }
        __syncthreads();
        float v[32];
        #pragma unroll
        for (int dc = 0; dc < 32; dc++) {
            int dd = c16 * 32 + dc;
            float a = scb[dd];
            #pragma unroll
            for (int k = 0; k < 4; k++) a = fmaf(sraw[(tid + k) * 33 + dc], scw[dd * 4 + k], a);
            v[dc] = siluf(a);
        }
        float* dst;
        if (c16 < 12) dst = g_x + ((size_t)b * TT + t) * DINNER + c16 * 32;
        else          dst = g_bc + ((size_t)b * TT + t) * 128 + (c16 - 12) * 32;
        #pragma unroll
        for (int q = 0; q < 8; q++)
            ((float4*)dst)[q] = make_float4(v[4 * q], v[4 * q + 1], v[4 * q + 2], v[4 * q + 3]);
    }

    // dt path (proj dims 896..903 via sW1 dims 512..519)
    #pragma unroll
    for (int hh = 0; hh < NH; hh++) {
        int dd = 512 + hh;
        float v = smv[dd];
        #pragma unroll
        for (int j = 0; j < 4; j++) v = fmaf(sx4[(tid + 3) * 4 + j], sW1[j * 520 + dd], v);
        float dt = softplusf(v + dt_bias[hh]);
        size_t o = ((size_t)b * TT + t) * NH + hh;
        g_dt[o] = dt;
        g_la[o] = dt * g_A[hh];
    }
}

// ---------------- kA: chunk-local end states via tf32 mma ----------------
// grid (NC, 128) block 192 (6 warps): warp = (p-strip w%3, n-half w/3)
__global__ __launch_bounds__(192) void kA() {
    __shared__ float sxw[CS * 56];   // [t][p] = w(t)*x(t,p), tf32
    __shared__ float sB[CS * 72];    // [t][n], tf32
    __shared__ float scs[CS];
    __shared__ float sdt[CS];

    int c = blockIdx.x, bh = blockIdx.y;
    int b = bh >> 3, h = bh & 7;
    int tid = threadIdx.x;
    int wid = tid >> 5, lane = tid & 31;
    int lq = lane & 3, lh = lane >> 2;
    int t0 = c * CS;

    if (tid < CS) {
        size_t o = ((size_t)b * TT + t0 + tid) * NH + h;
        scs[tid] = g_la[o];
        sdt[tid] = g_dt[o];
    }
    const float* bp = g_bc + ((size_t)b * TT + t0) * 128;
    for (int i = tid; i < CS * 16; i += 192) {
        int r = i >> 4, col = i & 15;
        float4 v = ((const float4*)(bp + (size_t)r * 128))[col];
        *(float4*)&sB[r * 72 + col * 4] =
            make_float4(tf32f(v.x), tf32f(v.y), tf32f(v.z), tf32f(v.w));
    }
    __syncthreads();

    // inclusive log-decay prefix via warp 0 shuffles (2 elems/lane)
    if (wid == 0) {
        float a0 = scs[2 * lane], a1 = scs[2 * lane + 1];
        float ps = a0 + a1;
        #pragma unroll
        for (int off = 1; off < 32; off <<= 1) {
            float v = __shfl_up_sync(0xffffffffu, ps, off);
            if (lane >= off) ps += v;
        }
        scs[2 * lane + 1] = ps;
        scs[2 * lane]     = ps - a1;
    }
    __syncthreads();

    float cstot = scs[CS - 1];
    const float* xp = g_x + ((size_t)b * TT + t0) * DINNER + h * HD;
    for (int i = tid; i < CS * 12; i += 192) {
        int r = i / 12, col = i % 12;
        float w = __expf(cstot - scs[r]) * sdt[r];
        float4 v = ((const float4*)(xp + (size_t)r * DINNER))[col];
        *(float4*)&sxw[r * 56 + col * 4] =
            make_float4(tf32f(v.x * w), tf32f(v.y * w), tf32f(v.z * w), tf32f(v.w * w));
    }
    __syncthreads();

    // S[p][n] = sum_t Xw[t][p] * B[t][n]
    int p0 = (wid % 3) * 16;
    int nb = (wid / 3) * 32;
    float acc[4][4];
    #pragma unroll
    for (int j = 0; j < 4; j++)
        #pragma unroll
        for (int e = 0; e < 4; e++) acc[j][e] = 0.f;

    #pragma unroll
    for (int k = 0; k < CS; k += 8) {
        uint32_t a[4];
        a[0] = __float_as_uint(sxw[(k + lq) * 56 + p0 + lh]);
        a[1] = __float_as_uint(sxw[(k + lq) * 56 + p0 + lh + 8]);
        a[2] = __float_as_uint(sxw[(k + 4 + lq) * 56 + p0 + lh]);
        a[3] = __float_as_uint(sxw[(k + 4 + lq) * 56 + p0 + lh + 8]);
        #pragma unroll
        for (int j = 0; j < 4; j++) {
            uint32_t bfr[2];
            bfr[0] = __float_as_uint(sB[(k + lq) * 72 + nb + 8 * j + lh]);
            bfr[1] = __float_as_uint(sB[(k + 4 + lq) * 72 + nb + 8 * j + lh]);
            mma8(acc[j], a, bfr);
        }
    }

    float* sp = g_S + ((size_t)bh * NC + c) * (HD * DS);
    #pragma unroll
    for (int j = 0; j < 4; j++) {
        int n0 = nb + 8 * j + 2 * lq;
        *(float2*)&sp[(p0 + lh) * DS + n0]     = make_float2(acc[j][0], acc[j][1]);
        *(float2*)&sp[(p0 + lh + 8) * DS + n0] = make_float2(acc[j][2], acc[j][3]);
    }
    if (tid == 0) g_Dc[bh * NC + c] = __expf(cstot);
}

// ---------------- kB: inter-chunk scan (prefetched) ----------------
// grid (128, 2) block 384 : thread owns 4 contiguous states
__global__ void kB() {
    int bh = blockIdx.x, half = blockIdx.y;
    int tid = threadIdx.x;
    float h4[4] = {0.f, 0.f, 0.f, 0.f};
    size_t base = (size_t)bh * NC * (HD * DS) + (size_t)half * 1536 + tid * 4;
    float4 a = *(float4*)(g_S + base);
    float Dc = g_Dc[bh * NC];
    for (int c = 0; c < NC; c++) {
        float* sp = g_S + base + (size_t)c * (HD * DS);
        float4 an = make_float4(0.f, 0.f, 0.f, 0.f);
        float Dn = 0.f;
        if (c + 1 < NC) {
            an = *(float4*)(sp + HD * DS);
            Dn = g_Dc[bh * NC + c + 1];
        }
        *(float4*)sp = make_float4(h4[0], h4[1], h4[2], h4[3]);
        h4[0] = fmaf(h4[0], Dc, a.x); h4[1] = fmaf(h4[1], Dc, a.y);
        h4[2] = fmaf(h4[2], Dc, a.z); h4[3] = fmaf(h4[3], Dc, a.w);
        a = an; Dc = Dn;
    }
}

// ---------------- kC: chunked SSD via tf32 tensor-core mma ----------------
// grid (NC, BB) block 256 (8 warps)
#define ST64 72
#define ST48 56
#define KC_BT   0                       // [n][s] tf32, 64*72
#define KC_CT   (KC_BT + 64 * ST64)     // [n][t] tf32
#define KC_G    (KC_CT + 64 * ST64)     // [t][s] tf32 (per head)
#define KC_SX   (KC_G + 64 * ST64)      // [s][p] fp32, 64*56
#define KC_SHIN (KC_SX + 64 * ST48)     // [n][p] tf32, 64*56
#define KC_SCS  (KC_SHIN + 64 * ST48)   // 8*64
#define KC_SDT  (KC_SCS + 512)          // 8*64
#define KC_SMEM_FLOATS (KC_SDT + 512)

__global__ __launch_bounds__(256) void kC(const float* __restrict__ D_skip) {
    extern __shared__ float sm[];
    float* sBt  = sm + KC_BT;
    float* sCt  = sm + KC_CT;
    float* sG   = sm + KC_G;
    float* sx   = sm + KC_SX;
    float* shin = sm + KC_SHIN;
    float* sCS  = sm + KC_SCS;
    float* sDT  = sm + KC_SDT;

    int c = blockIdx.x, b = blockIdx.y;
    int tid = threadIdx.x;
    int wid = tid >> 5, lane = tid & 31;
    int lq = lane & 3, lh = lane >> 2;
    int t0c = c * CS;

    if (tid < 128) {
        const float* lap = g_la + ((size_t)b * TT + t0c) * NH;
        const float* dtp = g_dt + ((size_t)b * TT + t0c) * NH;
        float4 v = ((const float4*)lap)[tid];
        float4 w = ((const float4*)dtp)[tid];
        int j0 = tid * 4;
        #pragma unroll
        for (int u = 0; u < 4; u++) {
            int j = j0 + u;
            int t = j >> 3, h = j & 7;
            sCS[h * 64 + t] = (&v.x)[u];
            sDT[h * 64 + t] = (&w.x)[u];
        }
    }

    const float* bp = g_bc + ((size_t)b * TT + t0c) * 128;
    for (int i = tid; i < CS * 16; i += 256) {
        int s = i >> 4, nq = i & 15;
        float4 v = ((const float4*)(bp + (size_t)s * 128))[nq];          // B[s][n]
        sBt[(nq * 4 + 0) * ST64 + s] = tf32f(v.x);
        sBt[(nq * 4 + 1) * ST64 + s] = tf32f(v.y);
        sBt[(nq * 4 + 2) * ST64 + s] = tf32f(v.z);
        sBt[(nq * 4 + 3) * ST64 + s] = tf32f(v.w);
        float4 w = ((const float4*)(bp + (size_t)s * 128))[nq + 16];     // C[s][n]
        sCt[(nq * 4 + 0) * ST64 + s] = tf32f(w.x);
        sCt[(nq * 4 + 1) * ST64 + s] = tf32f(w.y);
        sCt[(nq * 4 + 2) * ST64 + s] = tf32f(w.z);
        sCt[(nq * 4 + 3) * ST64 + s] = tf32f(w.w);
    }
    __syncthreads();

    // per-head inclusive log-decay prefix (warp w = head w)
    {
        float a0 = sCS[wid * 64 + 2 * lane];
        float a1 = sCS[wid * 64 + 2 * lane + 1];
        float ps = a0 + a1;
        #pragma unroll
        for (int off = 1; off < 32; off <<= 1) {
            float v = __shfl_up_sync(0xffffffffu, ps, off);
            if (lane >= off) ps += v;
        }
        sCS[wid * 64 + 2 * lane + 1] = ps;
        sCS[wid * 64 + 2 * lane]     = ps - a1;
    }

    // GEMM1 (shared across heads): Graw[t][s] = sum_n C[t][n]*B[s][n]
    int t0 = (wid & 3) * 16;
    int sb = (wid >> 2) * 32;
    float g1[4][4];
    #pragma unroll
    for (int j = 0; j < 4; j++)
        #pragma unroll
        for (int e = 0; e < 4; e++) g1[j][e] = 0.f;

    #pragma unroll
    for (int k = 0; k < DS; k += 8) {
        uint32_t a[4];
        a[0] = __float_as_uint(sCt[(k + lq) * ST64 + t0 + lh]);
        a[1] = __float_as_uint(sCt[(k + lq) * ST64 + t0 + lh + 8]);
        a[2] = __float_as_uint(sCt[(k + 4 + lq) * ST64 + t0 + lh]);
        a[3] = __float_as_uint(sCt[(k + 4 + lq) * ST64 + t0 + lh + 8]);
        #pragma unroll
        for (int j = 0; j < 4; j++) {
            uint32_t bfr[2];
            bfr[0] = __float_as_uint(sBt[(k + lq) * ST64 + sb + 8 * j + lh]);
            bfr[1] = __float_as_uint(sBt[(k + 4 + lq) * ST64 + sb + 8 * j + lh]);
            mma8(g1[j], a, bfr);
        }
    }

    int pb = (wid >> 2) * 24;

    for (int h = 0; h < NH; h++) {
        __syncthreads();

        const float* xp = g_x + ((size_t)b * TT + t0c) * DINNER + h * HD;
        for (int i = tid; i < CS * 12; i += 256) {
            int s = i / 12, col = i % 12;
            float4 v = ((const float4*)(xp + (size_t)s * DINNER))[col];
            *(float4*)&sx[s * ST48 + col * 4] = v;
        }
        const float* hp = g_S + ((size_t)(b * NH + h) * NC + c) * (HD * DS);
        for (int i = tid; i < HD * 16; i += 256) {
            int p = i >> 4, nq = i & 15;
            float4 v = ((const float4*)(hp + p * DS))[nq];
            shin[(nq * 4 + 0) * ST48 + p] = tf32f(v.x);
            shin[(nq * 4 + 1) * ST48 + p] = tf32f(v.y);
            shin[(nq * 4 + 2) * ST48 + p] = tf32f(v.z);
            shin[(nq * 4 + 3) * ST48 + p] = tf32f(v.w);
        }

        const float* csh = sCS + h * 64;
        const float* dth = sDT + h * 64;
        {
            float cs_r0 = csh[t0 + lh], cs_r1 = csh[t0 + lh + 8];
            #pragma unroll
            for (int j = 0; j < 4; j++) {
                int c0 = sb + 8 * j + 2 * lq;
                float cs_c0 = csh[c0], cs_c1 = csh[c0 + 1];
                float dt_c0 = dth[c0], dt_c1 = dth[c0 + 1];
                int r0 = t0 + lh, r1 = r0 + 8;
                float m00 = (c0 <= r0) ? __expf(cs_r0 - cs_c0) * dt_c0 : 0.f;
                float m01 = (c0 + 1 <= r0) ? __expf(cs_r0 - cs_c1) * dt_c1 : 0.f;
                float m10 = (c0 <= r1) ? __expf(cs_r1 - cs_c0) * dt_c0 : 0.f;
                float m11 = (c0 + 1 <= r1) ? __expf(cs_r1 - cs_c1) * dt_c1 : 0.f;
                sG[r0 * ST64 + c0]     = tf32f(g1[j][0] * m00);
                sG[r0 * ST64 + c0 + 1] = tf32f(g1[j][1] * m01);
                sG[r1 * ST64 + c0]     = tf32f(g1[j][2] * m10);
                sG[r1 * ST64 + c0 + 1] = tf32f(g1[j][3] * m11);
            }
        }
        __syncthreads();

        float accA[3][4], accB[3][4];
        #pragma unroll
        for (int j = 0; j < 3; j++)
            #pragma unroll
            for (int e = 0; e < 4; e++) { accA[j][e] = 0.f; accB[j][e] = 0.f; }

        #pragma unroll
        for (int k = 0; k < CS; k += 8) {
            uint32_t a[4];
            a[0] = __float_as_uint(sG[(t0 + lh) * ST64 + k + lq]);
            a[1] = __float_as_uint(sG[(t0 + lh + 8) * ST64 + k + lq]);
            a[2] = __float_as_uint(sG[(t0 + lh) * ST64 + k + 4 + lq]);
            a[3] = __float_as_uint(sG[(t0 + lh + 8) * ST64 + k + 4 + lq]);
            #pragma unroll
            for (int j = 0; j < 3; j++) {
                uint32_t bfr[2];
                bfr[0] = tf32u(sx[(k + lq) * ST48 + pb + 8 * j + lh]);
                bfr[1] = tf32u(sx[(k + 4 + lq) * ST48 + pb + 8 * j + lh]);
                mma8(accA[j], a, bfr);
            }
        }
        #pragma unroll
        for (int k = 0; k < DS; k += 8) {
            uint32_t a[4];
            a[0] = __float_as_uint(sCt[(k + lq) * ST64 + t0 + lh]);
            a[1] = __float_as_uint(sCt[(k + lq) * ST64 + t0 + lh + 8]);
            a[2] = __float_as_uint(sCt[(k + 4 + lq) * ST64 + t0 + lh]);
            a[3] = __float_as_uint(sCt[(k + 4 + lq) * ST64 + t0 + lh + 8]);
            #pragma unroll
            for (int j = 0; j < 3; j++) {
                uint32_t bfr[2];
                bfr[0] = __float_as_uint(shin[(k + lq) * ST48 + pb + 8 * j + lh]);
                bfr[1] = __float_as_uint(shin[(k + 4 + lq) * ST48 + pb + 8 * j + lh]);
                mma8(accB[j], a, bfr);
            }
        }

        float dskip = D_skip[h];
        float et0 = __expf(csh[t0 + lh]);
        float et1 = __expf(csh[t0 + lh + 8]);
        float* yp = g_y + ((size_t)b * TT + t0c) * DINNER + h * HD;
        #pragma unroll
        for (int j = 0; j < 3; j++) {
            int p0 = pb + 8 * j + 2 * lq;
            int r0 = t0 + lh, r1 = r0 + 8;
            yp[(size_t)r0 * DINNER + p0]     = accA[j][0] + et0 * accB[j][0] + dskip * sx[r0 * ST48 + p0];
            yp[(size_t)r0 * DINNER + p0 + 1] = accA[j][1] + et0 * accB[j][1] + dskip * sx[r0 * ST48 + p0 + 1];
            yp[(size_t)r1 * DINNER + p0]     = accA[j][2] + et1 * accB[j][2] + dskip * sx[r1 * ST48 + p0];
            yp[(size_t)r1 * DINNER + p0 + 1] = accA[j][3] + et1 * accB[j][3] + dskip * sx[r1 * ST48 + p0 + 1];
        }
    }
}

// ---------------- kD: gating + RMSNorm + mma GEMM(W2) + mix2 + partial ----
// grid (128, 16) block 256, 32 rows/block, dynamic smem
#define KD_SG 0            // 32*388 (tf32 gated values, row-major)
#define KD_SWM2 12416      // 1024
#define KD_SW1Z 13440      // 1536
#define KD_SMV 14976       // 384
#define KD_SM1 15360       // 32*33
#define KD_SRSTD 16416     // 32
#define KD_SMEM_FLOATS 16448

__global__ __launch_bounds__(256) void kD(const float* __restrict__ x,
                   const float* __restrict__ w_mix2, const float* __restrict__ b_mix1,
                   const float* __restrict__ b_mix2) {
    extern __shared__ float sm[];
    float* sg   = sm + KD_SG;     // [r][dd] stride 388, tf32 values
    float* swm2 = sm + KD_SWM2;
    float* sW1z = sm + KD_SW1Z;
    float* smv  = sm + KD_SMV;
    float* sm1  = sm + KD_SM1;    // [r][o] stride 33
    float* srstd= sm + KD_SRSTD;

    int tid = threadIdx.x;
    int wid = tid >> 5, lane = tid & 31;
    int lq = lane & 3, lh = lane >> 2;
    int b = blockIdx.y;
    int t0 = blockIdx.x * 32;

    for (int i = tid; i < DINNER; i += 256) smv[i] = g_mvec[b * DPROJ + i];
    for (int i = tid; i < 4 * DINNER; i += 256) sW1z[i] = g_W1[(i / DINNER) * DPROJ + (i % DINNER)];
    for (int i = tid; i < MIXD * MIXD; i += 256) swm2[i] = w_mix2[i];
    __syncthreads();

    // phase 1: gating, store tf32 g, row sum-of-squares -> rstd
    int r = tid >> 3, seg = tid & 7;
    int dd0 = seg * 48;
    const float* xr = x + ((size_t)b * TT + t0 + r) * 4;
    float x0 = xr[0], x1 = xr[1], x2 = xr[2], x3 = xr[3];
    const float* yr = g_y + ((size_t)b * TT + t0 + r) * DINNER + dd0;
    float ss = 0.f;
    #pragma unroll
    for (int q = 0; q < 12; q++) {
        float4 y4 = ((const float4*)yr)[q];
        float gv[4] = {y4.x, y4.y, y4.z, y4.w};
        #pragma unroll
        for (int u = 0; u < 4; u++) {
            int dd = dd0 + q * 4 + u;
            float z = smv[dd];
            z = fmaf(x0, sW1z[dd], z);
            z = fmaf(x1, sW1z[DINNER + dd], z);
            z = fmaf(x2, sW1z[2 * DINNER + dd], z);
            z = fmaf(x3, sW1z[3 * DINNER + dd], z);
            float g = gv[u] * siluf(z);
            ss = fmaf(g, g, ss);
            gv[u] = tf32f(g);
        }
        *(float4*)&sg[r * 388 + dd0 + q * 4] = make_float4(gv[0], gv[1], gv[2], gv[3]);
    }
    ss += __shfl_xor_sync(0xffffffffu, ss, 1);
    ss += __shfl_xor_sync(0xffffffffu, ss, 2);
    ss += __shfl_xor_sync(0xffffffffu, ss, 4);
    if (seg == 0) srstd[r] = rsqrtf(ss * (1.f / DINNER) + 1e-5f);
    __syncthreads();

    // mma GEMM: m1_raw[r][o] = sum_dd g[r][dd] * W2n[dd][o]
    // 8 warps: m-strip (w&1)*16, o-col8 (w>>1)*8; K = 384
    {
        int m0 = (wid & 1) * 16;
        int o0 = (wid >> 1) * 8;
        float acc[4] = {0.f, 0.f, 0.f, 0.f};
        #pragma unroll 4
        for (int k = 0; k < DINNER; k += 8) {
            uint32_t a[4];
            a[0] = __float_as_uint(sg[(m0 + lh) * 388 + k + lq]);
            a[1] = __float_as_uint(sg[(m0 + lh + 8) * 388 + k + lq]);
            a[2] = __float_as_uint(sg[(m0 + lh) * 388 + k + 4 + lq]);
            a[3] = __float_as_uint(sg[(m0 + lh + 8) * 388 + k + 4 + lq]);
            uint32_t bfr[2];
            bfr[0] = tf32u(g_W2[(k + lq) * MIXD + o0 + lh]);
            bfr[1] = tf32u(g_W2[(k + 4 + lq) * MIXD + o0 + lh]);
            mma8(acc, a, bfr);
        }
        int r0 = m0 + lh, r1 = r0 + 8;
        int oc = o0 + 2 * lq;
        float rs0 = srstd[r0], rs1 = srstd[r1];
        sm1[r0 * 33 + oc]     = fmaxf(fmaf(acc[0], rs0, b_mix1[oc]), 0.f);
        sm1[r0 * 33 + oc + 1] = fmaxf(fmaf(acc[1], rs0, b_mix1[oc + 1]), 0.f);
        sm1[r1 * 33 + oc]     = fmaxf(fmaf(acc[2], rs1, b_mix1[oc]), 0.f);
        sm1[r1 * 33 + oc + 1] = fmaxf(fmaf(acc[3], rs1, b_mix1[oc + 1]), 0.f);
    }
    __syncthreads();

    // mix2 + relu
    int io4 = tid & 7, r2 = tid >> 3;
    int o0 = io4 * 4;
    float m2[4] = {b_mix2[o0], b_mix2[o0 + 1], b_mix2[o0 + 2], b_mix2[o0 + 3]};
    #pragma unroll
    for (int i = 0; i < MIXD; i++) {
        float m = sm1[r2 * 33 + i];
        float4 w = *(const float4*)&swm2[i * MIXD + o0];
        m2[0] = fmaf(m, w.x, m2[0]);
        m2[1] = fmaf(m, w.y, m2[1]);
        m2[2] = fmaf(m, w.z, m2[2]);
        m2[3] = fmaf(m, w.w, m2[3]);
    }
    float* sred = sg;
    #pragma unroll
    for (int u = 0; u < 4; u++) sred[r2 * 33 + o0 + u] = fmaxf(m2[u], 0.f);
    __syncthreads();
    if (tid < MIXD) {
        float a = 0.f;
        for (int rr = 0; rr < 32; rr++) a += sred[rr * 33 + tid];
        g_part[((size_t)b * 128 + blockIdx.x) * MIXD + tid] = a;
    }
}

// ---------------- kF: final mean + w_out ----------------
__global__ void kF(const float* __restrict__ w_out, const float* __restrict__ b_out,
                   float* __restrict__ out) {
    int b = threadIdx.x;
    if (b < BB) {
        float s = 0.f;
        for (int o = 0; o < MIXD; o++) {
            float a = 0.f;
            for (int blk = 0; blk < 128; blk++) a += g_part[((size_t)b * 128 + blk) * MIXD + o];
            s = fmaf(a * (1.f / (float)TT), w_out[o], s);
        }
        out[b] = s + b_out[0];
    }
}

extern "C" void kernel_launch(void* const* d_in, const int* in_sizes, int n_in,
                              void* d_out, int out_size) {
    const float* x        = (const float*)d_in[0];
    const float* mic_pos  = (const float*)d_in[1];
    const float* w_in     = (const float*)d_in[2];
    const float* b_in     = (const float*)d_in[3];
    const float* w_mic    = (const float*)d_in[4];
    const float* b_mic    = (const float*)d_in[5];
    const float* w_inproj = (const float*)d_in[6];
    const float* conv_w   = (const float*)d_in[7];
    const float* conv_b   = (const float*)d_in[8];
    const float* dt_bias  = (const float*)d_in[9];
    const float* A_log    = (const float*)d_in[10];
    const float* D_skip   = (const float*)d_in[11];
    const float* norm_w   = (const float*)d_in[12];
    const float* w_outproj= (const float*)d_in[13];
    const float* w_mix1   = (const float*)d_in[14];
    const float* b_mix1   = (const float*)d_in[15];
    const float* w_mix2   = (const float*)d_in[16];
    const float* b_mix2   = (const float*)d_in[17];
    const float* w_out    = (const float*)d_in[18];
    const float* b_out    = (const float*)d_in[19];
    float* out = (float*)d_out;

    cudaFuncSetAttribute(kC, cudaFuncAttributeMaxDynamicSharedMemorySize, KC_SMEM_FLOATS * 4);
    cudaFuncSetAttribute(kD, cudaFuncAttributeMaxDynamicSharedMemorySize, KD_SMEM_FLOATS * 4);

    k0a<<<1, 256>>>(mic_pos, w_mic, b_mic, b_in, A_log);
    k0b<<<(4 * DPROJ + BB * DPROJ + DINNER * MIXD + 255) / 256, 256>>>(w_in, w_inproj, w_outproj, w_mix1, norm_w);
    k1<<<dim3(32, 16), 128>>>(x, conv_w, conv_b, dt_bias);
    kA<<<dim3(NC, 128), 192>>>();
    kB<<<dim3(128, 2), 384>>>();
    kC<<<dim3(NC, BB), 256, KC_SMEM_FLOATS * 4>>>(D_skip);
    kD<<<dim3(128, 16), 256, KD_SMEM_FLOATS * 4>>>(x, w_mix2, b_mix1, b_mix2);
    kF<<<1, 32>>>(w_out, b_out, out);
}

// round 7
// speedup vs baseline: 2.8016x; 1.1681x over previous
#include <cuda_runtime.h>
#include <cuda_bf16.h>
#include <math.h>
#include <stdint.h>

#define BB 16
#define TT 4096
#define DINNER 384
#define NH 8
#define HD 48
#define DS 64
#define DPROJ 904
#define NC 64
#define CS 64
#define MIXD 32

// ---------------- scratch (static device arrays; no runtime alloc) ----------
__device__ float g_W1[4 * DPROJ];            // w_in @ w_inproj
__device__ float g_mvec[BB * DPROJ];         // (b_in + relu(mic)) @ w_inproj
__device__ uint32_t g_W2bt32[32 * 192];      // bf16x2 [o][dpair]: norm_w*(w_outproj@w_mix1) transposed
__device__ float g_hb[BB * 192];
__device__ float g_A[NH];
__device__ float g_x[(size_t)BB * TT * DINNER];   // silu(conv) xs
__device__ float g_bc[(size_t)BB * TT * 128];     // B(64) | C(64)
__device__ float g_dt[(size_t)BB * TT * NH];
__device__ float g_la[(size_t)BB * TT * NH];      // log-decay = dt*A
__device__ float g_S[(size_t)128 * NC * HD * DS]; // chunk states -> h_in (in place)
__device__ float g_Dc[128 * NC];
__device__ uint32_t g_ybf32[(size_t)BB * TT * 192]; // gated y, bf16x2 pairs
__device__ float g_rstd[BB * TT];
__device__ float g_part[2048 * MIXD];

__device__ __forceinline__ float siluf(float v) {
    if (fabsf(v) < 0.25f) {
        float z2 = v * v;
        float sig = 0.5f + v * (0.25f + z2 * (-(1.f / 48.f) + z2 * (1.f / 480.f)));
        return v * sig;
    }
    return __fdividef(v, 1.f + __expf(-v));
}
__device__ __forceinline__ float softplusf(float v) { return v > 20.f ? v : __logf(1.f + __expf(v)); }

__device__ __forceinline__ uint32_t tf32u(float x) {
    uint32_t r;
    asm("cvt.rna.tf32.f32 %0, %1;" : "=r"(r) : "f"(x));
    return r;
}
__device__ __forceinline__ float tf32f(float x) { return __uint_as_float(tf32u(x)); }

__device__ __forceinline__ uint32_t packbf(float lo, float hi) {
    uint32_t w;
    asm("cvt.rn.bf16x2.f32 %0, %1, %2;" : "=r"(w) : "f"(hi), "f"(lo));
    return w;
}

__device__ __forceinline__ void mma8(float d[4], const uint32_t a[4], const uint32_t b[2]) {
    asm volatile(
        "mma.sync.aligned.m16n8k8.row.col.f32.tf32.tf32.f32 "
        "{%0,%1,%2,%3},{%4,%5,%6,%7},{%8,%9},{%0,%1,%2,%3};\n"
        : "+f"(d[0]), "+f"(d[1]), "+f"(d[2]), "+f"(d[3])
        : "r"(a[0]), "r"(a[1]), "r"(a[2]), "r"(a[3]),
          "r"(b[0]), "r"(b[1]));
}

__device__ __forceinline__ void mma16(float d[4], const uint32_t a[4], const uint32_t b[2]) {
    asm volatile(
        "mma.sync.aligned.m16n8k16.row.col.f32.bf16.bf16.f32 "
        "{%0,%1,%2,%3},{%4,%5,%6,%7},{%8,%9},{%0,%1,%2,%3};\n"
        : "+f"(d[0]), "+f"(d[1]), "+f"(d[2]), "+f"(d[3])
        : "r"(a[0]), "r"(a[1]), "r"(a[2]), "r"(a[3]),
          "r"(b[0]), "r"(b[1]));
}

// ---------------- k0a: mic MLP + A ----------------
__global__ void k0a(const float* __restrict__ mic_pos, const float* __restrict__ w_mic,
                    const float* __restrict__ b_mic, const float* __restrict__ b_in,
                    const float* __restrict__ A_log) {
    int tid = threadIdx.x;
    for (int i = tid; i < BB * 192; i += 256) {
        int b = i / 192, d = i % 192;
        float s = b_mic[d];
        #pragma unroll
        for (int j = 0; j < 12; j++) s = fmaf(mic_pos[b * 12 + j], w_mic[j * 192 + d], s);
        g_hb[i] = b_in[d] + fmaxf(s, 0.f);
    }
    if (tid < NH) g_A[tid] = -expf(A_log[tid]);
}

// ---------------- k0b: folded weights ----------------
__global__ void k0b(const float* __restrict__ w_in, const float* __restrict__ w_inproj,
                    const float* __restrict__ w_outproj, const float* __restrict__ w_mix1,
                    const float* __restrict__ norm_w) {
    int i = blockIdx.x * 256 + threadIdx.x;
    if (i < 4 * DPROJ) {
        int j = i / DPROJ, d = i % DPROJ;
        float s = 0.f;
        for (int m = 0; m < 192; m++) s = fmaf(w_in[j * 192 + m], w_inproj[m * DPROJ + d], s);
        g_W1[i] = s;
    } else if (i < 4 * DPROJ + BB * DPROJ) {
        int ii = i - 4 * DPROJ;
        int b = ii / DPROJ, d = ii % DPROJ;
        float s = 0.f;
        for (int m = 0; m < 192; m++) s = fmaf(g_hb[b * 192 + m], w_inproj[m * DPROJ + d], s);
        g_mvec[ii] = s;
    } else if (i < 4 * DPROJ + BB * DPROJ + 32 * 192) {
        int ii = i - (4 * DPROJ + BB * DPROJ);
        int o = ii / 192, kw = ii % 192;
        int d0 = 2 * kw, d1 = d0 + 1;
        float s0 = 0.f, s1 = 0.f;
        for (int m = 0; m < 192; m++) {
            s0 = fmaf(w_outproj[d0 * 192 + m], w_mix1[m * MIXD + o], s0);
            s1 = fmaf(w_outproj[d1 * 192 + m], w_mix1[m * MIXD + o], s1);
        }
        g_W2bt32[o * 192 + kw] = packbf(s0 * norm_w[d0], s1 * norm_w[d1]);
    }
}

// ---------------- k1: fused inproj + conv4 + silu + dt/la ----------------
// grid (32, 16) block 128 : thread = one t
__global__ void k1(const float* __restrict__ x, const float* __restrict__ conv_w,
                   const float* __restrict__ conv_b, const float* __restrict__ dt_bias) {
    __shared__ float sW1[4 * 520];   // proj dims 384..903
    __shared__ float smv[520];
    __shared__ float scw[512 * 4];
    __shared__ float scb[512];
    __shared__ float sx4[131 * 4];
    __shared__ float sraw[131 * 33];

    int tid = threadIdx.x;
    int b = blockIdx.y;
    int t0 = blockIdx.x * 128;

    for (int i = tid; i < 4 * 520; i += 128) sW1[i] = g_W1[(i / 520) * DPROJ + 384 + (i % 520)];
    for (int i = tid; i < 520; i += 128) smv[i] = g_mvec[b * DPROJ + 384 + i];
    for (int i = tid; i < 512 * 4; i += 128) scw[i] = conv_w[i];
    for (int i = tid; i < 512; i += 128) scb[i] = conv_b[i];
    for (int i = tid; i < 131 * 4; i += 128) {
        int r = i >> 2, j = i & 3;
        int t = t0 + r - 3;
        sx4[i] = (t >= 0) ? x[((size_t)b * TT + t) * 4 + j] : 0.f;
    }

    int t = t0 + tid;
    for (int c16 = 0; c16 < 16; c16++) {
        __syncthreads();
        for (int i = tid; i < 131 * 32; i += 128) {
            int r = i >> 5, dc = i & 31;
            int dd = c16 * 32 + dc;
            float v = 0.f;
            if (t0 + r - 3 >= 0) {
                v = smv[dd];
                #pragma unroll
                for (int j = 0; j < 4; j++) v = fmaf(sx4[r * 4 + j], sW1[j * 520 + dd], v);
            }
            sraw[r * 33 + dc] = v;
        }
        __syncthreads();
        float v[32];
        #pragma unroll
        for (int dc = 0; dc < 32; dc++) {
            int dd = c16 * 32 + dc;
            float a = scb[dd];
            #pragma unroll
            for (int k = 0; k < 4; k++) a = fmaf(sraw[(tid + k) * 33 + dc], scw[dd * 4 + k], a);
            v[dc] = siluf(a);
        }
        float* dst;
        if (c16 < 12) dst = g_x + ((size_t)b * TT + t) * DINNER + c16 * 32;
        else          dst = g_bc + ((size_t)b * TT + t) * 128 + (c16 - 12) * 32;
        #pragma unroll
        for (int q = 0; q < 8; q++)
            ((float4*)dst)[q] = make_float4(v[4 * q], v[4 * q + 1], v[4 * q + 2], v[4 * q + 3]);
    }

    // dt path (proj dims 896..903 via sW1 dims 512..519)
    #pragma unroll
    for (int hh = 0; hh < NH; hh++) {
        int dd = 512 + hh;
        float v = smv[dd];
        #pragma unroll
        for (int j = 0; j < 4; j++) v = fmaf(sx4[(tid + 3) * 4 + j], sW1[j * 520 + dd], v);
        float dt = softplusf(v + dt_bias[hh]);
        size_t o = ((size_t)b * TT + t) * NH + hh;
        g_dt[o] = dt;
        g_la[o] = dt * g_A[hh];
    }
}

// ---------------- kA: chunk-local end states via tf32 mma ----------------
// grid (NC, 128) block 192 (6 warps): warp = (p-strip w%3, n-half w/3)
__global__ __launch_bounds__(192) void kA() {
    __shared__ float sxw[CS * 56];   // [t][p] = w(t)*x(t,p), tf32
    __shared__ float sB[CS * 72];    // [t][n], tf32
    __shared__ float scs[CS];
    __shared__ float sdt[CS];

    int c = blockIdx.x, bh = blockIdx.y;
    int b = bh >> 3, h = bh & 7;
    int tid = threadIdx.x;
    int wid = tid >> 5, lane = tid & 31;
    int lq = lane & 3, lh = lane >> 2;
    int t0 = c * CS;

    if (tid < CS) {
        size_t o = ((size_t)b * TT + t0 + tid) * NH + h;
        scs[tid] = g_la[o];
        sdt[tid] = g_dt[o];
    }
    const float* bp = g_bc + ((size_t)b * TT + t0) * 128;
    for (int i = tid; i < CS * 16; i += 192) {
        int r = i >> 4, col = i & 15;
        float4 v = ((const float4*)(bp + (size_t)r * 128))[col];
        *(float4*)&sB[r * 72 + col * 4] =
            make_float4(tf32f(v.x), tf32f(v.y), tf32f(v.z), tf32f(v.w));
    }
    __syncthreads();

    if (wid == 0) {
        float a0 = scs[2 * lane], a1 = scs[2 * lane + 1];
        float ps = a0 + a1;
        #pragma unroll
        for (int off = 1; off < 32; off <<= 1) {
            float v = __shfl_up_sync(0xffffffffu, ps, off);
            if (lane >= off) ps += v;
        }
        scs[2 * lane + 1] = ps;
        scs[2 * lane]     = ps - a1;
    }
    __syncthreads();

    float cstot = scs[CS - 1];
    const float* xp = g_x + ((size_t)b * TT + t0) * DINNER + h * HD;
    for (int i = tid; i < CS * 12; i += 192) {
        int r = i / 12, col = i % 12;
        float w = __expf(cstot - scs[r]) * sdt[r];
        float4 v = ((const float4*)(xp + (size_t)r * DINNER))[col];
        *(float4*)&sxw[r * 56 + col * 4] =
            make_float4(tf32f(v.x * w), tf32f(v.y * w), tf32f(v.z * w), tf32f(v.w * w));
    }
    __syncthreads();

    int p0 = (wid % 3) * 16;
    int nb = (wid / 3) * 32;
    float acc[4][4];
    #pragma unroll
    for (int j = 0; j < 4; j++)
        #pragma unroll
        for (int e = 0; e < 4; e++) acc[j][e] = 0.f;

    #pragma unroll
    for (int k = 0; k < CS; k += 8) {
        uint32_t a[4];
        a[0] = __float_as_uint(sxw[(k + lq) * 56 + p0 + lh]);
        a[1] = __float_as_uint(sxw[(k + lq) * 56 + p0 + lh + 8]);
        a[2] = __float_as_uint(sxw[(k + 4 + lq) * 56 + p0 + lh]);
        a[3] = __float_as_uint(sxw[(k + 4 + lq) * 56 + p0 + lh + 8]);
        #pragma unroll
        for (int j = 0; j < 4; j++) {
            uint32_t bfr[2];
            bfr[0] = __float_as_uint(sB[(k + lq) * 72 + nb + 8 * j + lh]);
            bfr[1] = __float_as_uint(sB[(k + 4 + lq) * 72 + nb + 8 * j + lh]);
            mma8(acc[j], a, bfr);
        }
    }

    float* sp = g_S + ((size_t)bh * NC + c) * (HD * DS);
    #pragma unroll
    for (int j = 0; j < 4; j++) {
        int n0 = nb + 8 * j + 2 * lq;
        *(float2*)&sp[(p0 + lh) * DS + n0]     = make_float2(acc[j][0], acc[j][1]);
        *(float2*)&sp[(p0 + lh + 8) * DS + n0] = make_float2(acc[j][2], acc[j][3]);
    }
    if (tid == 0) g_Dc[bh * NC + c] = __expf(cstot);
}

// ---------------- kB: inter-chunk scan (prefetched) ----------------
__global__ void kB() {
    int bh = blockIdx.x, half = blockIdx.y;
    int tid = threadIdx.x;
    float h4[4] = {0.f, 0.f, 0.f, 0.f};
    size_t base = (size_t)bh * NC * (HD * DS) + (size_t)half * 1536 + tid * 4;
    float4 a = *(float4*)(g_S + base);
    float Dc = g_Dc[bh * NC];
    for (int c = 0; c < NC; c++) {
        float* sp = g_S + base + (size_t)c * (HD * DS);
        float4 an = make_float4(0.f, 0.f, 0.f, 0.f);
        float Dn = 0.f;
        if (c + 1 < NC) {
            an = *(float4*)(sp + HD * DS);
            Dn = g_Dc[bh * NC + c + 1];
        }
        *(float4*)sp = make_float4(h4[0], h4[1], h4[2], h4[3]);
        h4[0] = fmaf(h4[0], Dc, a.x); h4[1] = fmaf(h4[1], Dc, a.y);
        h4[2] = fmaf(h4[2], Dc, a.z); h4[3] = fmaf(h4[3], Dc, a.w);
        a = an; Dc = Dn;
    }
}

// ---------------- kC: chunked SSD + fused gating/RMS-stats ----------------
// grid (NC, BB) block 256 (8 warps)
#define ST64 72
#define STG 68
#define ST48 56
#define KC_BT   0                        // [n][s] tf32, 64*72
#define KC_CT   (KC_BT + 64 * ST64)      // [n][t] tf32
#define KC_G    (KC_CT + 64 * ST64)      // [t][s] tf32 (per head), stride 68
#define KC_SX   (KC_G + 64 * STG)        // [s][p] fp32, 64*56
#define KC_SHIN (KC_SX + 64 * ST48)      // [n][p] tf32, 64*56
#define KC_SCS  (KC_SHIN + 64 * ST48)    // 8*64 (reused as ss buffer at end)
#define KC_SDT  (KC_SCS + 512)           // 8*64
#define KC_W1Z  (KC_SDT + 512)           // 4*384
#define KC_MVZ  (KC_W1Z + 1536)          // 384
#define KC_X4   (KC_MVZ + 384)           // 64*4
#define KC_SMEM_FLOATS (KC_X4 + 256)

__global__ __launch_bounds__(256) void kC(const float* __restrict__ D_skip,
                                          const float* __restrict__ xin) {
    extern __shared__ float sm[];
    float* sBt  = sm + KC_BT;
    float* sCt  = sm + KC_CT;
    float* sG   = sm + KC_G;
    float* sx   = sm + KC_SX;
    float* shin = sm + KC_SHIN;
    float* sCS  = sm + KC_SCS;
    float* sDT  = sm + KC_SDT;
    float* sW1z = sm + KC_W1Z;
    float* smvz = sm + KC_MVZ;
    float* sx4  = sm + KC_X4;

    int c = blockIdx.x, b = blockIdx.y;
    int tid = threadIdx.x;
    int wid = tid >> 5, lane = tid & 31;
    int lq = lane & 3, lh = lane >> 2;
    int t0c = c * CS;

    if (tid < 128) {
        const float* lap = g_la + ((size_t)b * TT + t0c) * NH;
        const float* dtp = g_dt + ((size_t)b * TT + t0c) * NH;
        float4 v = ((const float4*)lap)[tid];
        float4 w = ((const float4*)dtp)[tid];
        int j0 = tid * 4;
        #pragma unroll
        for (int u = 0; u < 4; u++) {
            int j = j0 + u;
            int t = j >> 3, h = j & 7;
            sCS[h * 64 + t] = (&v.x)[u];
            sDT[h * 64 + t] = (&w.x)[u];
        }
    }
    for (int i = tid; i < 4 * DINNER; i += 256) sW1z[i] = g_W1[(i / DINNER) * DPROJ + (i % DINNER)];
    for (int i = tid; i < DINNER; i += 256) smvz[i] = g_mvec[b * DPROJ + i];
    if (tid < 256) {
        int r = tid >> 2, j = tid & 3;
        sx4[tid] = xin[((size_t)b * TT + t0c + r) * 4 + j];
    }

    const float* bp = g_bc + ((size_t)b * TT + t0c) * 128;
    for (int i = tid; i < CS * 16; i += 256) {
        int s = i >> 4, nq = i & 15;
        float4 v = ((const float4*)(bp + (size_t)s * 128))[nq];          // B[s][n]
        sBt[(nq * 4 + 0) * ST64 + s] = tf32f(v.x);
        sBt[(nq * 4 + 1) * ST64 + s] = tf32f(v.y);
        sBt[(nq * 4 + 2) * ST64 + s] = tf32f(v.z);
        sBt[(nq * 4 + 3) * ST64 + s] = tf32f(v.w);
        float4 w = ((const float4*)(bp + (size_t)s * 128))[nq + 16];     // C[s][n]
        sCt[(nq * 4 + 0) * ST64 + s] = tf32f(w.x);
        sCt[(nq * 4 + 1) * ST64 + s] = tf32f(w.y);
        sCt[(nq * 4 + 2) * ST64 + s] = tf32f(w.z);
        sCt[(nq * 4 + 3) * ST64 + s] = tf32f(w.w);
    }
    __syncthreads();

    // per-head inclusive log-decay prefix (warp w = head w)
    {
        float a0 = sCS[wid * 64 + 2 * lane];
        float a1 = sCS[wid * 64 + 2 * lane + 1];
        float ps = a0 + a1;
        #pragma unroll
        for (int off = 1; off < 32; off <<= 1) {
            float v = __shfl_up_sync(0xffffffffu, ps, off);
            if (lane >= off) ps += v;
        }
        sCS[wid * 64 + 2 * lane + 1] = ps;
        sCS[wid * 64 + 2 * lane]     = ps - a1;
    }

    int t0 = (wid & 3) * 16;
    int sb = (wid >> 2) * 32;
    int pb = (wid >> 2) * 24;

    // per-row x inputs (rows fixed per thread for the whole kernel)
    float xr0[4], xr1[4];
    #pragma unroll
    for (int u = 0; u < 4; u++) {
        xr0[u] = sx4[(t0 + lh) * 4 + u];
        xr1[u] = sx4[(t0 + lh + 8) * 4 + u];
    }

    // GEMM1 (shared across heads): Graw[t][s] = sum_n C[t][n]*B[s][n]
    float g1[4][4];
    #pragma unroll
    for (int j = 0; j < 4; j++)
        #pragma unroll
        for (int e = 0; e < 4; e++) g1[j][e] = 0.f;

    #pragma unroll
    for (int k = 0; k < DS; k += 8) {
        uint32_t a[4];
        a[0] = __float_as_uint(sCt[(k + lq) * ST64 + t0 + lh]);
        a[1] = __float_as_uint(sCt[(k + lq) * ST64 + t0 + lh + 8]);
        a[2] = __float_as_uint(sCt[(k + 4 + lq) * ST64 + t0 + lh]);
        a[3] = __float_as_uint(sCt[(k + 4 + lq) * ST64 + t0 + lh + 8]);
        #pragma unroll
        for (int j = 0; j < 4; j++) {
            uint32_t bfr[2];
            bfr[0] = __float_as_uint(sBt[(k + lq) * ST64 + sb + 8 * j + lh]);
            bfr[1] = __float_as_uint(sBt[(k + 4 + lq) * ST64 + sb + 8 * j + lh]);
            mma8(g1[j], a, bfr);
        }
    }

    float ss0 = 0.f, ss1 = 0.f;
    uint32_t* ybase = g_ybf32 + ((size_t)b * TT + t0c) * 192;

    for (int h = 0; h < NH; h++) {
        __syncthreads();

        const float* xp = g_x + ((size_t)b * TT + t0c) * DINNER + h * HD;
        for (int i = tid; i < CS * 12; i += 256) {
            int s = i / 12, col = i % 12;
            float4 v = ((const float4*)(xp + (size_t)s * DINNER))[col];
            *(float4*)&sx[s * ST48 + col * 4] = v;
        }
        const float* hp = g_S + ((size_t)(b * NH + h) * NC + c) * (HD * DS);
        for (int i = tid; i < HD * 16; i += 256) {
            int p = i >> 4, nq = i & 15;
            float4 v = ((const float4*)(hp + p * DS))[nq];
            shin[(nq * 4 + 0) * ST48 + p] = tf32f(v.x);
            shin[(nq * 4 + 1) * ST48 + p] = tf32f(v.y);
            shin[(nq * 4 + 2) * ST48 + p] = tf32f(v.z);
            shin[(nq * 4 + 3) * ST48 + p] = tf32f(v.w);
        }

        const float* csh = sCS + h * 64;
        const float* dth = sDT + h * 64;
        {
            float cs_r0 = csh[t0 + lh], cs_r1 = csh[t0 + lh + 8];
            #pragma unroll
            for (int j = 0; j < 4; j++) {
                int c0 = sb + 8 * j + 2 * lq;
                float cs_c0 = csh[c0], cs_c1 = csh[c0 + 1];
                float dt_c0 = dth[c0], dt_c1 = dth[c0 + 1];
                int r0 = t0 + lh, r1 = r0 + 8;
                float m00 = (c0 <= r0) ? __expf(cs_r0 - cs_c0) * dt_c0 : 0.f;
                float m01 = (c0 + 1 <= r0) ? __expf(cs_r0 - cs_c1) * dt_c1 : 0.f;
                float m10 = (c0 <= r1) ? __expf(cs_r1 - cs_c0) * dt_c0 : 0.f;
                float m11 = (c0 + 1 <= r1) ? __expf(cs_r1 - cs_c1) * dt_c1 : 0.f;
                sG[r0 * STG + c0]     = tf32f(g1[j][0] * m00);
                sG[r0 * STG + c0 + 1] = tf32f(g1[j][1] * m01);
                sG[r1 * STG + c0]     = tf32f(g1[j][2] * m10);
                sG[r1 * STG + c0 + 1] = tf32f(g1[j][3] * m11);
            }
        }
        __syncthreads();

        float accA[3][4], accB[3][4];
        #pragma unroll
        for (int j = 0; j < 3; j++)
            #pragma unroll
            for (int e = 0; e < 4; e++) { accA[j][e] = 0.f; accB[j][e] = 0.f; }

        #pragma unroll
        for (int k = 0; k < CS; k += 8) {
            uint32_t a[4];
            a[0] = __float_as_uint(sG[(t0 + lh) * STG + k + lq]);
            a[1] = __float_as_uint(sG[(t0 + lh + 8) * STG + k + lq]);
            a[2] = __float_as_uint(sG[(t0 + lh) * STG + k + 4 + lq]);
            a[3] = __float_as_uint(sG[(t0 + lh + 8) * STG + k + 4 + lq]);
            #pragma unroll
            for (int j = 0; j < 3; j++) {
                uint32_t bfr[2];
                bfr[0] = tf32u(sx[(k + lq) * ST48 + pb + 8 * j + lh]);
                bfr[1] = tf32u(sx[(k + 4 + lq) * ST48 + pb + 8 * j + lh]);
                mma8(accA[j], a, bfr);
            }
        }
        #pragma unroll
        for (int k = 0; k < DS; k += 8) {
            uint32_t a[4];
            a[0] = __float_as_uint(sCt[(k + lq) * ST64 + t0 + lh]);
            a[1] = __float_as_uint(sCt[(k + lq) * ST64 + t0 + lh + 8]);
            a[2] = __float_as_uint(sCt[(k + 4 + lq) * ST64 + t0 + lh]);
            a[3] = __float_as_uint(sCt[(k + 4 + lq) * ST64 + t0 + lh + 8]);
            #pragma unroll
            for (int j = 0; j < 3; j++) {
                uint32_t bfr[2];
                bfr[0] = __float_as_uint(shin[(k + lq) * ST48 + pb + 8 * j + lh]);
                bfr[1] = __float_as_uint(shin[(k + 4 + lq) * ST48 + pb + 8 * j + lh]);
                mma8(accB[j], a, bfr);
            }
        }

        // epilogue: y = intra + exp(cs)*inter + D*x; gate; accumulate ss; store bf16
        float dskip = D_skip[h];
        float et0 = __expf(csh[t0 + lh]);
        float et1 = __expf(csh[t0 + lh + 8]);
        #pragma unroll
        for (int j = 0; j < 3; j++) {
            int p0c = pb + 8 * j + 2 * lq;
            int r0 = t0 + lh, r1 = r0 + 8;
            int dd = h * HD + p0c;
            float y00 = accA[j][0] + et0 * accB[j][0] + dskip * sx[r0 * ST48 + p0c];
            float y01 = accA[j][1] + et0 * accB[j][1] + dskip * sx[r0 * ST48 + p0c + 1];
            float y10 = accA[j][2] + et1 * accB[j][2] + dskip * sx[r1 * ST48 + p0c];
            float y11 = accA[j][3] + et1 * accB[j][3] + dskip * sx[r1 * ST48 + p0c + 1];
            float w0a = sW1z[dd],            w0b = sW1z[dd + 1];
            float w1a = sW1z[DINNER + dd],   w1b = sW1z[DINNER + dd + 1];
            float w2a = sW1z[2*DINNER + dd], w2b = sW1z[2*DINNER + dd + 1];
            float w3a = sW1z[3*DINNER + dd], w3b = sW1z[3*DINNER + dd + 1];
            float mva = smvz[dd], mvb = smvz[dd + 1];
            float za0 = fmaf(xr0[3], w3a, fmaf(xr0[2], w2a, fmaf(xr0[1], w1a, fmaf(xr0[0], w0a, mva))));
            float zb0 = fmaf(xr0[3], w3b, fmaf(xr0[2], w2b, fmaf(xr0[1], w1b, fmaf(xr0[0], w0b, mvb))));
            float za1 = fmaf(xr1[3], w3a, fmaf(xr1[2], w2a, fmaf(xr1[1], w1a, fmaf(xr1[0], w0a, mva))));
            float zb1 = fmaf(xr1[3], w3b, fmaf(xr1[2], w2b, fmaf(xr1[1], w1b, fmaf(xr1[0], w0b, mvb))));
            float g00 = y00 * siluf(za0);
            float g01 = y01 * siluf(zb0);
            float g10 = y10 * siluf(za1);
            float g11 = y11 * siluf(zb1);
            ss0 = fmaf(g00, g00, fmaf(g01, g01, ss0));
            ss1 = fmaf(g10, g10, fmaf(g11, g11, ss1));
            ybase[(size_t)r0 * 192 + (dd >> 1)] = packbf(g00, g01);
            ybase[(size_t)r1 * 192 + (dd >> 1)] = packbf(g10, g11);
        }
    }

    // row sum-of-squares -> rstd   (reuse sCS region)
    __syncthreads();
    ss0 += __shfl_xor_sync(0xffffffffu, ss0, 1);
    ss0 += __shfl_xor_sync(0xffffffffu, ss0, 2);
    ss1 += __shfl_xor_sync(0xffffffffu, ss1, 1);
    ss1 += __shfl_xor_sync(0xffffffffu, ss1, 2);
    if (lq == 0) {
        sCS[(wid >> 2) * 64 + t0 + lh]     = ss0;
        sCS[(wid >> 2) * 64 + t0 + lh + 8] = ss1;
    }
    __syncthreads();
    if (tid < 64) {
        float s = sCS[tid] + sCS[64 + tid];
        g_rstd[(size_t)b * TT + t0c + tid] = rsqrtf(s * (1.f / DINNER) + 1e-5f);
    }
}

// ---------------- kD2: bf16 mma GEMM(W2) + rstd + mix2 + partial ----------
// grid (32, BB) block 256 (8 warps), 128 rows/block
__global__ __launch_bounds__(256) void kD2(const float* __restrict__ b_mix1,
                   const float* __restrict__ w_mix2, const float* __restrict__ b_mix2) {
    __shared__ float sm1[128 * 33];
    __shared__ float swm2[MIXD * MIXD];

    int tid = threadIdx.x;
    int wid = tid >> 5, lane = tid & 31;
    int lq = lane & 3, lh = lane >> 2;
    int b = blockIdx.y;
    int t0 = blockIdx.x * 128;

    for (int i = tid; i < MIXD * MIXD; i += 256) swm2[i] = w_mix2[i];

    // GEMM: warp = 16-row strip; acc over N=32 (4 n8 tiles), K=384
    const uint32_t* arow = g_ybf32 + ((size_t)b * TT + t0 + wid * 16) * 192;
    float acc[4][4];
    #pragma unroll
    for (int j = 0; j < 4; j++)
        #pragma unroll
        for (int e = 0; e < 4; e++) acc[j][e] = 0.f;

    #pragma unroll 4
    for (int k16 = 0; k16 < DINNER; k16 += 16) {
        int kw = k16 >> 1;
        uint32_t a[4];
        a[0] = __ldg(arow + (size_t)lh * 192 + kw + lq);
        a[1] = __ldg(arow + (size_t)(lh + 8) * 192 + kw + lq);
        a[2] = __ldg(arow + (size_t)lh * 192 + kw + 4 + lq);
        a[3] = __ldg(arow + (size_t)(lh + 8) * 192 + kw + 4 + lq);
        #pragma unroll
        for (int j = 0; j < 4; j++) {
            uint32_t bfr[2];
            bfr[0] = __ldg(&g_W2bt32[(8 * j + lh) * 192 + kw + lq]);
            bfr[1] = __ldg(&g_W2bt32[(8 * j + lh) * 192 + kw + 4 + lq]);
            mma16(acc[j], a, bfr);
        }
    }

    // m1 = relu(rstd*acc + b1)
    {
        int r0 = wid * 16 + lh, r1 = r0 + 8;
        float rs0 = g_rstd[(size_t)b * TT + t0 + r0];
        float rs1 = g_rstd[(size_t)b * TT + t0 + r1];
        #pragma unroll
        for (int j = 0; j < 4; j++) {
            int oc = 8 * j + 2 * lq;
            sm1[r0 * 33 + oc]     = fmaxf(fmaf(acc[j][0], rs0, b_mix1[oc]), 0.f);
            sm1[r0 * 33 + oc + 1] = fmaxf(fmaf(acc[j][1], rs0, b_mix1[oc + 1]), 0.f);
            sm1[r1 * 33 + oc]     = fmaxf(fmaf(acc[j][2], rs1, b_mix1[oc]), 0.f);
            sm1[r1 * 33 + oc + 1] = fmaxf(fmaf(acc[j][3], rs1, b_mix1[oc + 1]), 0.f);
        }
    }
    __syncthreads();

    // mix2: thread = (row, 16-output half)
    int r2 = tid >> 1;
    int oh = (tid & 1) * 16;
    float m2[16];
    #pragma unroll
    for (int o = 0; o < 16; o++) m2[o] = b_mix2[oh + o];
    #pragma unroll 4
    for (int i = 0; i < MIXD; i++) {
        float m = sm1[r2 * 33 + i];
        #pragma unroll
        for (int o = 0; o < 16; o++) m2[o] = fmaf(m, swm2[i * MIXD + oh + o], m2[o]);
    }
    #pragma unroll
    for (int o = 0; o < 16; o++) m2[o] = fmaxf(m2[o], 0.f);
    __syncthreads();
    #pragma unroll
    for (int o = 0; o < 16; o++) sm1[r2 * 33 + oh + o] = m2[o];
    __syncthreads();

    // reduce 128 rows
    for (int s = 64; s >= 1; s >>= 1) {
        for (int idx = tid; idx < s * 32; idx += 256) {
            int r = idx >> 5, o = idx & 31;
            sm1[r * 33 + o] += sm1[(r + s) * 33 + o];
        }
        __syncthreads();
    }
    if (tid < MIXD) g_part[((size_t)b * 32 + blockIdx.x) * MIXD + tid] = sm1[tid];
}

// ---------------- kF: final mean + w_out ----------------
__global__ void kF(const float* __restrict__ w_out, const float* __restrict__ b_out,
                   float* __restrict__ out) {
    int b = threadIdx.x;
    if (b < BB) {
        float s = 0.f;
        for (int o = 0; o < MIXD; o++) {
            float a = 0.f;
            for (int blk = 0; blk < 32; blk++) a += g_part[((size_t)b * 32 + blk) * MIXD + o];
            s = fmaf(a * (1.f / (float)TT), w_out[o], s);
        }
        out[b] = s + b_out[0];
    }
}

extern "C" void kernel_launch(void* const* d_in, const int* in_sizes, int n_in,
                              void* d_out, int out_size) {
    const float* x        = (const float*)d_in[0];
    const float* mic_pos  = (const float*)d_in[1];
    const float* w_in     = (const float*)d_in[2];
    const float* b_in     = (const float*)d_in[3];
    const float* w_mic    = (const float*)d_in[4];
    const float* b_mic    = (const float*)d_in[5];
    const float* w_inproj = (const float*)d_in[6];
    const float* conv_w   = (const float*)d_in[7];
    const float* conv_b   = (const float*)d_in[8];
    const float* dt_bias  = (const float*)d_in[9];
    const float* A_log    = (const float*)d_in[10];
    const float* D_skip   = (const float*)d_in[11];
    const float* norm_w   = (const float*)d_in[12];
    const float* w_outproj= (const float*)d_in[13];
    const float* w_mix1   = (const float*)d_in[14];
    const float* b_mix1   = (const float*)d_in[15];
    const float* w_mix2   = (const float*)d_in[16];
    const float* b_mix2   = (const float*)d_in[17];
    const float* w_out    = (const float*)d_in[18];
    const float* b_out    = (const float*)d_in[19];
    float* out = (float*)d_out;

    cudaFuncSetAttribute(kC, cudaFuncAttributeMaxDynamicSharedMemorySize, KC_SMEM_FLOATS * 4);

    k0a<<<1, 256>>>(mic_pos, w_mic, b_mic, b_in, A_log);
    k0b<<<(4 * DPROJ + BB * DPROJ + 32 * 192 + 255) / 256, 256>>>(w_in, w_inproj, w_outproj, w_mix1, norm_w);
    k1<<<dim3(32, 16), 128>>>(x, conv_w, conv_b, dt_bias);
    kA<<<dim3(NC, 128), 192>>>();
    kB<<<dim3(128, 2), 384>>>();
    kC<<<dim3(NC, BB), 256, KC_SMEM_FLOATS * 4>>>(D_skip, x);
    kD2<<<dim3(32, BB), 256>>>(b_mix1, w_mix2, b_mix2);
    kF<<<1, 32>>>(w_out, b_out, out);
}

// round 9
// speedup vs baseline: 3.4551x; 1.2332x over previous
#include <cuda_runtime.h>
#include <cuda_bf16.h>
#include <math.h>
#include <stdint.h>

#define BB 16
#define TT 4096
#define DINNER 384
#define NH 8
#define HD 48
#define DS 64
#define DPROJ 904
#define NC 64
#define CS 64
#define MIXD 32

// ---------------- scratch (static device arrays; no runtime alloc) ----------
__device__ float g_W1[4 * DPROJ];            // w_in @ w_inproj
__device__ float g_mvec[BB * DPROJ];         // (b_in + relu(mic)) @ w_inproj
__device__ uint32_t g_W2bt32[32 * 192];      // bf16x2 [o][dpair]
__device__ float g_hb[BB * 192];
__device__ float g_A[NH];
__device__ uint32_t g_xbf[(size_t)BB * TT * 192];  // silu(conv) xs, bf16x2 pairs along p
__device__ float g_bc[(size_t)BB * TT * 128];      // B(64) | C(64) fp32
__device__ float g_dt[(size_t)BB * TT * NH];
__device__ float g_la[(size_t)BB * TT * NH];       // log-decay = dt*A
__device__ uint32_t g_Sbf[(size_t)128 * NC * HD * 32]; // chunk states bf16x2 (pairs along n) -> h_in in place
__device__ float g_Dc[128 * NC];
__device__ uint32_t g_ybf32[(size_t)BB * TT * 192];    // gated y, bf16x2
__device__ float g_rstd[BB * TT];
__device__ float g_part[2048 * MIXD];

__device__ __forceinline__ float siluf(float v) {
    if (fabsf(v) < 0.25f) {
        float z2 = v * v;
        float sig = 0.5f + v * (0.25f + z2 * (-(1.f / 48.f) + z2 * (1.f / 480.f)));
        return v * sig;
    }
    return __fdividef(v, 1.f + __expf(-v));
}
__device__ __forceinline__ float softplusf(float v) { return v > 20.f ? v : __logf(1.f + __expf(v)); }

__device__ __forceinline__ uint32_t tf32u(float x) {
    uint32_t r;
    asm("cvt.rna.tf32.f32 %0, %1;" : "=r"(r) : "f"(x));
    return r;
}
__device__ __forceinline__ float tf32f(float x) { return __uint_as_float(tf32u(x)); }

__device__ __forceinline__ uint32_t packbf(float lo, float hi) {
    uint32_t w;
    asm("cvt.rn.bf16x2.f32 %0, %1, %2;" : "=r"(w) : "f"(hi), "f"(lo));
    return w;
}
__device__ __forceinline__ float2 unpackbf(uint32_t w) {
    return make_float2(__uint_as_float(w << 16), __uint_as_float(w & 0xffff0000u));
}

__device__ __forceinline__ void mma8(float d[4], const uint32_t a[4], const uint32_t b[2]) {
    asm volatile(
        "mma.sync.aligned.m16n8k8.row.col.f32.tf32.tf32.f32 "
        "{%0,%1,%2,%3},{%4,%5,%6,%7},{%8,%9},{%0,%1,%2,%3};\n"
        : "+f"(d[0]), "+f"(d[1]), "+f"(d[2]), "+f"(d[3])
        : "r"(a[0]), "r"(a[1]), "r"(a[2]), "r"(a[3]),
          "r"(b[0]), "r"(b[1]));
}

__device__ __forceinline__ void mma16(float d[4], const uint32_t a[4], const uint32_t b[2]) {
    asm volatile(
        "mma.sync.aligned.m16n8k16.row.col.f32.bf16.bf16.f32 "
        "{%0,%1,%2,%3},{%4,%5,%6,%7},{%8,%9},{%0,%1,%2,%3};\n"
        : "+f"(d[0]), "+f"(d[1]), "+f"(d[2]), "+f"(d[3])
        : "r"(a[0]), "r"(a[1]), "r"(a[2]), "r"(a[3]),
          "r"(b[0]), "r"(b[1]));
}

// ---------------- k0a: mic MLP + A ----------------
__global__ void k0a(const float* __restrict__ mic_pos, const float* __restrict__ w_mic,
                    const float* __restrict__ b_mic, const float* __restrict__ b_in,
                    const float* __restrict__ A_log) {
    int tid = threadIdx.x;
    for (int i = tid; i < BB * 192; i += 256) {
        int b = i / 192, d = i % 192;
        float s = b_mic[d];
        #pragma unroll
        for (int j = 0; j < 12; j++) s = fmaf(mic_pos[b * 12 + j], w_mic[j * 192 + d], s);
        g_hb[i] = b_in[d] + fmaxf(s, 0.f);
    }
    if (tid < NH) g_A[tid] = -expf(A_log[tid]);
}

// ---------------- k0b: folded weights ----------------
__global__ void k0b(const float* __restrict__ w_in, const float* __restrict__ w_inproj,
                    const float* __restrict__ w_outproj, const float* __restrict__ w_mix1,
                    const float* __restrict__ norm_w) {
    int i = blockIdx.x * 256 + threadIdx.x;
    if (i < 4 * DPROJ) {
        int j = i / DPROJ, d = i % DPROJ;
        float s = 0.f;
        for (int m = 0; m < 192; m++) s = fmaf(w_in[j * 192 + m], w_inproj[m * DPROJ + d], s);
        g_W1[i] = s;
    } else if (i < 4 * DPROJ + BB * DPROJ) {
        int ii = i - 4 * DPROJ;
        int b = ii / DPROJ, d = ii % DPROJ;
        float s = 0.f;
        for (int m = 0; m < 192; m++) s = fmaf(g_hb[b * 192 + m], w_inproj[m * DPROJ + d], s);
        g_mvec[ii] = s;
    } else if (i < 4 * DPROJ + BB * DPROJ + 32 * 192) {
        int ii = i - (4 * DPROJ + BB * DPROJ);
        int o = ii / 192, kw = ii % 192;
        int d0 = 2 * kw, d1 = d0 + 1;
        float s0 = 0.f, s1 = 0.f;
        for (int m = 0; m < 192; m++) {
            s0 = fmaf(w_outproj[d0 * 192 + m], w_mix1[m * MIXD + o], s0);
            s1 = fmaf(w_outproj[d1 * 192 + m], w_mix1[m * MIXD + o], s1);
        }
        g_W2bt32[o * 192 + kw] = packbf(s0 * norm_w[d0], s1 * norm_w[d1]);
    }
}

// ---------------- k1: fused inproj + conv4 + silu + dt/la ----------------
// grid (32, 16) block 128 : thread = one t
__global__ void k1(const float* __restrict__ x, const float* __restrict__ conv_w,
                   const float* __restrict__ conv_b, const float* __restrict__ dt_bias) {
    __shared__ float sW1[4 * 520];   // proj dims 384..903
    __shared__ float smv[520];
    __shared__ float scw[512 * 4];
    __shared__ float scb[512];
    __shared__ float sx4[131 * 4];
    __shared__ float sraw[131 * 33];

    int tid = threadIdx.x;
    int b = blockIdx.y;
    int t0 = blockIdx.x * 128;

    for (int i = tid; i < 4 * 520; i += 128) sW1[i] = g_W1[(i / 520) * DPROJ + 384 + (i % 520)];
    for (int i = tid; i < 520; i += 128) smv[i] = g_mvec[b * DPROJ + 384 + i];
    for (int i = tid; i < 512 * 4; i += 128) scw[i] = conv_w[i];
    for (int i = tid; i < 512; i += 128) scb[i] = conv_b[i];
    for (int i = tid; i < 131 * 4; i += 128) {
        int r = i >> 2, j = i & 3;
        int t = t0 + r - 3;
        sx4[i] = (t >= 0) ? x[((size_t)b * TT + t) * 4 + j] : 0.f;
    }

    int t = t0 + tid;
    for (int c16 = 0; c16 < 16; c16++) {
        __syncthreads();
        for (int i = tid; i < 131 * 32; i += 128) {
            int r = i >> 5, dc = i & 31;
            int dd = c16 * 32 + dc;
            float v = 0.f;
            if (t0 + r - 3 >= 0) {
                v = smv[dd];
                #pragma unroll
                for (int j = 0; j < 4; j++) v = fmaf(sx4[r * 4 + j], sW1[j * 520 + dd], v);
            }
            sraw[r * 33 + dc] = v;
        }
        __syncthreads();
        float v[32];
        #pragma unroll
        for (int dc = 0; dc < 32; dc++) {
            int dd = c16 * 32 + dc;
            float a = scb[dd];
            #pragma unroll
            for (int k = 0; k < 4; k++) a = fmaf(sraw[(tid + k) * 33 + dc], scw[dd * 4 + k], a);
            v[dc] = siluf(a);
        }
        if (c16 < 12) {
            uint32_t* dst = g_xbf + ((size_t)b * TT + t) * 192 + c16 * 16;
            #pragma unroll
            for (int q = 0; q < 4; q++) {
                uint4 w;
                w.x = packbf(v[8 * q + 0], v[8 * q + 1]);
                w.y = packbf(v[8 * q + 2], v[8 * q + 3]);
                w.z = packbf(v[8 * q + 4], v[8 * q + 5]);
                w.w = packbf(v[8 * q + 6], v[8 * q + 7]);
                ((uint4*)dst)[q] = w;
            }
        } else {
            float* dst = g_bc + ((size_t)b * TT + t) * 128 + (c16 - 12) * 32;
            #pragma unroll
            for (int q = 0; q < 8; q++)
                ((float4*)dst)[q] = make_float4(v[4 * q], v[4 * q + 1], v[4 * q + 2], v[4 * q + 3]);
        }
    }

    // dt path (proj dims 896..903 via sW1 dims 512..519)
    #pragma unroll
    for (int hh = 0; hh < NH; hh++) {
        int dd = 512 + hh;
        float v = smv[dd];
        #pragma unroll
        for (int j = 0; j < 4; j++) v = fmaf(sx4[(tid + 3) * 4 + j], sW1[j * 520 + dd], v);
        float dt = softplusf(v + dt_bias[hh]);
        size_t o = ((size_t)b * TT + t) * NH + hh;
        g_dt[o] = dt;
        g_la[o] = dt * g_A[hh];
    }
}

// ---------------- kA: chunk-local end states via tf32 mma ----------------
// grid (NC, 128) block 192 (6 warps): warp = (p-strip w%3, n-half w/3)
__global__ __launch_bounds__(192) void kA() {
    __shared__ float sxw[CS * 56];   // [t][p] = w(t)*x(t,p), tf32
    __shared__ float sB[CS * 72];    // [t][n], tf32
    __shared__ float scs[CS];
    __shared__ float sdt[CS];

    int c = blockIdx.x, bh = blockIdx.y;
    int b = bh >> 3, h = bh & 7;
    int tid = threadIdx.x;
    int wid = tid >> 5, lane = tid & 31;
    int lq = lane & 3, lh = lane >> 2;
    int t0 = c * CS;

    if (tid < CS) {
        size_t o = ((size_t)b * TT + t0 + tid) * NH + h;
        scs[tid] = g_la[o];
        sdt[tid] = g_dt[o];
    }
    const float* bp = g_bc + ((size_t)b * TT + t0) * 128;
    for (int i = tid; i < CS * 16; i += 192) {
        int r = i >> 4, col = i & 15;
        float4 v = ((const float4*)(bp + (size_t)r * 128))[col];
        *(float4*)&sB[r * 72 + col * 4] =
            make_float4(tf32f(v.x), tf32f(v.y), tf32f(v.z), tf32f(v.w));
    }
    __syncthreads();

    if (wid == 0) {
        float a0 = scs[2 * lane], a1 = scs[2 * lane + 1];
        float ps = a0 + a1;
        #pragma unroll
        for (int off = 1; off < 32; off <<= 1) {
            float v = __shfl_up_sync(0xffffffffu, ps, off);
            if (lane >= off) ps += v;
        }
        scs[2 * lane + 1] = ps;
        scs[2 * lane]     = ps - a1;
    }
    __syncthreads();

    float cstot = scs[CS - 1];
    const uint32_t* xp = g_xbf + ((size_t)b * TT + t0) * 192 + h * 24;
    for (int i = tid; i < CS * 6; i += 192) {
        int r = i / 6, col = i % 6;
        float wgt = __expf(cstot - scs[r]) * sdt[r];
        uint4 w4 = ((const uint4*)(xp + (size_t)r * 192))[col];
        float2 q0 = unpackbf(w4.x), q1 = unpackbf(w4.y), q2 = unpackbf(w4.z), q3 = unpackbf(w4.w);
        *(float4*)&sxw[r * 56 + col * 8] =
            make_float4(tf32f(q0.x * wgt), tf32f(q0.y * wgt), tf32f(q1.x * wgt), tf32f(q1.y * wgt));
        *(float4*)&sxw[r * 56 + col * 8 + 4] =
            make_float4(tf32f(q2.x * wgt), tf32f(q2.y * wgt), tf32f(q3.x * wgt), tf32f(q3.y * wgt));
    }
    __syncthreads();

    int p0 = (wid % 3) * 16;
    int nb = (wid / 3) * 32;
    float acc[4][4];
    #pragma unroll
    for (int j = 0; j < 4; j++)
        #pragma unroll
        for (int e = 0; e < 4; e++) acc[j][e] = 0.f;

    #pragma unroll
    for (int k = 0; k < CS; k += 8) {
        uint32_t a[4];
        a[0] = __float_as_uint(sxw[(k + lq) * 56 + p0 + lh]);
        a[1] = __float_as_uint(sxw[(k + lq) * 56 + p0 + lh + 8]);
        a[2] = __float_as_uint(sxw[(k + 4 + lq) * 56 + p0 + lh]);
        a[3] = __float_as_uint(sxw[(k + 4 + lq) * 56 + p0 + lh + 8]);
        #pragma unroll
        for (int j = 0; j < 4; j++) {
            uint32_t bfr[2];
            bfr[0] = __float_as_uint(sB[(k + lq) * 72 + nb + 8 * j + lh]);
            bfr[1] = __float_as_uint(sB[(k + 4 + lq) * 72 + nb + 8 * j + lh]);
            mma8(acc[j], a, bfr);
        }
    }

    uint32_t* sp = g_Sbf + ((size_t)bh * NC + c) * 1536;
    #pragma unroll
    for (int j = 0; j < 4; j++) {
        int n0 = nb + 8 * j + 2 * lq;
        sp[(p0 + lh) * 32 + (n0 >> 1)]     = packbf(acc[j][0], acc[j][1]);
        sp[(p0 + lh + 8) * 32 + (n0 >> 1)] = packbf(acc[j][2], acc[j][3]);
    }
    if (tid == 0) g_Dc[bh * NC + c] = __expf(cstot);
}

// ---------------- kB: inter-chunk scan (fp32 regs, bf16 storage) ----------
// grid (128, 2) block 384 : thread owns 4 states (2 words)
__global__ void kB() {
    int bh = blockIdx.x, half = blockIdx.y;
    int tid = threadIdx.x;
    float h0 = 0.f, h1 = 0.f, h2 = 0.f, h3 = 0.f;
    size_t base = (size_t)bh * NC * 1536 + (size_t)half * 768 + tid * 2;
    uint2 a = *(uint2*)(g_Sbf + base);
    float Dc = g_Dc[bh * NC];
    for (int c = 0; c < NC; c++) {
        uint32_t* sp = g_Sbf + base + (size_t)c * 1536;
        uint2 an = make_uint2(0u, 0u);
        float Dn = 0.f;
        if (c + 1 < NC) {
            an = *(uint2*)(sp + 1536);
            Dn = g_Dc[bh * NC + c + 1];
        }
        float2 p0 = unpackbf(a.x), p1 = unpackbf(a.y);
        *(uint2*)sp = make_uint2(packbf(h0, h1), packbf(h2, h3));
        h0 = fmaf(h0, Dc, p0.x); h1 = fmaf(h1, Dc, p0.y);
        h2 = fmaf(h2, Dc, p1.x); h3 = fmaf(h3, Dc, p1.y);
        a = an; Dc = Dn;
    }
}

// ---------------- kC: chunked SSD + fused gating/RMS-stats ----------------
// grid (NC, BB) block 256 (8 warps)
#define ST64 72
#define STG 68
#define ST48 56
#define KC_BT   0                        // [n][s] tf32, 64*72
#define KC_CT   (KC_BT + 64 * ST64)      // [n][t] tf32
#define KC_G    (KC_CT + 64 * ST64)      // [t][s] tf32 (per head), stride 68
#define KC_SX   (KC_G + 64 * STG)        // [s][p] fp32, 64*56
#define KC_SHIN (KC_SX + 64 * ST48)      // [n][p] fp32, 64*56
#define KC_SCS  (KC_SHIN + 64 * ST48)    // 8*64 (reused as ss buffer at end)
#define KC_SDT  (KC_SCS + 512)           // 8*64
#define KC_W1Z  (KC_SDT + 512)           // 4*384
#define KC_MVZ  (KC_W1Z + 1536)          // 384
#define KC_X4   (KC_MVZ + 384)           // 64*4
#define KC_SMEM_FLOATS (KC_X4 + 256)

__global__ __launch_bounds__(256) void kC(const float* __restrict__ D_skip,
                                          const float* __restrict__ xin) {
    extern __shared__ float sm[];
    float* sBt  = sm + KC_BT;
    float* sCt  = sm + KC_CT;
    float* sG   = sm + KC_G;
    float* sx   = sm + KC_SX;
    float* shin = sm + KC_SHIN;
    float* sCS  = sm + KC_SCS;
    float* sDT  = sm + KC_SDT;
    float* sW1z = sm + KC_W1Z;
    float* smvz = sm + KC_MVZ;
    float* sx4  = sm + KC_X4;

    int c = blockIdx.x, b = blockIdx.y;
    int tid = threadIdx.x;
    int wid = tid >> 5, lane = tid & 31;
    int lq = lane & 3, lh = lane >> 2;
    int t0c = c * CS;

    if (tid < 128) {
        const float* lap = g_la + ((size_t)b * TT + t0c) * NH;
        const float* dtp = g_dt + ((size_t)b * TT + t0c) * NH;
        float4 v = ((const float4*)lap)[tid];
        float4 w = ((const float4*)dtp)[tid];
        int j0 = tid * 4;
        #pragma unroll
        for (int u = 0; u < 4; u++) {
            int j = j0 + u;
            int t = j >> 3, h = j & 7;
            sCS[h * 64 + t] = (&v.x)[u];
            sDT[h * 64 + t] = (&w.x)[u];
        }
    }
    for (int i = tid; i < 4 * DINNER; i += 256) sW1z[i] = g_W1[(i / DINNER) * DPROJ + (i % DINNER)];
    for (int i = tid; i < DINNER; i += 256) smvz[i] = g_mvec[b * DPROJ + i];
    if (tid < 256) {
        int r = tid >> 2, j = tid & 3;
        sx4[tid] = xin[((size_t)b * TT + t0c + r) * 4 + j];
    }

    const float* bp = g_bc + ((size_t)b * TT + t0c) * 128;
    for (int i = tid; i < CS * 16; i += 256) {
        int s = i >> 4, nq = i & 15;
        float4 v = ((const float4*)(bp + (size_t)s * 128))[nq];          // B[s][n]
        sBt[(nq * 4 + 0) * ST64 + s] = tf32f(v.x);
        sBt[(nq * 4 + 1) * ST64 + s] = tf32f(v.y);
        sBt[(nq * 4 + 2) * ST64 + s] = tf32f(v.z);
        sBt[(nq * 4 + 3) * ST64 + s] = tf32f(v.w);
        float4 w = ((const float4*)(bp + (size_t)s * 128))[nq + 16];     // C[s][n]
        sCt[(nq * 4 + 0) * ST64 + s] = tf32f(w.x);
        sCt[(nq * 4 + 1) * ST64 + s] = tf32f(w.y);
        sCt[(nq * 4 + 2) * ST64 + s] = tf32f(w.z);
        sCt[(nq * 4 + 3) * ST64 + s] = tf32f(w.w);
    }
    __syncthreads();

    // per-head inclusive log-decay prefix (warp w = head w)
    {
        float a0 = sCS[wid * 64 + 2 * lane];
        float a1 = sCS[wid * 64 + 2 * lane + 1];
        float ps = a0 + a1;
        #pragma unroll
        for (int off = 1; off < 32; off <<= 1) {
            float v = __shfl_up_sync(0xffffffffu, ps, off);
            if (lane >= off) ps += v;
        }
        sCS[wid * 64 + 2 * lane + 1] = ps;
        sCS[wid * 64 + 2 * lane]     = ps - a1;
    }

    int t0 = (wid & 3) * 16;
    int sb = (wid >> 2) * 32;
    int pb = (wid >> 2) * 24;

    float xr0[4], xr1[4];
    #pragma unroll
    for (int u = 0; u < 4; u++) {
        xr0[u] = sx4[(t0 + lh) * 4 + u];
        xr1[u] = sx4[(t0 + lh + 8) * 4 + u];
    }

    // GEMM1 (shared across heads): Graw[t][s] = sum_n C[t][n]*B[s][n]
    float g1[4][4];
    #pragma unroll
    for (int j = 0; j < 4; j++)
        #pragma unroll
        for (int e = 0; e < 4; e++) g1[j][e] = 0.f;

    #pragma unroll
    for (int k = 0; k < DS; k += 8) {
        uint32_t a[4];
        a[0] = __float_as_uint(sCt[(k + lq) * ST64 + t0 + lh]);
        a[1] = __float_as_uint(sCt[(k + lq) * ST64 + t0 + lh + 8]);
        a[2] = __float_as_uint(sCt[(k + 4 + lq) * ST64 + t0 + lh]);
        a[3] = __float_as_uint(sCt[(k + 4 + lq) * ST64 + t0 + lh + 8]);
        #pragma unroll
        for (int j = 0; j < 4; j++) {
            uint32_t bfr[2];
            bfr[0] = __float_as_uint(sBt[(k + lq) * ST64 + sb + 8 * j + lh]);
            bfr[1] = __float_as_uint(sBt[(k + 4 + lq) * ST64 + sb + 8 * j + lh]);
            mma8(g1[j], a, bfr);
        }
    }

    float ss0 = 0.f, ss1 = 0.f;
    uint32_t* ybase = g_ybf32 + ((size_t)b * TT + t0c) * 192;

    for (int h = 0; h < NH; h++) {
        __syncthreads();

        const uint32_t* xp = g_xbf + ((size_t)b * TT + t0c) * 192 + h * 24;
        for (int i = tid; i < CS * 6; i += 256) {
            int s = i / 6, col = i % 6;
            uint4 w4 = ((const uint4*)(xp + (size_t)s * 192))[col];
            float2 q0 = unpackbf(w4.x), q1 = unpackbf(w4.y), q2 = unpackbf(w4.z), q3 = unpackbf(w4.w);
            *(float4*)&sx[s * ST48 + col * 8]     = make_float4(q0.x, q0.y, q1.x, q1.y);
            *(float4*)&sx[s * ST48 + col * 8 + 4] = make_float4(q2.x, q2.y, q3.x, q3.y);
        }
        const uint32_t* hp = g_Sbf + ((size_t)(b * NH + h) * NC + c) * 1536;
        for (int i = tid; i < HD * 8; i += 256) {
            int p = i >> 3, nw = i & 7;
            uint4 w4 = ((const uint4*)(hp + p * 32))[nw];
            float2 q0 = unpackbf(w4.x), q1 = unpackbf(w4.y), q2 = unpackbf(w4.z), q3 = unpackbf(w4.w);
            int n0 = nw * 8;
            shin[(n0 + 0) * ST48 + p] = q0.x;
            shin[(n0 + 1) * ST48 + p] = q0.y;
            shin[(n0 + 2) * ST48 + p] = q1.x;
            shin[(n0 + 3) * ST48 + p] = q1.y;
            shin[(n0 + 4) * ST48 + p] = q2.x;
            shin[(n0 + 5) * ST48 + p] = q2.y;
            shin[(n0 + 6) * ST48 + p] = q3.x;
            shin[(n0 + 7) * ST48 + p] = q3.y;
        }

        const float* csh = sCS + h * 64;
        const float* dth = sDT + h * 64;
        {
            float cs_r0 = csh[t0 + lh], cs_r1 = csh[t0 + lh + 8];
            #pragma unroll
            for (int j = 0; j < 4; j++) {
                int c0 = sb + 8 * j + 2 * lq;
                float cs_c0 = csh[c0], cs_c1 = csh[c0 + 1];
                float dt_c0 = dth[c0], dt_c1 = dth[c0 + 1];
                int r0 = t0 + lh, r1 = r0 + 8;
                float m00 = (c0 <= r0) ? __expf(cs_r0 - cs_c0) * dt_c0 : 0.f;
                float m01 = (c0 + 1 <= r0) ? __expf(cs_r0 - cs_c1) * dt_c1 : 0.f;
                float m10 = (c0 <= r1) ? __expf(cs_r1 - cs_c0) * dt_c0 : 0.f;
                float m11 = (c0 + 1 <= r1) ? __expf(cs_r1 - cs_c1) * dt_c1 : 0.f;
                sG[r0 * STG + c0]     = tf32f(g1[j][0] * m00);
                sG[r0 * STG + c0 + 1] = tf32f(g1[j][1] * m01);
                sG[r1 * STG + c0]     = tf32f(g1[j][2] * m10);
                sG[r1 * STG + c0 + 1] = tf32f(g1[j][3] * m11);
            }
        }
        __syncthreads();

        float accA[3][4], accB[3][4];
        #pragma unroll
        for (int j = 0; j < 3; j++)
            #pragma unroll
            for (int e = 0; e < 4; e++) { accA[j][e] = 0.f; accB[j][e] = 0.f; }

        #pragma unroll
        for (int k = 0; k < CS; k += 8) {
            uint32_t a[4];
            a[0] = __float_as_uint(sG[(t0 + lh) * STG + k + lq]);
            a[1] = __float_as_uint(sG[(t0 + lh + 8) * STG + k + lq]);
            a[2] = __float_as_uint(sG[(t0 + lh) * STG + k + 4 + lq]);
            a[3] = __float_as_uint(sG[(t0 + lh + 8) * STG + k + 4 + lq]);
            #pragma unroll
            for (int j = 0; j < 3; j++) {
                uint32_t bfr[2];
                bfr[0] = tf32u(sx[(k + lq) * ST48 + pb + 8 * j + lh]);
                bfr[1] = tf32u(sx[(k + 4 + lq) * ST48 + pb + 8 * j + lh]);
                mma8(accA[j], a, bfr);
            }
        }
        #pragma unroll
        for (int k = 0; k < DS; k += 8) {
            uint32_t a[4];
            a[0] = __float_as_uint(sCt[(k + lq) * ST64 + t0 + lh]);
            a[1] = __float_as_uint(sCt[(k + lq) * ST64 + t0 + lh + 8]);
            a[2] = __float_as_uint(sCt[(k + 4 + lq) * ST64 + t0 + lh]);
            a[3] = __float_as_uint(sCt[(k + 4 + lq) * ST64 + t0 + lh + 8]);
            #pragma unroll
            for (int j = 0; j < 3; j++) {
                uint32_t bfr[2];
                bfr[0] = __float_as_uint(shin[(k + lq) * ST48 + pb + 8 * j + lh]);
                bfr[1] = __float_as_uint(shin[(k + 4 + lq) * ST48 + pb + 8 * j + lh]);
                mma8(accB[j], a, bfr);
            }
        }

        // epilogue: y = intra + exp(cs)*inter + D*x; gate; accumulate ss; store bf16
        float dskip = D_skip[h];
        float et0 = __expf(csh[t0 + lh]);
        float et1 = __expf(csh[t0 + lh + 8]);
        #pragma unroll
        for (int j = 0; j < 3; j++) {
            int p0c = pb + 8 * j + 2 * lq;
            int r0 = t0 + lh, r1 = r0 + 8;
            int dd = h * HD + p0c;
            float y00 = accA[j][0] + et0 * accB[j][0] + dskip * sx[r0 * ST48 + p0c];
            float y01 = accA[j][1] + et0 * accB[j][1] + dskip * sx[r0 * ST48 + p0c + 1];
            float y10 = accA[j][2] + et1 * accB[j][2] + dskip * sx[r1 * ST48 + p0c];
            float y11 = accA[j][3] + et1 * accB[j][3] + dskip * sx[r1 * ST48 + p0c + 1];
            float w0a = sW1z[dd],            w0b = sW1z[dd + 1];
            float w1a = sW1z[DINNER + dd],   w1b = sW1z[DINNER + dd + 1];
            float w2a = sW1z[2*DINNER + dd], w2b = sW1z[2*DINNER + dd + 1];
            float w3a = sW1z[3*DINNER + dd], w3b = sW1z[3*DINNER + dd + 1];
            float mva = smvz[dd], mvb = smvz[dd + 1];
            float za0 = fmaf(xr0[3], w3a, fmaf(xr0[2], w2a, fmaf(xr0[1], w1a, fmaf(xr0[0], w0a, mva))));
            float zb0 = fmaf(xr0[3], w3b, fmaf(xr0[2], w2b, fmaf(xr0[1], w1b, fmaf(xr0[0], w0b, mvb))));
            float za1 = fmaf(xr1[3], w3a, fmaf(xr1[2], w2a, fmaf(xr1[1], w1a, fmaf(xr1[0], w0a, mva))));
            float zb1 = fmaf(xr1[3], w3b, fmaf(xr1[2], w2b, fmaf(xr1[1], w1b, fmaf(xr1[0], w0b, mvb))));
            float g00 = y00 * siluf(za0);
            float g01 = y01 * siluf(zb0);
            float g10 = y10 * siluf(za1);
            float g11 = y11 * siluf(zb1);
            ss0 = fmaf(g00, g00, fmaf(g01, g01, ss0));
            ss1 = fmaf(g10, g10, fmaf(g11, g11, ss1));
            ybase[(size_t)r0 * 192 + (dd >> 1)] = packbf(g00, g01);
            ybase[(size_t)r1 * 192 + (dd >> 1)] = packbf(g10, g11);
        }
    }

    // row sum-of-squares -> rstd   (reuse sCS region)
    __syncthreads();
    ss0 += __shfl_xor_sync(0xffffffffu, ss0, 1);
    ss0 += __shfl_xor_sync(0xffffffffu, ss0, 2);
    ss1 += __shfl_xor_sync(0xffffffffu, ss1, 1);
    ss1 += __shfl_xor_sync(0xffffffffu, ss1, 2);
    if (lq == 0) {
        sCS[(wid >> 2) * 64 + t0 + lh]     = ss0;
        sCS[(wid >> 2) * 64 + t0 + lh + 8] = ss1;
    }
    __syncthreads();
    if (tid < 64) {
        float s = sCS[tid] + sCS[64 + tid];
        g_rstd[(size_t)b * TT + t0c + tid] = rsqrtf(s * (1.f / DINNER) + 1e-5f);
    }
}

// ---------------- kD2: bf16 mma GEMM(W2) + rstd + mix2 + partial ----------
// grid (32, BB) block 256 (8 warps), 128 rows/block
__global__ __launch_bounds__(256) void kD2(const float* __restrict__ b_mix1,
                   const float* __restrict__ w_mix2, const float* __restrict__ b_mix2) {
    __shared__ float sm1[128 * 33];
    __shared__ float swm2[MIXD * MIXD];

    int tid = threadIdx.x;
    int wid = tid >> 5, lane = tid & 31;
    int lq = lane & 3, lh = lane >> 2;
    int b = blockIdx.y;
    int t0 = blockIdx.x * 128;

    for (int i = tid; i < MIXD * MIXD; i += 256) swm2[i] = w_mix2[i];

    const uint32_t* arow = g_ybf32 + ((size_t)b * TT + t0 + wid * 16) * 192;
    float acc[4][4];
    #pragma unroll
    for (int j = 0; j < 4; j++)
        #pragma unroll
        for (int e = 0; e < 4; e++) acc[j][e] = 0.f;

    #pragma unroll 4
    for (int k16 = 0; k16 < DINNER; k16 += 16) {
        int kw = k16 >> 1;
        uint32_t a[4];
        a[0] = __ldg(arow + (size_t)lh * 192 + kw + lq);
        a[1] = __ldg(arow + (size_t)(lh + 8) * 192 + kw + lq);
        a[2] = __ldg(arow + (size_t)lh * 192 + kw + 4 + lq);
        a[3] = __ldg(arow + (size_t)(lh + 8) * 192 + kw + 4 + lq);
        #pragma unroll
        for (int j = 0; j < 4; j++) {
            uint32_t bfr[2];
            bfr[0] = __ldg(&g_W2bt32[(8 * j + lh) * 192 + kw + lq]);
            bfr[1] = __ldg(&g_W2bt32[(8 * j + lh) * 192 + kw + 4 + lq]);
            mma16(acc[j], a, bfr);
        }
    }

    {
        int r0 = wid * 16 + lh, r1 = r0 + 8;
        float rs0 = g_rstd[(size_t)b * TT + t0 + r0];
        float rs1 = g_rstd[(size_t)b * TT + t0 + r1];
        #pragma unroll
        for (int j = 0; j < 4; j++) {
            int oc = 8 * j + 2 * lq;
            sm1[r0 * 33 + oc]     = fmaxf(fmaf(acc[j][0], rs0, b_mix1[oc]), 0.f);
            sm1[r0 * 33 + oc + 1] = fmaxf(fmaf(acc[j][1], rs0, b_mix1[oc + 1]), 0.f);
            sm1[r1 * 33 + oc]     = fmaxf(fmaf(acc[j][2], rs1, b_mix1[oc]), 0.f);
            sm1[r1 * 33 + oc + 1] = fmaxf(fmaf(acc[j][3], rs1, b_mix1[oc + 1]), 0.f);
        }
    }
    __syncthreads();

    int r2 = tid >> 1;
    int oh = (tid & 1) * 16;
    float m2[16];
    #pragma unroll
    for (int o = 0; o < 16; o++) m2[o] = b_mix2[oh + o];
    #pragma unroll 4
    for (int i = 0; i < MIXD; i++) {
        float m = sm1[r2 * 33 + i];
        #pragma unroll
        for (int o = 0; o < 16; o++) m2[o] = fmaf(m, swm2[i * MIXD + oh + o], m2[o]);
    }
    #pragma unroll
    for (int o = 0; o < 16; o++) m2[o] = fmaxf(m2[o], 0.f);
    __syncthreads();
    #pragma unroll
    for (int o = 0; o < 16; o++) sm1[r2 * 33 + oh + o] = m2[o];
    __syncthreads();

    for (int s = 64; s >= 1; s >>= 1) {
        for (int idx = tid; idx < s * 32; idx += 256) {
            int r = idx >> 5, o = idx & 31;
            sm1[r * 33 + o] += sm1[(r + s) * 33 + o];
        }
        __syncthreads();
    }
    if (tid < MIXD) g_part[((size_t)b * 32 + blockIdx.x) * MIXD + tid] = sm1[tid];
}

// ---------------- kF: final mean + w_out ----------------
__global__ void kF(const float* __restrict__ w_out, const float* __restrict__ b_out,
                   float* __restrict__ out) {
    int b = threadIdx.x;
    if (b < BB) {
        float s = 0.f;
        for (int o = 0; o < MIXD; o++) {
            float a = 0.f;
            for (int blk = 0; blk < 32; blk++) a += g_part[((size_t)b * 32 + blk) * MIXD + o];
            s = fmaf(a * (1.f / (float)TT), w_out[o], s);
        }
        out[b] = s + b_out[0];
    }
}

extern "C" void kernel_launch(void* const* d_in, const int* in_sizes, int n_in,
                              void* d_out, int out_size) {
    const float* x        = (const float*)d_in[0];
    const float* mic_pos  = (const float*)d_in[1];
    const float* w_in     = (const float*)d_in[2];
    const float* b_in     = (const float*)d_in[3];
    const float* w_mic    = (const float*)d_in[4];
    const float* b_mic    = (const float*)d_in[5];
    const float* w_inproj = (const float*)d_in[6];
    const float* conv_w   = (const float*)d_in[7];
    const float* conv_b   = (const float*)d_in[8];
    const float* dt_bias  = (const float*)d_in[9];
    const float* A_log    = (const float*)d_in[10];
    const float* D_skip   = (const float*)d_in[11];
    const float* norm_w   = (const float*)d_in[12];
    const float* w_outproj= (const float*)d_in[13];
    const float* w_mix1   = (const float*)d_in[14];
    const float* b_mix1   = (const float*)d_in[15];
    const float* w_mix2   = (const float*)d_in[16];
    const float* b_mix2   = (const float*)d_in[17];
    const float* w_out    = (const float*)d_in[18];
    const float* b_out    = (const float*)d_in[19];
    float* out = (float*)d_out;

    cudaFuncSetAttribute(kC, cudaFuncAttributeMaxDynamicSharedMemorySize, KC_SMEM_FLOATS * 4);

    k0a<<<1, 256>>>(mic_pos, w_mic, b_mic, b_in, A_log);
    k0b<<<(4 * DPROJ + BB * DPROJ + 32 * 192 + 255) / 256, 256>>>(w_in, w_inproj, w_outproj, w_mix1, norm_w);
    k1<<<dim3(32, 16), 128>>>(x, conv_w, conv_b, dt_bias);
    kA<<<dim3(NC, 128), 192>>>();
    kB<<<dim3(128, 2), 384>>>();
    kC<<<dim3(NC, BB), 256, KC_SMEM_FLOATS * 4>>>(D_skip, x);
    kD2<<<dim3(32, BB), 256>>>(b_mix1, w_mix2, b_mix2);
    kF<<<1, 32>>>(w_out, b_out, out);
}

// round 11
// speedup vs baseline: 3.8624x; 1.1179x over previous
#include <cuda_runtime.h>
#include <cuda_bf16.h>
#include <math.h>
#include <stdint.h>

#define BB 16
#define TT 4096
#define DINNER 384
#define NH 8
#define HD 48
#define DS 64
#define DPROJ 904
#define NC 64
#define CS 64
#define MIXD 32

// ---------------- scratch (static device arrays; no runtime alloc) ----------
__device__ float g_W1[4 * DPROJ];            // w_in @ w_inproj
__device__ float g_mvec[BB * DPROJ];         // (b_in + relu(mic)) @ w_inproj
__device__ uint32_t g_W2bt32[32 * 192];      // bf16x2 [o][dpair]
__device__ float g_hb[BB * 192];
__device__ float g_A[NH];
__device__ uint32_t g_xbf[(size_t)BB * TT * 192];  // silu(conv) xs, bf16x2 pairs along p
__device__ float g_bc[(size_t)BB * TT * 128];      // B(64) | C(64) fp32
__device__ float g_dt[(size_t)BB * TT * NH];
__device__ float g_la[(size_t)BB * TT * NH];       // log-decay = dt*A
__device__ uint32_t g_Sbf[(size_t)128 * NC * HD * 32]; // chunk states bf16x2 (pairs along n) -> h_in in place
__device__ float g_Dc[128 * NC];
__device__ uint32_t g_ybf32[(size_t)BB * TT * 192];    // gated y, bf16x2
__device__ float g_rstd[BB * TT];
__device__ float g_part[2048 * MIXD];

__device__ __forceinline__ float siluf(float v) {
    if (fabsf(v) < 0.25f) {
        float z2 = v * v;
        float sig = 0.5f + v * (0.25f + z2 * (-(1.f / 48.f) + z2 * (1.f / 480.f)));
        return v * sig;
    }
    return __fdividef(v, 1.f + __expf(-v));
}
__device__ __forceinline__ float softplusf(float v) { return v > 20.f ? v : __logf(1.f + __expf(v)); }

__device__ __forceinline__ uint32_t tf32u(float x) {
    uint32_t r;
    asm("cvt.rna.tf32.f32 %0, %1;" : "=r"(r) : "f"(x));
    return r;
}
__device__ __forceinline__ float tf32f(float x) { return __uint_as_float(tf32u(x)); }

__device__ __forceinline__ uint32_t packbf(float lo, float hi) {
    uint32_t w;
    asm("cvt.rn.bf16x2.f32 %0, %1, %2;" : "=r"(w) : "f"(hi), "f"(lo));
    return w;
}
__device__ __forceinline__ float2 unpackbf(uint32_t w) {
    return make_float2(__uint_as_float(w << 16), __uint_as_float(w & 0xffff0000u));
}
__device__ __forceinline__ float bfh(uint16_t v) {
    return __uint_as_float(((uint32_t)v) << 16);
}

__device__ __forceinline__ void mma8(float d[4], const uint32_t a[4], const uint32_t b[2]) {
    asm volatile(
        "mma.sync.aligned.m16n8k8.row.col.f32.tf32.tf32.f32 "
        "{%0,%1,%2,%3},{%4,%5,%6,%7},{%8,%9},{%0,%1,%2,%3};\n"
        : "+f"(d[0]), "+f"(d[1]), "+f"(d[2]), "+f"(d[3])
        : "r"(a[0]), "r"(a[1]), "r"(a[2]), "r"(a[3]),
          "r"(b[0]), "r"(b[1]));
}

__device__ __forceinline__ void mma16(float d[4], const uint32_t a[4], const uint32_t b[2]) {
    asm volatile(
        "mma.sync.aligned.m16n8k16.row.col.f32.bf16.bf16.f32 "
        "{%0,%1,%2,%3},{%4,%5,%6,%7},{%8,%9},{%0,%1,%2,%3};\n"
        : "+f"(d[0]), "+f"(d[1]), "+f"(d[2]), "+f"(d[3])
        : "r"(a[0]), "r"(a[1]), "r"(a[2]), "r"(a[3]),
          "r"(b[0]), "r"(b[1]));
}

// ---------------- k0a: mic MLP + A ----------------
__global__ void k0a(const float* __restrict__ mic_pos, const float* __restrict__ w_mic,
                    const float* __restrict__ b_mic, const float* __restrict__ b_in,
                    const float* __restrict__ A_log) {
    int tid = threadIdx.x;
    for (int i = tid; i < BB * 192; i += 256) {
        int b = i / 192, d = i % 192;
        float s = b_mic[d];
        #pragma unroll
        for (int j = 0; j < 12; j++) s = fmaf(mic_pos[b * 12 + j], w_mic[j * 192 + d], s);
        g_hb[i] = b_in[d] + fmaxf(s, 0.f);
    }
    if (tid < NH) g_A[tid] = -expf(A_log[tid]);
}

// ---------------- k0b: folded weights ----------------
__global__ void k0b(const float* __restrict__ w_in, const float* __restrict__ w_inproj,
                    const float* __restrict__ w_outproj, const float* __restrict__ w_mix1,
                    const float* __restrict__ norm_w) {
    int i = blockIdx.x * 256 + threadIdx.x;
    if (i < 4 * DPROJ) {
        int j = i / DPROJ, d = i % DPROJ;
        float s = 0.f;
        for (int m = 0; m < 192; m++) s = fmaf(w_in[j * 192 + m], w_inproj[m * DPROJ + d], s);
        g_W1[i] = s;
    } else if (i < 4 * DPROJ + BB * DPROJ) {
        int ii = i - 4 * DPROJ;
        int b = ii / DPROJ, d = ii % DPROJ;
        float s = 0.f;
        for (int m = 0; m < 192; m++) s = fmaf(g_hb[b * 192 + m], w_inproj[m * DPROJ + d], s);
        g_mvec[ii] = s;
    } else if (i < 4 * DPROJ + BB * DPROJ + 32 * 192) {
        int ii = i - (4 * DPROJ + BB * DPROJ);
        int o = ii / 192, kw = ii % 192;
        int d0 = 2 * kw, d1 = d0 + 1;
        float s0 = 0.f, s1 = 0.f;
        for (int m = 0; m < 192; m++) {
            s0 = fmaf(w_outproj[d0 * 192 + m], w_mix1[m * MIXD + o], s0);
            s1 = fmaf(w_outproj[d1 * 192 + m], w_mix1[m * MIXD + o], s1);
        }
        g_W2bt32[o * 192 + kw] = packbf(s0 * norm_w[d0], s1 * norm_w[d1]);
    }
}

// ---------------- k1: fused inproj + conv4 + silu + dt/la ----------------
// grid (32, 16) block 128 : thread = one t
__global__ void k1(const float* __restrict__ x, const float* __restrict__ conv_w,
                   const float* __restrict__ conv_b, const float* __restrict__ dt_bias) {
    __shared__ float sW1[4 * 520];   // proj dims 384..903
    __shared__ float smv[520];
    __shared__ float scw[512 * 4];
    __shared__ float scb[512];
    __shared__ float sx4[131 * 4];
    __shared__ float sraw[131 * 33];

    int tid = threadIdx.x;
    int b = blockIdx.y;
    int t0 = blockIdx.x * 128;

    for (int i = tid; i < 4 * 520; i += 128) sW1[i] = g_W1[(i / 520) * DPROJ + 384 + (i % 520)];
    for (int i = tid; i < 520; i += 128) smv[i] = g_mvec[b * DPROJ + 384 + i];
    for (int i = tid; i < 512 * 4; i += 128) scw[i] = conv_w[i];
    for (int i = tid; i < 512; i += 128) scb[i] = conv_b[i];
    for (int i = tid; i < 131 * 4; i += 128) {
        int r = i >> 2, j = i & 3;
        int t = t0 + r - 3;
        sx4[i] = (t >= 0) ? x[((size_t)b * TT + t) * 4 + j] : 0.f;
    }

    int t = t0 + tid;
    for (int c16 = 0; c16 < 16; c16++) {
        __syncthreads();
        for (int i = tid; i < 131 * 32; i += 128) {
            int r = i >> 5, dc = i & 31;
            int dd = c16 * 32 + dc;
            float v = 0.f;
            if (t0 + r - 3 >= 0) {
                v = smv[dd];
                #pragma unroll
                for (int j = 0; j < 4; j++) v = fmaf(sx4[r * 4 + j], sW1[j * 520 + dd], v);
            }
            sraw[r * 33 + dc] = v;
        }
        __syncthreads();
        float v[32];
        #pragma unroll
        for (int dc = 0; dc < 32; dc++) {
            int dd = c16 * 32 + dc;
            float a = scb[dd];
            #pragma unroll
            for (int k = 0; k < 4; k++) a = fmaf(sraw[(tid + k) * 33 + dc], scw[dd * 4 + k], a);
            v[dc] = siluf(a);
        }
        if (c16 < 12) {
            uint32_t* dst = g_xbf + ((size_t)b * TT + t) * 192 + c16 * 16;
            #pragma unroll
            for (int q = 0; q < 4; q++) {
                uint4 w;
                w.x = packbf(v[8 * q + 0], v[8 * q + 1]);
                w.y = packbf(v[8 * q + 2], v[8 * q + 3]);
                w.z = packbf(v[8 * q + 4], v[8 * q + 5]);
                w.w = packbf(v[8 * q + 6], v[8 * q + 7]);
                ((uint4*)dst)[q] = w;
            }
        } else {
            float* dst = g_bc + ((size_t)b * TT + t) * 128 + (c16 - 12) * 32;
            #pragma unroll
            for (int q = 0; q < 8; q++)
                ((float4*)dst)[q] = make_float4(v[4 * q], v[4 * q + 1], v[4 * q + 2], v[4 * q + 3]);
        }
    }

    // dt path (proj dims 896..903 via sW1 dims 512..519)
    #pragma unroll
    for (int hh = 0; hh < NH; hh++) {
        int dd = 512 + hh;
        float v = smv[dd];
        #pragma unroll
        for (int j = 0; j < 4; j++) v = fmaf(sx4[(tid + 3) * 4 + j], sW1[j * 520 + dd], v);
        float dt = softplusf(v + dt_bias[hh]);
        size_t o = ((size_t)b * TT + t) * NH + hh;
        g_dt[o] = dt;
        g_la[o] = dt * g_A[hh];
    }
}

// ---------------- kA: chunk-local end states via tf32 mma ----------------
// grid (NC, 128) block 192 (6 warps): warp = (p-strip w%3, n-half w/3)
__global__ __launch_bounds__(192) void kA() {
    __shared__ float sxw[CS * 56];   // [t][p] = w(t)*x(t,p), tf32
    __shared__ float sB[CS * 72];    // [t][n], tf32
    __shared__ float scs[CS];
    __shared__ float sdt[CS];

    int c = blockIdx.x, bh = blockIdx.y;
    int b = bh >> 3, h = bh & 7;
    int tid = threadIdx.x;
    int wid = tid >> 5, lane = tid & 31;
    int lq = lane & 3, lh = lane >> 2;
    int t0 = c * CS;

    if (tid < CS) {
        size_t o = ((size_t)b * TT + t0 + tid) * NH + h;
        scs[tid] = g_la[o];
        sdt[tid] = g_dt[o];
    }
    const float* bp = g_bc + ((size_t)b * TT + t0) * 128;
    for (int i = tid; i < CS * 16; i += 192) {
        int r = i >> 4, col = i & 15;
        float4 v = ((const float4*)(bp + (size_t)r * 128))[col];
        *(float4*)&sB[r * 72 + col * 4] =
            make_float4(tf32f(v.x), tf32f(v.y), tf32f(v.z), tf32f(v.w));
    }
    __syncthreads();

    if (wid == 0) {
        float a0 = scs[2 * lane], a1 = scs[2 * lane + 1];
        float ps = a0 + a1;
        #pragma unroll
        for (int off = 1; off < 32; off <<= 1) {
            float v = __shfl_up_sync(0xffffffffu, ps, off);
            if (lane >= off) ps += v;
        }
        scs[2 * lane + 1] = ps;
        scs[2 * lane]     = ps - a1;
    }
    __syncthreads();

    float cstot = scs[CS - 1];
    const uint32_t* xp = g_xbf + ((size_t)b * TT + t0) * 192 + h * 24;
    for (int i = tid; i < CS * 6; i += 192) {
        int r = i / 6, col = i % 6;
        float wgt = __expf(cstot - scs[r]) * sdt[r];
        uint4 w4 = ((const uint4*)(xp + (size_t)r * 192))[col];
        float2 q0 = unpackbf(w4.x), q1 = unpackbf(w4.y), q2 = unpackbf(w4.z), q3 = unpackbf(w4.w);
        *(float4*)&sxw[r * 56 + col * 8] =
            make_float4(tf32f(q0.x * wgt), tf32f(q0.y * wgt), tf32f(q1.x * wgt), tf32f(q1.y * wgt));
        *(float4*)&sxw[r * 56 + col * 8 + 4] =
            make_float4(tf32f(q2.x * wgt), tf32f(q2.y * wgt), tf32f(q3.x * wgt), tf32f(q3.y * wgt));
    }
    __syncthreads();

    int p0 = (wid % 3) * 16;
    int nb = (wid / 3) * 32;
    float acc[4][4];
    #pragma unroll
    for (int j = 0; j < 4; j++)
        #pragma unroll
        for (int e = 0; e < 4; e++) acc[j][e] = 0.f;

    #pragma unroll
    for (int k = 0; k < CS; k += 8) {
        uint32_t a[4];
        a[0] = __float_as_uint(sxw[(k + lq) * 56 + p0 + lh]);
        a[1] = __float_as_uint(sxw[(k + lq) * 56 + p0 + lh + 8]);
        a[2] = __float_as_uint(sxw[(k + 4 + lq) * 56 + p0 + lh]);
        a[3] = __float_as_uint(sxw[(k + 4 + lq) * 56 + p0 + lh + 8]);
        #pragma unroll
        for (int j = 0; j < 4; j++) {
            uint32_t bfr[2];
            bfr[0] = __float_as_uint(sB[(k + lq) * 72 + nb + 8 * j + lh]);
            bfr[1] = __float_as_uint(sB[(k + 4 + lq) * 72 + nb + 8 * j + lh]);
            mma8(acc[j], a, bfr);
        }
    }

    uint32_t* sp = g_Sbf + ((size_t)bh * NC + c) * 1536;
    #pragma unroll
    for (int j = 0; j < 4; j++) {
        int n0 = nb + 8 * j + 2 * lq;
        sp[(p0 + lh) * 32 + (n0 >> 1)]     = packbf(acc[j][0], acc[j][1]);
        sp[(p0 + lh + 8) * 32 + (n0 >> 1)] = packbf(acc[j][2], acc[j][3]);
    }
    if (tid == 0) g_Dc[bh * NC + c] = __expf(cstot);
}

// ---------------- kB: inter-chunk scan (fp32 regs, bf16 storage) ----------
// grid (128, 4) block 384 : thread owns 2 states (1 word), depth-2 prefetch
__global__ void kB() {
    int bh = blockIdx.x, q = blockIdx.y;
    int tid = threadIdx.x;
    float h0 = 0.f, h1 = 0.f;
    size_t base = (size_t)bh * NC * 1536 + (size_t)q * 384 + tid;
    uint32_t a0 = g_Sbf[base];
    uint32_t a1 = g_Sbf[base + 1536];
    float D0 = g_Dc[bh * NC];
    float D1 = g_Dc[bh * NC + 1];
    for (int c = 0; c < NC; c++) {
        uint32_t* sp = g_Sbf + base + (size_t)c * 1536;
        uint32_t an = 0u;
        float Dn = 0.f;
        if (c + 2 < NC) {
            an = sp[2 * 1536];
            Dn = g_Dc[bh * NC + c + 2];
        }
        float2 p = unpackbf(a0);
        sp[0] = packbf(h0, h1);
        h0 = fmaf(h0, D0, p.x);
        h1 = fmaf(h1, D0, p.y);
        a0 = a1; a1 = an; D0 = D1; D1 = Dn;
    }
}

// ---------------- kC: chunked SSD + fused gating/RMS-stats ----------------
// grid (NC, BB) block 256 (8 warps)
// GEMM1 tf32; GEMM2/GEMM3 bf16 mma16. G bf16 aliased onto sBt. h_in read from global.
#define ST64 72
#define STB 36
#define KC_BT   0                        // GEMM1 B: B^T [n][t] tf32 (4608) ∪ G bf16 words [t][STB]
#define KC_CT   (KC_BT + 64 * ST64)      // GEMM1 A: C^T [n][t] tf32 (4608)
#define KC_CB   (KC_CT + 64 * ST64)      // C bf16 words [t][STB] (2304)
#define KC_XT   (KC_CB + 64 * STB)       // x^T bf16 words [p:48][STB] (1728)
#define KC_SCS  (KC_XT + 48 * STB)       // 8*64
#define KC_SDT  (KC_SCS + 512)           // 8*64
#define KC_W1Z  (KC_SDT + 512)           // 4*384
#define KC_MVZ  (KC_W1Z + 1536)          // 384
#define KC_X4   (KC_MVZ + 384)           // 64*4
#define KC_SMEM_FLOATS (KC_X4 + 256)

__global__ __launch_bounds__(256) void kC(const float* __restrict__ D_skip,
                                          const float* __restrict__ xin) {
    extern __shared__ float sm[];
    uint32_t* smu = (uint32_t*)sm;
    uint16_t* smh = (uint16_t*)sm;
    float* sBt  = sm + KC_BT;
    float* sCt  = sm + KC_CT;
    float* sCS  = sm + KC_SCS;
    float* sDT  = sm + KC_SDT;
    float* sW1z = sm + KC_W1Z;
    float* smvz = sm + KC_MVZ;
    float* sx4  = sm + KC_X4;

    int c = blockIdx.x, b = blockIdx.y;
    int tid = threadIdx.x;
    int wid = tid >> 5, lane = tid & 31;
    int lq = lane & 3, lh = lane >> 2;
    int t0c = c * CS;

    if (tid < 128) {
        const float* lap = g_la + ((size_t)b * TT + t0c) * NH;
        const float* dtp = g_dt + ((size_t)b * TT + t0c) * NH;
        float4 v = ((const float4*)lap)[tid];
        float4 w = ((const float4*)dtp)[tid];
        int j0 = tid * 4;
        #pragma unroll
        for (int u = 0; u < 4; u++) {
            int j = j0 + u;
            int t = j >> 3, h = j & 7;
            sCS[h * 64 + t] = (&v.x)[u];
            sDT[h * 64 + t] = (&w.x)[u];
        }
    }
    for (int i = tid; i < 4 * DINNER; i += 256) sW1z[i] = g_W1[(i / DINNER) * DPROJ + (i % DINNER)];
    for (int i = tid; i < DINNER; i += 256) smvz[i] = g_mvec[b * DPROJ + i];
    if (tid < 256) {
        int r = tid >> 2, j = tid & 3;
        sx4[tid] = xin[((size_t)b * TT + t0c + r) * 4 + j];
    }

    // B,C load: tf32 transposed [n][t] + bf16-packed C [t][STB]
    const float* bp = g_bc + ((size_t)b * TT + t0c) * 128;
    for (int i = tid; i < CS * 16; i += 256) {
        int s = i >> 4, nq = i & 15;
        float4 v = ((const float4*)(bp + (size_t)s * 128))[nq];          // B[s][n]
        sBt[(nq * 4 + 0) * ST64 + s] = tf32f(v.x);
        sBt[(nq * 4 + 1) * ST64 + s] = tf32f(v.y);
        sBt[(nq * 4 + 2) * ST64 + s] = tf32f(v.z);
        sBt[(nq * 4 + 3) * ST64 + s] = tf32f(v.w);
        float4 w = ((const float4*)(bp + (size_t)s * 128))[nq + 16];     // C[s][n]
        sCt[(nq * 4 + 0) * ST64 + s] = tf32f(w.x);
        sCt[(nq * 4 + 1) * ST64 + s] = tf32f(w.y);
        sCt[(nq * 4 + 2) * ST64 + s] = tf32f(w.z);
        sCt[(nq * 4 + 3) * ST64 + s] = tf32f(w.w);
        smu[KC_CB + s * STB + 2 * nq]     = packbf(w.x, w.y);
        smu[KC_CB + s * STB + 2 * nq + 1] = packbf(w.z, w.w);
    }
    __syncthreads();

    // per-head inclusive log-decay prefix (warp w = head w)
    {
        float a0 = sCS[wid * 64 + 2 * lane];
        float a1 = sCS[wid * 64 + 2 * lane + 1];
        float ps = a0 + a1;
        #pragma unroll
        for (int off = 1; off < 32; off <<= 1) {
            float v = __shfl_up_sync(0xffffffffu, ps, off);
            if (lane >= off) ps += v;
        }
        sCS[wid * 64 + 2 * lane + 1] = ps;
        sCS[wid * 64 + 2 * lane]     = ps - a1;
    }

    int t0 = (wid & 3) * 16;
    int sb = (wid >> 2) * 32;
    int pb = (wid >> 2) * 24;

    float xr0[4], xr1[4];
    #pragma unroll
    for (int u = 0; u < 4; u++) {
        xr0[u] = sx4[(t0 + lh) * 4 + u];
        xr1[u] = sx4[(t0 + lh + 8) * 4 + u];
    }

    // GEMM1 (tf32, shared across heads): Graw[t][s] = sum_n C[t][n]*B[s][n]
    float g1[4][4];
    #pragma unroll
    for (int j = 0; j < 4; j++)
        #pragma unroll
        for (int e = 0; e < 4; e++) g1[j][e] = 0.f;

    #pragma unroll
    for (int k = 0; k < DS; k += 8) {
        uint32_t a[4];
        a[0] = __float_as_uint(sCt[(k + lq) * ST64 + t0 + lh]);
        a[1] = __float_as_uint(sCt[(k + lq) * ST64 + t0 + lh + 8]);
        a[2] = __float_as_uint(sCt[(k + 4 + lq) * ST64 + t0 + lh]);
        a[3] = __float_as_uint(sCt[(k + 4 + lq) * ST64 + t0 + lh + 8]);
        #pragma unroll
        for (int j = 0; j < 4; j++) {
            uint32_t bfr[2];
            bfr[0] = __float_as_uint(sBt[(k + lq) * ST64 + sb + 8 * j + lh]);
            bfr[1] = __float_as_uint(sBt[(k + 4 + lq) * ST64 + sb + 8 * j + lh]);
            mma8(g1[j], a, bfr);
        }
    }

    float ss0 = 0.f, ss1 = 0.f;
    uint32_t* ybase = g_ybf32 + ((size_t)b * TT + t0c) * 192;

    for (int h = 0; h < NH; h++) {
        __syncthreads();   // prior reads of G(BT)/xT done; on h=0 GEMM1 reads of sBt done

        // build x^T [p][s-pair] bf16 for this head (16-bit smem stores)
        const uint32_t* xp = g_xbf + ((size_t)b * TT + t0c) * 192 + h * 24;
        for (int i = tid; i < CS * 6; i += 256) {
            int s = i / 6, col = i % 6;
            uint4 w4 = ((const uint4*)(xp + (size_t)s * 192))[col];
            int p0w = col * 8;
            int half = s & 1, sw = s >> 1;
            uint32_t ws[4] = {w4.x, w4.y, w4.z, w4.w};
            #pragma unroll
            for (int u = 0; u < 4; u++) {
                int p = p0w + 2 * u;
                smh[(KC_XT + p * STB + sw) * 2 + half]       = (uint16_t)(ws[u] & 0xffffu);
                smh[(KC_XT + (p + 1) * STB + sw) * 2 + half] = (uint16_t)(ws[u] >> 16);
            }
        }

        // mask+scale Graw with this head's decay, store bf16 G [t][s-pair] (aliased onto BT)
        const float* csh = sCS + h * 64;
        const float* dth = sDT + h * 64;
        {
            float cs_r0 = csh[t0 + lh], cs_r1 = csh[t0 + lh + 8];
            #pragma unroll
            for (int j = 0; j < 4; j++) {
                int c0 = sb + 8 * j + 2 * lq;
                float cs_c0 = csh[c0], cs_c1 = csh[c0 + 1];
                float dt_c0 = dth[c0], dt_c1 = dth[c0 + 1];
                int r0 = t0 + lh, r1 = r0 + 8;
                float m00 = (c0 <= r0) ? __expf(cs_r0 - cs_c0) * dt_c0 : 0.f;
                float m01 = (c0 + 1 <= r0) ? __expf(cs_r0 - cs_c1) * dt_c1 : 0.f;
                float m10 = (c0 <= r1) ? __expf(cs_r1 - cs_c0) * dt_c0 : 0.f;
                float m11 = (c0 + 1 <= r1) ? __expf(cs_r1 - cs_c1) * dt_c1 : 0.f;
                int cw = c0 >> 1;
                smu[KC_BT + r0 * STB + cw] = packbf(g1[j][0] * m00, g1[j][1] * m01);
                smu[KC_BT + r1 * STB + cw] = packbf(g1[j][2] * m10, g1[j][3] * m11);
            }
        }
        __syncthreads();

        // GEMM2 (bf16): Yintra[t][p] = sum_s G[t][s]*x[s][p]
        // GEMM3 (bf16): Yinter[t][p] = sum_n C[t][n]*hin[n][p]  (B fragments direct from global)
        float accA[3][4], accB[3][4];
        #pragma unroll
        for (int j = 0; j < 3; j++)
            #pragma unroll
            for (int e = 0; e < 4; e++) { accA[j][e] = 0.f; accB[j][e] = 0.f; }

        const uint32_t* hp = g_Sbf + ((size_t)(b * NH + h) * NC + c) * 1536;
        #pragma unroll
        for (int k16 = 0; k16 < 64; k16 += 16) {
            int kw = k16 >> 1;
            uint32_t a[4];
            a[0] = smu[KC_BT + (t0 + lh) * STB + kw + lq];
            a[1] = smu[KC_BT + (t0 + lh + 8) * STB + kw + lq];
            a[2] = smu[KC_BT + (t0 + lh) * STB + kw + lq + 4];
            a[3] = smu[KC_BT + (t0 + lh + 8) * STB + kw + lq + 4];
            #pragma unroll
            for (int j = 0; j < 3; j++) {
                int p = pb + 8 * j + lh;
                uint32_t bfr[2];
                bfr[0] = smu[KC_XT + p * STB + kw + lq];
                bfr[1] = smu[KC_XT + p * STB + kw + lq + 4];
                mma16(accA[j], a, bfr);
            }
            uint32_t a2[4];
            a2[0] = smu[KC_CB + (t0 + lh) * STB + kw + lq];
            a2[1] = smu[KC_CB + (t0 + lh + 8) * STB + kw + lq];
            a2[2] = smu[KC_CB + (t0 + lh) * STB + kw + lq + 4];
            a2[3] = smu[KC_CB + (t0 + lh + 8) * STB + kw + lq + 4];
            #pragma unroll
            for (int j = 0; j < 3; j++) {
                int p = pb + 8 * j + lh;
                uint32_t bfr[2];
                bfr[0] = __ldg(hp + p * 32 + kw + lq);
                bfr[1] = __ldg(hp + p * 32 + kw + lq + 4);
                mma16(accB[j], a2, bfr);
            }
        }

        // epilogue: y = intra + exp(cs)*inter + D*x; gate; accumulate ss; store bf16
        float dskip = D_skip[h];
        float et0 = __expf(csh[t0 + lh]);
        float et1 = __expf(csh[t0 + lh + 8]);
        #pragma unroll
        for (int j = 0; j < 3; j++) {
            int p0c = pb + 8 * j + 2 * lq;
            int r0 = t0 + lh, r1 = r0 + 8;
            int dd = h * HD + p0c;
            float x00 = bfh(smh[(KC_XT + p0c * STB + (r0 >> 1)) * 2 + (r0 & 1)]);
            float x01 = bfh(smh[(KC_XT + (p0c + 1) * STB + (r0 >> 1)) * 2 + (r0 & 1)]);
            float x10 = bfh(smh[(KC_XT + p0c * STB + (r1 >> 1)) * 2 + (r1 & 1)]);
            float x11 = bfh(smh[(KC_XT + (p0c + 1) * STB + (r1 >> 1)) * 2 + (r1 & 1)]);
            float y00 = accA[j][0] + et0 * accB[j][0] + dskip * x00;
            float y01 = accA[j][1] + et0 * accB[j][1] + dskip * x01;
            float y10 = accA[j][2] + et1 * accB[j][2] + dskip * x10;
            float y11 = accA[j][3] + et1 * accB[j][3] + dskip * x11;
            float w0a = sW1z[dd],            w0b = sW1z[dd + 1];
            float w1a = sW1z[DINNER + dd],   w1b = sW1z[DINNER + dd + 1];
            float w2a = sW1z[2*DINNER + dd], w2b = sW1z[2*DINNER + dd + 1];
            float w3a = sW1z[3*DINNER + dd], w3b = sW1z[3*DINNER + dd + 1];
            float mva = smvz[dd], mvb = smvz[dd + 1];
            float za0 = fmaf(xr0[3], w3a, fmaf(xr0[2], w2a, fmaf(xr0[1], w1a, fmaf(xr0[0], w0a, mva))));
            float zb0 = fmaf(xr0[3], w3b, fmaf(xr0[2], w2b, fmaf(xr0[1], w1b, fmaf(xr0[0], w0b, mvb))));
            float za1 = fmaf(xr1[3], w3a, fmaf(xr1[2], w2a, fmaf(xr1[1], w1a, fmaf(xr1[0], w0a, mva))));
            float zb1 = fmaf(xr1[3], w3b, fmaf(xr1[2], w2b, fmaf(xr1[1], w1b, fmaf(xr1[0], w0b, mvb))));
            float g00 = y00 * siluf(za0);
            float g01 = y01 * siluf(zb0);
            float g10 = y10 * siluf(za1);
            float g11 = y11 * siluf(zb1);
            ss0 = fmaf(g00, g00, fmaf(g01, g01, ss0));
            ss1 = fmaf(g10, g10, fmaf(g11, g11, ss1));
            ybase[(size_t)r0 * 192 + (dd >> 1)] = packbf(g00, g01);
            ybase[(size_t)r1 * 192 + (dd >> 1)] = packbf(g10, g11);
        }
    }

    // row sum-of-squares -> rstd   (reuse sCS region)
    __syncthreads();
    ss0 += __shfl_xor_sync(0xffffffffu, ss0, 1);
    ss0 += __shfl_xor_sync(0xffffffffu, ss0, 2);
    ss1 += __shfl_xor_sync(0xffffffffu, ss1, 1);
    ss1 += __shfl_xor_sync(0xffffffffu, ss1, 2);
    if (lq == 0) {
        sCS[(wid >> 2) * 64 + t0 + lh]     = ss0;
        sCS[(wid >> 2) * 64 + t0 + lh + 8] = ss1;
    }
    __syncthreads();
    if (tid < 64) {
        float s = sCS[tid] + sCS[64 + tid];
        g_rstd[(size_t)b * TT + t0c + tid] = rsqrtf(s * (1.f / DINNER) + 1e-5f);
    }
}

// ---------------- kD2: bf16 mma GEMM(W2) + rstd + mix2 + partial ----------
// grid (32, BB) block 256 (8 warps), 128 rows/block
__global__ __launch_bounds__(256) void kD2(const float* __restrict__ b_mix1,
                   const float* __restrict__ w_mix2, const float* __restrict__ b_mix2) {
    __shared__ float sm1[128 * 33];
    __shared__ float swm2[MIXD * MIXD];

    int tid = threadIdx.x;
    int wid = tid >> 5, lane = tid & 31;
    int lq = lane & 3, lh = lane >> 2;
    int b = blockIdx.y;
    int t0 = blockIdx.x * 128;

    for (int i = tid; i < MIXD * MIXD; i += 256) swm2[i] = w_mix2[i];

    const uint32_t* arow = g_ybf32 + ((size_t)b * TT + t0 + wid * 16) * 192;
    float acc[4][4];
    #pragma unroll
    for (int j = 0; j < 4; j++)
        #pragma unroll
        for (int e = 0; e < 4; e++) acc[j][e] = 0.f;

    #pragma unroll 4
    for (int k16 = 0; k16 < DINNER; k16 += 16) {
        int kw = k16 >> 1;
        uint32_t a[4];
        a[0] = __ldg(arow + (size_t)lh * 192 + kw + lq);
        a[1] = __ldg(arow + (size_t)(lh + 8) * 192 + kw + lq);
        a[2] = __ldg(arow + (size_t)lh * 192 + kw + 4 + lq);
        a[3] = __ldg(arow + (size_t)(lh + 8) * 192 + kw + 4 + lq);
        #pragma unroll
        for (int j = 0; j < 4; j++) {
            uint32_t bfr[2];
            bfr[0] = __ldg(&g_W2bt32[(8 * j + lh) * 192 + kw + lq]);
            bfr[1] = __ldg(&g_W2bt32[(8 * j + lh) * 192 + kw + 4 + lq]);
            mma16(acc[j], a, bfr);
        }
    }

    {
        int r0 = wid * 16 + lh, r1 = r0 + 8;
        float rs0 = g_rstd[(size_t)b * TT + t0 + r0];
        float rs1 = g_rstd[(size_t)b * TT + t0 + r1];
        #pragma unroll
        for (int j = 0; j < 4; j++) {
            int oc = 8 * j + 2 * lq;
            sm1[r0 * 33 + oc]     = fmaxf(fmaf(acc[j][0], rs0, b_mix1[oc]), 0.f);
            sm1[r0 * 33 + oc + 1] = fmaxf(fmaf(acc[j][1], rs0, b_mix1[oc + 1]), 0.f);
            sm1[r1 * 33 + oc]     = fmaxf(fmaf(acc[j][2], rs1, b_mix1[oc]), 0.f);
            sm1[r1 * 33 + oc + 1] = fmaxf(fmaf(acc[j][3], rs1, b_mix1[oc + 1]), 0.f);
        }
    }
    __syncthreads();

    int r2 = tid >> 1;
    int oh = (tid & 1) * 16;
    float m2[16];
    #pragma unroll
    for (int o = 0; o < 16; o++) m2[o] = b_mix2[oh + o];
    #pragma unroll 4
    for (int i = 0; i < MIXD; i++) {
        float m = sm1[r2 * 33 + i];
        #pragma unroll
        for (int o = 0; o < 16; o++) m2[o] = fmaf(m, swm2[i * MIXD + oh + o], m2[o]);
    }
    #pragma unroll
    for (int o = 0; o < 16; o++) m2[o] = fmaxf(m2[o], 0.f);
    __syncthreads();
    #pragma unroll
    for (int o = 0; o < 16; o++) sm1[r2 * 33 + oh + o] = m2[o];
    __syncthreads();

    for (int s = 64; s >= 1; s >>= 1) {
        for (int idx = tid; idx < s * 32; idx += 256) {
            int r = idx >> 5, o = idx & 31;
            sm1[r * 33 + o] += sm1[(r + s) * 33 + o];
        }
        __syncthreads();
    }
    if (tid < MIXD) g_part[((size_t)b * 32 + blockIdx.x) * MIXD + tid] = sm1[tid];
}

// ---------------- kF: final mean + w_out ----------------
__global__ void kF(const float* __restrict__ w_out, const float* __restrict__ b_out,
                   float* __restrict__ out) {
    int b = threadIdx.x;
    if (b < BB) {
        float s = 0.f;
        for (int o = 0; o < MIXD; o++) {
            float a = 0.f;
            for (int blk = 0; blk < 32; blk++) a += g_part[((size_t)b * 32 + blk) * MIXD + o];
            s = fmaf(a * (1.f / (float)TT), w_out[o], s);
        }
        out[b] = s + b_out[0];
    }
}

extern "C" void kernel_launch(void* const* d_in, const int* in_sizes, int n_in,
                              void* d_out, int out_size) {
    const float* x        = (const float*)d_in[0];
    const float* mic_pos  = (const float*)d_in[1];
    const float* w_in     = (const float*)d_in[2];
    const float* b_in     = (const float*)d_in[3];
    const float* w_mic    = (const float*)d_in[4];
    const float* b_mic    = (const float*)d_in[5];
    const float* w_inproj = (const float*)d_in[6];
    const float* conv_w   = (const float*)d_in[7];
    const float* conv_b   = (const float*)d_in[8];
    const float* dt_bias  = (const float*)d_in[9];
    const float* A_log    = (const float*)d_in[10];
    const float* D_skip   = (const float*)d_in[11];
    const float* norm_w   = (const float*)d_in[12];
    const float* w_outproj= (const float*)d_in[13];
    const float* w_mix1   = (const float*)d_in[14];
    const float* b_mix1   = (const float*)d_in[15];
    const float* w_mix2   = (const float*)d_in[16];
    const float* b_mix2   = (const float*)d_in[17];
    const float* w_out    = (const float*)d_in[18];
    const float* b_out    = (const float*)d_in[19];
    float* out = (float*)d_out;

    cudaFuncSetAttribute(kC, cudaFuncAttributeMaxDynamicSharedMemorySize, KC_SMEM_FLOATS * 4);

    k0a<<<1, 256>>>(mic_pos, w_mic, b_mic, b_in, A_log);
    k0b<<<(4 * DPROJ + BB * DPROJ + 32 * 192 + 255) / 256, 256>>>(w_in, w_inproj, w_outproj, w_mix1, norm_w);
    k1<<<dim3(32, 16), 128>>>(x, conv_w, conv_b, dt_bias);
    kA<<<dim3(NC, 128), 192>>>();
    kB<<<dim3(128, 4), 384>>>();
    kC<<<dim3(NC, BB), 256, KC_SMEM_FLOATS * 4>>>(D_skip, x);
    kD2<<<dim3(32, BB), 256>>>(b_mix1, w_mix2, b_mix2);
    kF<<<1, 32>>>(w_out, b_out, out);
}

// round 12
// speedup vs baseline: 4.0684x; 1.0533x over previous
#include <cuda_runtime.h>
#include <cuda_bf16.h>
#include <math.h>
#include <stdint.h>

#define BB 16
#define TT 4096
#define DINNER 384
#define NH 8
#define HD 48
#define DS 64
#define DPROJ 904
#define NC 64
#define CS 64
#define MIXD 32

// ---------------- scratch (static device arrays; no runtime alloc) ----------
__device__ float g_W1[4 * DPROJ];            // w_in @ w_inproj
__device__ float g_mvec[BB * DPROJ];         // (b_in + relu(mic)) @ w_inproj
__device__ uint32_t g_W2bt32[32 * 192];      // bf16x2 [o][dpair]
__device__ float g_hb[BB * 192];
__device__ float g_A[NH];
__device__ uint32_t g_xbf[(size_t)BB * TT * 192];  // silu(conv) xs, bf16x2 pairs along p
__device__ float g_bc[(size_t)BB * TT * 128];      // B(64) | C(64) fp32
__device__ float g_dt[(size_t)BB * TT * NH];
__device__ float g_la[(size_t)BB * TT * NH];       // log-decay = dt*A
__device__ uint32_t g_Sbf[(size_t)128 * NC * HD * 32]; // chunk states bf16x2 (pairs along n) -> h_in in place
__device__ float g_Dc[128 * NC];
__device__ uint32_t g_ybf32[(size_t)BB * TT * 192];    // gated y, bf16x2
__device__ float g_rstd[BB * TT];
__device__ float g_part[2048 * MIXD];

__device__ __forceinline__ float siluf(float v) {
    if (fabsf(v) < 0.25f) {
        float z2 = v * v;
        float sig = 0.5f + v * (0.25f + z2 * (-(1.f / 48.f) + z2 * (1.f / 480.f)));
        return v * sig;
    }
    return __fdividef(v, 1.f + __expf(-v));
}
__device__ __forceinline__ float softplusf(float v) { return v > 20.f ? v : __logf(1.f + __expf(v)); }

__device__ __forceinline__ uint32_t tf32u(float x) {
    uint32_t r;
    asm("cvt.rna.tf32.f32 %0, %1;" : "=r"(r) : "f"(x));
    return r;
}
__device__ __forceinline__ float tf32f(float x) { return __uint_as_float(tf32u(x)); }

__device__ __forceinline__ uint32_t packbf(float lo, float hi) {
    uint32_t w;
    asm("cvt.rn.bf16x2.f32 %0, %1, %2;" : "=r"(w) : "f"(hi), "f"(lo));
    return w;
}
__device__ __forceinline__ float2 unpackbf(uint32_t w) {
    return make_float2(__uint_as_float(w << 16), __uint_as_float(w & 0xffff0000u));
}
__device__ __forceinline__ float bfh(uint16_t v) {
    return __uint_as_float(((uint32_t)v) << 16);
}

__device__ __forceinline__ void mma8(float d[4], const uint32_t a[4], const uint32_t b[2]) {
    asm volatile(
        "mma.sync.aligned.m16n8k8.row.col.f32.tf32.tf32.f32 "
        "{%0,%1,%2,%3},{%4,%5,%6,%7},{%8,%9},{%0,%1,%2,%3};\n"
        : "+f"(d[0]), "+f"(d[1]), "+f"(d[2]), "+f"(d[3])
        : "r"(a[0]), "r"(a[1]), "r"(a[2]), "r"(a[3]),
          "r"(b[0]), "r"(b[1]));
}

__device__ __forceinline__ void mma16(float d[4], const uint32_t a[4], const uint32_t b[2]) {
    asm volatile(
        "mma.sync.aligned.m16n8k16.row.col.f32.bf16.bf16.f32 "
        "{%0,%1,%2,%3},{%4,%5,%6,%7},{%8,%9},{%0,%1,%2,%3};\n"
        : "+f"(d[0]), "+f"(d[1]), "+f"(d[2]), "+f"(d[3])
        : "r"(a[0]), "r"(a[1]), "r"(a[2]), "r"(a[3]),
          "r"(b[0]), "r"(b[1]));
}

// ---------------- k0a: mic MLP + A ----------------
__global__ void k0a(const float* __restrict__ mic_pos, const float* __restrict__ w_mic,
                    const float* __restrict__ b_mic, const float* __restrict__ b_in,
                    const float* __restrict__ A_log) {
    int tid = threadIdx.x;
    for (int i = tid; i < BB * 192; i += 256) {
        int b = i / 192, d = i % 192;
        float s = b_mic[d];
        #pragma unroll
        for (int j = 0; j < 12; j++) s = fmaf(mic_pos[b * 12 + j], w_mic[j * 192 + d], s);
        g_hb[i] = b_in[d] + fmaxf(s, 0.f);
    }
    if (tid < NH) g_A[tid] = -expf(A_log[tid]);
}

// ---------------- k0b: folded weights ----------------
__global__ void k0b(const float* __restrict__ w_in, const float* __restrict__ w_inproj,
                    const float* __restrict__ w_outproj, const float* __restrict__ w_mix1,
                    const float* __restrict__ norm_w) {
    int i = blockIdx.x * 256 + threadIdx.x;
    if (i < 4 * DPROJ) {
        int j = i / DPROJ, d = i % DPROJ;
        float s = 0.f;
        for (int m = 0; m < 192; m++) s = fmaf(w_in[j * 192 + m], w_inproj[m * DPROJ + d], s);
        g_W1[i] = s;
    } else if (i < 4 * DPROJ + BB * DPROJ) {
        int ii = i - 4 * DPROJ;
        int b = ii / DPROJ, d = ii % DPROJ;
        float s = 0.f;
        for (int m = 0; m < 192; m++) s = fmaf(g_hb[b * 192 + m], w_inproj[m * DPROJ + d], s);
        g_mvec[ii] = s;
    } else if (i < 4 * DPROJ + BB * DPROJ + 32 * 192) {
        int ii = i - (4 * DPROJ + BB * DPROJ);
        int o = ii / 192, kw = ii % 192;
        int d0 = 2 * kw, d1 = d0 + 1;
        float s0 = 0.f, s1 = 0.f;
        for (int m = 0; m < 192; m++) {
            s0 = fmaf(w_outproj[d0 * 192 + m], w_mix1[m * MIXD + o], s0);
            s1 = fmaf(w_outproj[d1 * 192 + m], w_mix1[m * MIXD + o], s1);
        }
        g_W2bt32[o * 192 + kw] = packbf(s0 * norm_w[d0], s1 * norm_w[d1]);
    }
}

// ---------------- k1: fused inproj + conv4 + silu + dt/la ----------------
// grid (32, 16) block 128 : thread = one t
__global__ void k1(const float* __restrict__ x, const float* __restrict__ conv_w,
                   const float* __restrict__ conv_b, const float* __restrict__ dt_bias) {
    __shared__ float sW1[4 * 520];   // proj dims 384..903
    __shared__ float smv[520];
    __shared__ float scw[512 * 4];
    __shared__ float scb[512];
    __shared__ float sx4[131 * 4];
    __shared__ float sraw[131 * 33];

    int tid = threadIdx.x;
    int b = blockIdx.y;
    int t0 = blockIdx.x * 128;

    for (int i = tid; i < 4 * 520; i += 128) sW1[i] = g_W1[(i / 520) * DPROJ + 384 + (i % 520)];
    for (int i = tid; i < 520; i += 128) smv[i] = g_mvec[b * DPROJ + 384 + i];
    for (int i = tid; i < 512 * 4; i += 128) scw[i] = conv_w[i];
    for (int i = tid; i < 512; i += 128) scb[i] = conv_b[i];
    for (int i = tid; i < 131 * 4; i += 128) {
        int r = i >> 2, j = i & 3;
        int t = t0 + r - 3;
        sx4[i] = (t >= 0) ? x[((size_t)b * TT + t) * 4 + j] : 0.f;
    }

    int t = t0 + tid;
    for (int c16 = 0; c16 < 16; c16++) {
        __syncthreads();
        for (int i = tid; i < 131 * 32; i += 128) {
            int r = i >> 5, dc = i & 31;
            int dd = c16 * 32 + dc;
            float v = 0.f;
            if (t0 + r - 3 >= 0) {
                v = smv[dd];
                #pragma unroll
                for (int j = 0; j < 4; j++) v = fmaf(sx4[r * 4 + j], sW1[j * 520 + dd], v);
            }
            sraw[r * 33 + dc] = v;
        }
        __syncthreads();
        float v[32];
        #pragma unroll
        for (int dc = 0; dc < 32; dc++) {
            int dd = c16 * 32 + dc;
            float a = scb[dd];
            #pragma unroll
            for (int k = 0; k < 4; k++) a = fmaf(sraw[(tid + k) * 33 + dc], scw[dd * 4 + k], a);
            v[dc] = siluf(a);
        }
        if (c16 < 12) {
            uint32_t* dst = g_xbf + ((size_t)b * TT + t) * 192 + c16 * 16;
            #pragma unroll
            for (int q = 0; q < 4; q++) {
                uint4 w;
                w.x = packbf(v[8 * q + 0], v[8 * q + 1]);
                w.y = packbf(v[8 * q + 2], v[8 * q + 3]);
                w.z = packbf(v[8 * q + 4], v[8 * q + 5]);
                w.w = packbf(v[8 * q + 6], v[8 * q + 7]);
                ((uint4*)dst)[q] = w;
            }
        } else {
            float* dst = g_bc + ((size_t)b * TT + t) * 128 + (c16 - 12) * 32;
            #pragma unroll
            for (int q = 0; q < 8; q++)
                ((float4*)dst)[q] = make_float4(v[4 * q], v[4 * q + 1], v[4 * q + 2], v[4 * q + 3]);
        }
    }

    // dt path (proj dims 896..903 via sW1 dims 512..519)
    #pragma unroll
    for (int hh = 0; hh < NH; hh++) {
        int dd = 512 + hh;
        float v = smv[dd];
        #pragma unroll
        for (int j = 0; j < 4; j++) v = fmaf(sx4[(tid + 3) * 4 + j], sW1[j * 520 + dd], v);
        float dt = softplusf(v + dt_bias[hh]);
        size_t o = ((size_t)b * TT + t) * NH + hh;
        g_dt[o] = dt;
        g_la[o] = dt * g_A[hh];
    }
}

// ---------------- kA: chunk-local end states via tf32 mma, all heads/block --
// grid (NC, BB) block 192 (6 warps): warp = (p-strip w%3, n-half w/3)
__global__ __launch_bounds__(192) void kA() {
    __shared__ float sxw[CS * 56];   // [t][p] = w(t)*x(t,p), tf32 (per head)
    __shared__ float sB[CS * 72];    // [t][n], tf32 (shared across heads)
    __shared__ float sCS[8 * 64];    // [h][t] inclusive log-decay prefix
    __shared__ float sDT[8 * 64];    // [h][t]

    int c = blockIdx.x, b = blockIdx.y;
    int tid = threadIdx.x;
    int wid = tid >> 5, lane = tid & 31;
    int lq = lane & 3, lh = lane >> 2;
    int t0 = c * CS;

    // la/dt for all heads, transpose to [h][t]
    if (tid < 128) {
        const float* lap = g_la + ((size_t)b * TT + t0) * NH;
        const float* dtp = g_dt + ((size_t)b * TT + t0) * NH;
        float4 v = ((const float4*)lap)[tid];
        float4 w = ((const float4*)dtp)[tid];
        int j0 = tid * 4;
        #pragma unroll
        for (int u = 0; u < 4; u++) {
            int j = j0 + u;
            int t = j >> 3, h = j & 7;
            sCS[h * 64 + t] = (&v.x)[u];
            sDT[h * 64 + t] = (&w.x)[u];
        }
    }

    // B staged ONCE (tf32, [t][n])
    const float* bp = g_bc + ((size_t)b * TT + t0) * 128;
    for (int i = tid; i < CS * 16; i += 192) {
        int r = i >> 4, col = i & 15;
        float4 v = ((const float4*)(bp + (size_t)r * 128))[col];
        *(float4*)&sB[r * 72 + col * 4] =
            make_float4(tf32f(v.x), tf32f(v.y), tf32f(v.z), tf32f(v.w));
    }
    __syncthreads();

    // per-head inclusive log-decay prefix scans (6 warps cover 8 heads)
    for (int hh = wid; hh < NH; hh += 6) {
        float a0 = sCS[hh * 64 + 2 * lane], a1 = sCS[hh * 64 + 2 * lane + 1];
        float ps = a0 + a1;
        #pragma unroll
        for (int off = 1; off < 32; off <<= 1) {
            float v = __shfl_up_sync(0xffffffffu, ps, off);
            if (lane >= off) ps += v;
        }
        sCS[hh * 64 + 2 * lane + 1] = ps;
        sCS[hh * 64 + 2 * lane]     = ps - a1;
    }
    __syncthreads();

    int p0 = (wid % 3) * 16;
    int nb = (wid / 3) * 32;

    for (int h = 0; h < NH; h++) {
        const float* csh = sCS + h * 64;
        const float* dth = sDT + h * 64;
        float cstot = csh[CS - 1];

        // stage this head's x slice, scaled by w(t) = exp(cstot-cs[t])*dt[t]
        const uint32_t* xp = g_xbf + ((size_t)b * TT + t0) * 192 + h * 24;
        for (int i = tid; i < CS * 6; i += 192) {
            int r = i / 6, col = i % 6;
            float wgt = __expf(cstot - csh[r]) * dth[r];
            uint4 w4 = ((const uint4*)(xp + (size_t)r * 192))[col];
            float2 q0 = unpackbf(w4.x), q1 = unpackbf(w4.y), q2 = unpackbf(w4.z), q3 = unpackbf(w4.w);
            *(float4*)&sxw[r * 56 + col * 8] =
                make_float4(tf32f(q0.x * wgt), tf32f(q0.y * wgt), tf32f(q1.x * wgt), tf32f(q1.y * wgt));
            *(float4*)&sxw[r * 56 + col * 8 + 4] =
                make_float4(tf32f(q2.x * wgt), tf32f(q2.y * wgt), tf32f(q3.x * wgt), tf32f(q3.y * wgt));
        }
        __syncthreads();

        // S[p][n] = sum_t Xw[t][p] * B[t][n]
        float acc[4][4];
        #pragma unroll
        for (int j = 0; j < 4; j++)
            #pragma unroll
            for (int e = 0; e < 4; e++) acc[j][e] = 0.f;

        #pragma unroll
        for (int k = 0; k < CS; k += 8) {
            uint32_t a[4];
            a[0] = __float_as_uint(sxw[(k + lq) * 56 + p0 + lh]);
            a[1] = __float_as_uint(sxw[(k + lq) * 56 + p0 + lh + 8]);
            a[2] = __float_as_uint(sxw[(k + 4 + lq) * 56 + p0 + lh]);
            a[3] = __float_as_uint(sxw[(k + 4 + lq) * 56 + p0 + lh + 8]);
            #pragma unroll
            for (int j = 0; j < 4; j++) {
                uint32_t bfr[2];
                bfr[0] = __float_as_uint(sB[(k + lq) * 72 + nb + 8 * j + lh]);
                bfr[1] = __float_as_uint(sB[(k + 4 + lq) * 72 + nb + 8 * j + lh]);
                mma8(acc[j], a, bfr);
            }
        }

        uint32_t* sp = g_Sbf + ((size_t)(b * NH + h) * NC + c) * 1536;
        #pragma unroll
        for (int j = 0; j < 4; j++) {
            int n0 = nb + 8 * j + 2 * lq;
            sp[(p0 + lh) * 32 + (n0 >> 1)]     = packbf(acc[j][0], acc[j][1]);
            sp[(p0 + lh + 8) * 32 + (n0 >> 1)] = packbf(acc[j][2], acc[j][3]);
        }
        if (tid == 0) g_Dc[(b * NH + h) * NC + c] = __expf(cstot);
        __syncthreads();   // sxw reads done before next head's staging
    }
}

// ---------------- kB: inter-chunk scan (fp32 regs, bf16 storage) ----------
// grid (128, 4) block 384 : thread owns 2 states (1 word), depth-2 prefetch
__global__ void kB() {
    int bh = blockIdx.x, q = blockIdx.y;
    int tid = threadIdx.x;
    float h0 = 0.f, h1 = 0.f;
    size_t base = (size_t)bh * NC * 1536 + (size_t)q * 384 + tid;
    uint32_t a0 = g_Sbf[base];
    uint32_t a1 = g_Sbf[base + 1536];
    float D0 = g_Dc[bh * NC];
    float D1 = g_Dc[bh * NC + 1];
    for (int c = 0; c < NC; c++) {
        uint32_t* sp = g_Sbf + base + (size_t)c * 1536;
        uint32_t an = 0u;
        float Dn = 0.f;
        if (c + 2 < NC) {
            an = sp[2 * 1536];
            Dn = g_Dc[bh * NC + c + 2];
        }
        float2 p = unpackbf(a0);
        sp[0] = packbf(h0, h1);
        h0 = fmaf(h0, D0, p.x);
        h1 = fmaf(h1, D0, p.y);
        a0 = a1; a1 = an; D0 = D1; D1 = Dn;
    }
}

// ---------------- kC: chunked SSD + fused gating/RMS-stats ----------------
// grid (NC, BB) block 256 (8 warps)
// GEMM1 tf32; GEMM2/GEMM3 bf16 mma16. G bf16 aliased onto sBt. h_in read from global.
#define ST64 72
#define STB 36
#define KC_BT   0                        // GEMM1 B: B^T [n][t] tf32 (4608) ∪ G bf16 words [t][STB]
#define KC_CT   (KC_BT + 64 * ST64)      // GEMM1 A: C^T [n][t] tf32 (4608)
#define KC_CB   (KC_CT + 64 * ST64)      // C bf16 words [t][STB] (2304)
#define KC_XT   (KC_CB + 64 * STB)       // x^T bf16 words [p:48][STB] (1728)
#define KC_SCS  (KC_XT + 48 * STB)       // 8*64
#define KC_SDT  (KC_SCS + 512)           // 8*64
#define KC_W1Z  (KC_SDT + 512)           // 4*384
#define KC_MVZ  (KC_W1Z + 1536)          // 384
#define KC_X4   (KC_MVZ + 384)           // 64*4
#define KC_SMEM_FLOATS (KC_X4 + 256)

__global__ __launch_bounds__(256) void kC(const float* __restrict__ D_skip,
                                          const float* __restrict__ xin) {
    extern __shared__ float sm[];
    uint32_t* smu = (uint32_t*)sm;
    uint16_t* smh = (uint16_t*)sm;
    float* sBt  = sm + KC_BT;
    float* sCt  = sm + KC_CT;
    float* sCS  = sm + KC_SCS;
    float* sDT  = sm + KC_SDT;
    float* sW1z = sm + KC_W1Z;
    float* smvz = sm + KC_MVZ;
    float* sx4  = sm + KC_X4;

    int c = blockIdx.x, b = blockIdx.y;
    int tid = threadIdx.x;
    int wid = tid >> 5, lane = tid & 31;
    int lq = lane & 3, lh = lane >> 2;
    int t0c = c * CS;

    if (tid < 128) {
        const float* lap = g_la + ((size_t)b * TT + t0c) * NH;
        const float* dtp = g_dt + ((size_t)b * TT + t0c) * NH;
        float4 v = ((const float4*)lap)[tid];
        float4 w = ((const float4*)dtp)[tid];
        int j0 = tid * 4;
        #pragma unroll
        for (int u = 0; u < 4; u++) {
            int j = j0 + u;
            int t = j >> 3, h = j & 7;
            sCS[h * 64 + t] = (&v.x)[u];
            sDT[h * 64 + t] = (&w.x)[u];
        }
    }
    for (int i = tid; i < 4 * DINNER; i += 256) sW1z[i] = g_W1[(i / DINNER) * DPROJ + (i % DINNER)];
    for (int i = tid; i < DINNER; i += 256) smvz[i] = g_mvec[b * DPROJ + i];
    if (tid < 256) {
        int r = tid >> 2, j = tid & 3;
        sx4[tid] = xin[((size_t)b * TT + t0c + r) * 4 + j];
    }

    // B,C load: tf32 transposed [n][t] + bf16-packed C [t][STB]
    const float* bp = g_bc + ((size_t)b * TT + t0c) * 128;
    for (int i = tid; i < CS * 16; i += 256) {
        int s = i >> 4, nq = i & 15;
        float4 v = ((const float4*)(bp + (size_t)s * 128))[nq];          // B[s][n]
        sBt[(nq * 4 + 0) * ST64 + s] = tf32f(v.x);
        sBt[(nq * 4 + 1) * ST64 + s] = tf32f(v.y);
        sBt[(nq * 4 + 2) * ST64 + s] = tf32f(v.z);
        sBt[(nq * 4 + 3) * ST64 + s] = tf32f(v.w);
        float4 w = ((const float4*)(bp + (size_t)s * 128))[nq + 16];     // C[s][n]
        sCt[(nq * 4 + 0) * ST64 + s] = tf32f(w.x);
        sCt[(nq * 4 + 1) * ST64 + s] = tf32f(w.y);
        sCt[(nq * 4 + 2) * ST64 + s] = tf32f(w.z);
        sCt[(nq * 4 + 3) * ST64 + s] = tf32f(w.w);
        smu[KC_CB + s * STB + 2 * nq]     = packbf(w.x, w.y);
        smu[KC_CB + s * STB + 2 * nq + 1] = packbf(w.z, w.w);
    }
    __syncthreads();

    // per-head inclusive log-decay prefix (warp w = head w)
    {
        float a0 = sCS[wid * 64 + 2 * lane];
        float a1 = sCS[wid * 64 + 2 * lane + 1];
        float ps = a0 + a1;
        #pragma unroll
        for (int off = 1; off < 32; off <<= 1) {
            float v = __shfl_up_sync(0xffffffffu, ps, off);
            if (lane >= off) ps += v;
        }
        sCS[wid * 64 + 2 * lane + 1] = ps;
        sCS[wid * 64 + 2 * lane]     = ps - a1;
    }

    int t0 = (wid & 3) * 16;
    int sb = (wid >> 2) * 32;
    int pb = (wid >> 2) * 24;

    float xr0[4], xr1[4];
    #pragma unroll
    for (int u = 0; u < 4; u++) {
        xr0[u] = sx4[(t0 + lh) * 4 + u];
        xr1[u] = sx4[(t0 + lh + 8) * 4 + u];
    }

    // GEMM1 (tf32, shared across heads): Graw[t][s] = sum_n C[t][n]*B[s][n]
    float g1[4][4];
    #pragma unroll
    for (int j = 0; j < 4; j++)
        #pragma unroll
        for (int e = 0; e < 4; e++) g1[j][e] = 0.f;

    #pragma unroll
    for (int k = 0; k < DS; k += 8) {
        uint32_t a[4];
        a[0] = __float_as_uint(sCt[(k + lq) * ST64 + t0 + lh]);
        a[1] = __float_as_uint(sCt[(k + lq) * ST64 + t0 + lh + 8]);
        a[2] = __float_as_uint(sCt[(k + 4 + lq) * ST64 + t0 + lh]);
        a[3] = __float_as_uint(sCt[(k + 4 + lq) * ST64 + t0 + lh + 8]);
        #pragma unroll
        for (int j = 0; j < 4; j++) {
            uint32_t bfr[2];
            bfr[0] = __float_as_uint(sBt[(k + lq) * ST64 + sb + 8 * j + lh]);
            bfr[1] = __float_as_uint(sBt[(k + 4 + lq) * ST64 + sb + 8 * j + lh]);
            mma8(g1[j], a, bfr);
        }
    }

    float ss0 = 0.f, ss1 = 0.f;
    uint32_t* ybase = g_ybf32 + ((size_t)b * TT + t0c) * 192;

    for (int h = 0; h < NH; h++) {
        __syncthreads();   // prior reads of G(BT)/xT done; on h=0 GEMM1 reads of sBt done

        // build x^T [p][s-pair] bf16 for this head (16-bit smem stores)
        const uint32_t* xp = g_xbf + ((size_t)b * TT + t0c) * 192 + h * 24;
        for (int i = tid; i < CS * 6; i += 256) {
            int s = i / 6, col = i % 6;
            uint4 w4 = ((const uint4*)(xp + (size_t)s * 192))[col];
            int p0w = col * 8;
            int half = s & 1, sw = s >> 1;
            uint32_t ws[4] = {w4.x, w4.y, w4.z, w4.w};
            #pragma unroll
            for (int u = 0; u < 4; u++) {
                int p = p0w + 2 * u;
                smh[(KC_XT + p * STB + sw) * 2 + half]       = (uint16_t)(ws[u] & 0xffffu);
                smh[(KC_XT + (p + 1) * STB + sw) * 2 + half] = (uint16_t)(ws[u] >> 16);
            }
        }

        // mask+scale Graw with this head's decay, store bf16 G [t][s-pair] (aliased onto BT)
        const float* csh = sCS + h * 64;
        const float* dth = sDT + h * 64;
        {
            float cs_r0 = csh[t0 + lh], cs_r1 = csh[t0 + lh + 8];
            #pragma unroll
            for (int j = 0; j < 4; j++) {
                int c0 = sb + 8 * j + 2 * lq;
                float cs_c0 = csh[c0], cs_c1 = csh[c0 + 1];
                float dt_c0 = dth[c0], dt_c1 = dth[c0 + 1];
                int r0 = t0 + lh, r1 = r0 + 8;
                float m00 = (c0 <= r0) ? __expf(cs_r0 - cs_c0) * dt_c0 : 0.f;
                float m01 = (c0 + 1 <= r0) ? __expf(cs_r0 - cs_c1) * dt_c1 : 0.f;
                float m10 = (c0 <= r1) ? __expf(cs_r1 - cs_c0) * dt_c0 : 0.f;
                float m11 = (c0 + 1 <= r1) ? __expf(cs_r1 - cs_c1) * dt_c1 : 0.f;
                int cw = c0 >> 1;
                smu[KC_BT + r0 * STB + cw] = packbf(g1[j][0] * m00, g1[j][1] * m01);
                smu[KC_BT + r1 * STB + cw] = packbf(g1[j][2] * m10, g1[j][3] * m11);
            }
        }
        __syncthreads();

        // GEMM2 (bf16): Yintra[t][p] = sum_s G[t][s]*x[s][p]
        // GEMM3 (bf16): Yinter[t][p] = sum_n C[t][n]*hin[n][p]  (B fragments direct from global)
        float accA[3][4], accB[3][4];
        #pragma unroll
        for (int j = 0; j < 3; j++)
            #pragma unroll
            for (int e = 0; e < 4; e++) { accA[j][e] = 0.f; accB[j][e] = 0.f; }

        const uint32_t* hp = g_Sbf + ((size_t)(b * NH + h) * NC + c) * 1536;
        #pragma unroll
        for (int k16 = 0; k16 < 64; k16 += 16) {
            int kw = k16 >> 1;
            uint32_t a[4];
            a[0] = smu[KC_BT + (t0 + lh) * STB + kw + lq];
            a[1] = smu[KC_BT + (t0 + lh + 8) * STB + kw + lq];
            a[2] = smu[KC_BT + (t0 + lh) * STB + kw + lq + 4];
            a[3] = smu[KC_BT + (t0 + lh + 8) * STB + kw + lq + 4];
            #pragma unroll
            for (int j = 0; j < 3; j++) {
                int p = pb + 8 * j + lh;
                uint32_t bfr[2];
                bfr[0] = smu[KC_XT + p * STB + kw + lq];
                bfr[1] = smu[KC_XT + p * STB + kw + lq + 4];
                mma16(accA[j], a, bfr);
            }
            uint32_t a2[4];
            a2[0] = smu[KC_CB + (t0 + lh) * STB + kw + lq];
            a2[1] = smu[KC_CB + (t0 + lh + 8) * STB + kw + lq];
            a2[2] = smu[KC_CB + (t0 + lh) * STB + kw + lq + 4];
            a2[3] = smu[KC_CB + (t0 + lh + 8) * STB + kw + lq + 4];
            #pragma unroll
            for (int j = 0; j < 3; j++) {
                int p = pb + 8 * j + lh;
                uint32_t bfr[2];
                bfr[0] = __ldg(hp + p * 32 + kw + lq);
                bfr[1] = __ldg(hp + p * 32 + kw + lq + 4);
                mma16(accB[j], a2, bfr);
            }
        }

        // epilogue: y = intra + exp(cs)*inter + D*x; gate; accumulate ss; store bf16
        float dskip = D_skip[h];
        float et0 = __expf(csh[t0 + lh]);
        float et1 = __expf(csh[t0 + lh + 8]);
        #pragma unroll
        for (int j = 0; j < 3; j++) {
            int p0c = pb + 8 * j + 2 * lq;
            int r0 = t0 + lh, r1 = r0 + 8;
            int dd = h * HD + p0c;
            float x00 = bfh(smh[(KC_XT + p0c * STB + (r0 >> 1)) * 2 + (r0 & 1)]);
            float x01 = bfh(smh[(KC_XT + (p0c + 1) * STB + (r0 >> 1)) * 2 + (r0 & 1)]);
            float x10 = bfh(smh[(KC_XT + p0c * STB + (r1 >> 1)) * 2 + (r1 & 1)]);
            float x11 = bfh(smh[(KC_XT + (p0c + 1) * STB + (r1 >> 1)) * 2 + (r1 & 1)]);
            float y00 = accA[j][0] + et0 * accB[j][0] + dskip * x00;
            float y01 = accA[j][1] + et0 * accB[j][1] + dskip * x01;
            float y10 = accA[j][2] + et1 * accB[j][2] + dskip * x10;
            float y11 = accA[j][3] + et1 * accB[j][3] + dskip * x11;
            float w0a = sW1z[dd],            w0b = sW1z[dd + 1];
            float w1a = sW1z[DINNER + dd],   w1b = sW1z[DINNER + dd + 1];
            float w2a = sW1z[2*DINNER + dd], w2b = sW1z[2*DINNER + dd + 1];
            float w3a = sW1z[3*DINNER + dd], w3b = sW1z[3*DINNER + dd + 1];
            float mva = smvz[dd], mvb = smvz[dd + 1];
            float za0 = fmaf(xr0[3], w3a, fmaf(xr0[2], w2a, fmaf(xr0[1], w1a, fmaf(xr0[0], w0a, mva))));
            float zb0 = fmaf(xr0[3], w3b, fmaf(xr0[2], w2b, fmaf(xr0[1], w1b, fmaf(xr0[0], w0b, mvb))));
            float za1 = fmaf(xr1[3], w3a, fmaf(xr1[2], w2a, fmaf(xr1[1], w1a, fmaf(xr1[0], w0a, mva))));
            float zb1 = fmaf(xr1[3], w3b, fmaf(xr1[2], w2b, fmaf(xr1[1], w1b, fmaf(xr1[0], w0b, mvb))));
            float g00 = y00 * siluf(za0);
            float g01 = y01 * siluf(zb0);
            float g10 = y10 * siluf(za1);
            float g11 = y11 * siluf(zb1);
            ss0 = fmaf(g00, g00, fmaf(g01, g01, ss0));
            ss1 = fmaf(g10, g10, fmaf(g11, g11, ss1));
            ybase[(size_t)r0 * 192 + (dd >> 1)] = packbf(g00, g01);
            ybase[(size_t)r1 * 192 + (dd >> 1)] = packbf(g10, g11);
        }
    }

    // row sum-of-squares -> rstd   (reuse sCS region)
    __syncthreads();
    ss0 += __shfl_xor_sync(0xffffffffu, ss0, 1);
    ss0 += __shfl_xor_sync(0xffffffffu, ss0, 2);
    ss1 += __shfl_xor_sync(0xffffffffu, ss1, 1);
    ss1 += __shfl_xor_sync(0xffffffffu, ss1, 2);
    if (lq == 0) {
        sCS[(wid >> 2) * 64 + t0 + lh]     = ss0;
        sCS[(wid >> 2) * 64 + t0 + lh + 8] = ss1;
    }
    __syncthreads();
    if (tid < 64) {
        float s = sCS[tid] + sCS[64 + tid];
        g_rstd[(size_t)b * TT + t0c + tid] = rsqrtf(s * (1.f / DINNER) + 1e-5f);
    }
}

// ---------------- kD2: bf16 mma GEMM(W2) + rstd + mix2 + partial ----------
// grid (32, BB) block 256 (8 warps), 128 rows/block
__global__ __launch_bounds__(256) void kD2(const float* __restrict__ b_mix1,
                   const float* __restrict__ w_mix2, const float* __restrict__ b_mix2) {
    __shared__ float sm1[128 * 33];
    __shared__ float swm2[MIXD * MIXD];

    int tid = threadIdx.x;
    int wid = tid >> 5, lane = tid & 31;
    int lq = lane & 3, lh = lane >> 2;
    int b = blockIdx.y;
    int t0 = blockIdx.x * 128;

    for (int i = tid; i < MIXD * MIXD; i += 256) swm2[i] = w_mix2[i];

    const uint32_t* arow = g_ybf32 + ((size_t)b * TT + t0 + wid * 16) * 192;
    float acc[4][4];
    #pragma unroll
    for (int j = 0; j < 4; j++)
        #pragma unroll
        for (int e = 0; e < 4; e++) acc[j][e] = 0.f;

    #pragma unroll 4
    for (int k16 = 0; k16 < DINNER; k16 += 16) {
        int kw = k16 >> 1;
        uint32_t a[4];
        a[0] = __ldg(arow + (size_t)lh * 192 + kw + lq);
        a[1] = __ldg(arow + (size_t)(lh + 8) * 192 + kw + lq);
        a[2] = __ldg(arow + (size_t)lh * 192 + kw + 4 + lq);
        a[3] = __ldg(arow + (size_t)(lh + 8) * 192 + kw + 4 + lq);
        #pragma unroll
        for (int j = 0; j < 4; j++) {
            uint32_t bfr[2];
            bfr[0] = __ldg(&g_W2bt32[(8 * j + lh) * 192 + kw + lq]);
            bfr[1] = __ldg(&g_W2bt32[(8 * j + lh) * 192 + kw + 4 + lq]);
            mma16(acc[j], a, bfr);
        }
    }

    {
        int r0 = wid * 16 + lh, r1 = r0 + 8;
        float rs0 = g_rstd[(size_t)b * TT + t0 + r0];
        float rs1 = g_rstd[(size_t)b * TT + t0 + r1];
        #pragma unroll
        for (int j = 0; j < 4; j++) {
            int oc = 8 * j + 2 * lq;
            sm1[r0 * 33 + oc]     = fmaxf(fmaf(acc[j][0], rs0, b_mix1[oc]), 0.f);
            sm1[r0 * 33 + oc + 1] = fmaxf(fmaf(acc[j][1], rs0, b_mix1[oc + 1]), 0.f);
            sm1[r1 * 33 + oc]     = fmaxf(fmaf(acc[j][2], rs1, b_mix1[oc]), 0.f);
            sm1[r1 * 33 + oc + 1] = fmaxf(fmaf(acc[j][3], rs1, b_mix1[oc + 1]), 0.f);
        }
    }
    __syncthreads();

    int r2 = tid >> 1;
    int oh = (tid & 1) * 16;
    float m2[16];
    #pragma unroll
    for (int o = 0; o < 16; o++) m2[o] = b_mix2[oh + o];
    #pragma unroll 4
    for (int i = 0; i < MIXD; i++) {
        float m = sm1[r2 * 33 + i];
        #pragma unroll
        for (int o = 0; o < 16; o++) m2[o] = fmaf(m, swm2[i * MIXD + oh + o], m2[o]);
    }
    #pragma unroll
    for (int o = 0; o < 16; o++) m2[o] = fmaxf(m2[o], 0.f);
    __syncthreads();
    #pragma unroll
    for (int o = 0; o < 16; o++) sm1[r2 * 33 + oh + o] = m2[o];
    __syncthreads();

    for (int s = 64; s >= 1; s >>= 1) {
        for (int idx = tid; idx < s * 32; idx += 256) {
            int r = idx >> 5, o = idx & 31;
            sm1[r * 33 + o] += sm1[(r + s) * 33 + o];
        }
        __syncthreads();
    }
    if (tid < MIXD) g_part[((size_t)b * 32 + blockIdx.x) * MIXD + tid] = sm1[tid];
}

// ---------------- kF: final mean + w_out ----------------
__global__ void kF(const float* __restrict__ w_out, const float* __restrict__ b_out,
                   float* __restrict__ out) {
    int b = threadIdx.x;
    if (b < BB) {
        float s = 0.f;
        for (int o = 0; o < MIXD; o++) {
            float a = 0.f;
            for (int blk = 0; blk < 32; blk++) a += g_part[((size_t)b * 32 + blk) * MIXD + o];
            s = fmaf(a * (1.f / (float)TT), w_out[o], s);
        }
        out[b] = s + b_out[0];
    }
}

extern "C" void kernel_launch(void* const* d_in, const int* in_sizes, int n_in,
                              void* d_out, int out_size) {
    const float* x        = (const float*)d_in[0];
    const float* mic_pos  = (const float*)d_in[1];
    const float* w_in     = (const float*)d_in[2];
    const float* b_in     = (const float*)d_in[3];
    const float* w_mic    = (const float*)d_in[4];
    const float* b_mic    = (const float*)d_in[5];
    const float* w_inproj = (const float*)d_in[6];
    const float* conv_w   = (const float*)d_in[7];
    const float* conv_b   = (const float*)d_in[8];
    const float* dt_bias  = (const float*)d_in[9];
    const float* A_log    = (const float*)d_in[10];
    const float* D_skip   = (const float*)d_in[11];
    const float* norm_w   = (const float*)d_in[12];
    const float* w_outproj= (const float*)d_in[13];
    const float* w_mix1   = (const float*)d_in[14];
    const float* b_mix1   = (const float*)d_in[15];
    const float* w_mix2   = (const float*)d_in[16];
    const float* b_mix2   = (const float*)d_in[17];
    const float* w_out    = (const float*)d_in[18];
    const float* b_out    = (const float*)d_in[19];
    float* out = (float*)d_out;

    cudaFuncSetAttribute(kC, cudaFuncAttributeMaxDynamicSharedMemorySize, KC_SMEM_FLOATS * 4);

    k0a<<<1, 256>>>(mic_pos, w_mic, b_mic, b_in, A_log);
    k0b<<<(4 * DPROJ + BB * DPROJ + 32 * 192 + 255) / 256, 256>>>(w_in, w_inproj, w_outproj, w_mix1, norm_w);
    k1<<<dim3(32, 16), 128>>>(x, conv_w, conv_b, dt_bias);
    kA<<<dim3(NC, BB), 192>>>();
    kB<<<dim3(128, 4), 384>>>();
    kC<<<dim3(NC, BB), 256, KC_SMEM_FLOATS * 4>>>(D_skip, x);
    kD2<<<dim3(32, BB), 256>>>(b_mix1, w_mix2, b_mix2);
    kF<<<1, 32>>>(w_out, b_out, out);
}